// round 6
// baseline (speedup 1.0000x reference)
#include <cuda_runtime.h>
#include <math.h>
#include <stdint.h>
#include <stddef.h>

// ---------------- problem constants ----------------
#define N_B   2
#define C_IN  1088
#define C_MID 136
#define HW    4096

typedef unsigned long long ull;

// ---------------- device scratch ----------------
__device__ __align__(16) float g_fa[N_B * C_MID * HW];
__device__ __align__(16) float g_fb[N_B * C_MID * HW];
// tf32-rounded raw, slot z: 0,1 = b_raw batches; 2,3 = a_raw batches
__device__ __align__(16) float g_traw[4ULL * C_IN * HW];

// ---------------- helpers ----------------
__device__ __forceinline__ ull pack2(float x, float y) {
    ull r; asm("mov.b64 %0, {%1, %2};" : "=l"(r) : "f"(x), "f"(y)); return r;
}
__device__ __forceinline__ float2 unpack2(ull v) {
    float2 f; asm("mov.b64 {%0, %1}, %2;" : "=f"(f.x), "=f"(f.y) : "l"(v)); return f;
}
__device__ __forceinline__ void ffma2u(ull& d, ull a, ull b) {
    asm("fma.rn.f32x2 %0, %1, %2, %0;" : "+l"(d) : "l"(a), "l"(b));
}
__device__ __forceinline__ uint32_t cvt_tf32(float f) {
    uint32_t u; asm("cvt.rna.tf32.f32 %0, %1;" : "=r"(u) : "f"(f)); return u;
}
__device__ __forceinline__ float cvt_tf32f(float f) {
    return __uint_as_float(cvt_tf32(f));
}
__device__ __forceinline__ void cp16(uint32_t dst, const void* src, uint32_t sz) {
    asm volatile("cp.async.ca.shared.global [%0], [%1], 16, %2;"
                 :: "r"(dst), "l"(src), "r"(sz));
}
__device__ __forceinline__ void cp_commit() { asm volatile("cp.async.commit_group;"); }
__device__ __forceinline__ void cp_wait0()  { asm volatile("cp.async.wait_group 0;" ::: "memory"); }
__device__ __forceinline__ void cp_wait1()  { asm volatile("cp.async.wait_group 1;" ::: "memory"); }

__device__ __forceinline__ float blk_sum(float v, float* red) {
    const int tid = threadIdx.x;
    #pragma unroll
    for (int o = 16; o > 0; o >>= 1) v += __shfl_down_sync(0xffffffffu, v, o);
    if ((tid & 31) == 0) red[tid >> 5] = v;
    __syncthreads();
    if (tid < 32) {
        v = (tid < 8) ? red[tid] : 0.f;
        #pragma unroll
        for (int o = 4; o > 0; o >>= 1) v += __shfl_down_sync(0xffffffffu, v, o);
        if (tid == 0) red[0] = v;
    }
    __syncthreads();
    v = red[0];
    __syncthreads();
    return v;
}

__device__ __forceinline__ float blk_max(float v, float* red) {
    const int tid = threadIdx.x;
    #pragma unroll
    for (int o = 16; o > 0; o >>= 1) v = fmaxf(v, __shfl_down_sync(0xffffffffu, v, o));
    if ((tid & 31) == 0) red[tid >> 5] = v;
    __syncthreads();
    if (tid < 32) {
        v = (tid < 8) ? red[tid] : -3.4e38f;
        #pragma unroll
        for (int o = 4; o > 0; o >>= 1) v = fmaxf(v, __shfl_down_sync(0xffffffffu, v, o));
        if (tid == 0) red[0] = v;
    }
    __syncthreads();
    v = red[0];
    __syncthreads();
    return v;
}

// ---------------- mma.sync tf32 primitive ----------------
__device__ __forceinline__ void mma_tf32(float4& c, const uint32_t a[4], const uint32_t b[2]) {
    asm volatile(
        "mma.sync.aligned.m16n8k8.row.col.f32.tf32.tf32.f32 "
        "{%0,%1,%2,%3},{%4,%5,%6,%7},{%8,%9},{%0,%1,%2,%3};"
        : "+f"(c.x), "+f"(c.y), "+f"(c.z), "+f"(c.w)
        : "r"(a[0]), "r"(a[1]), "r"(a[2]), "r"(a[3]), "r"(b[0]), "r"(b[1]));
}

// ---------------- warp-stage GEMM: mma.sync tf32, CTA 128x256, 3-stage cp.async ----------------
// C[z][M=1088, 4096] = traw[z] @ corr[z]   (corr rows are K, cols are N -> col-major B frags)
#define ST_A_PAD 36
#define ST_B_PAD 264
#define ST_A_BYTES (128 * ST_A_PAD * 4)      // 18432
#define ST_B_BYTES (32 * ST_B_PAD * 4)       // 33792
#define ST_BYTES   (ST_A_BYTES + ST_B_BYTES) // 52224
#define N_STAGE 3
#define WG_SMEM (N_STAGE * ST_BYTES)         // 156672

__global__ __launch_bounds__(256)
void wgemm_mma_kernel(const float* __restrict__ Araw, const float* __restrict__ corr,
                      float* __restrict__ b_warp, float* __restrict__ a_warp)
{
    extern __shared__ float sm[];
    const uint32_t smem_base = (uint32_t)__cvta_generic_to_shared(sm);

    const int z = blockIdx.z;
    const float* A = Araw + (size_t)z * C_IN * HW;
    const float* B = corr + (size_t)z * HW * HW;     // corr slots contiguous: ab0,ab1,ba0,ba1
    float* C = (z < 2) ? (b_warp + (size_t)z * C_IN * HW)
                       : (a_warp + (size_t)(z - 2) * C_IN * HW);

    const int m0 = blockIdx.y * 128;
    const int n0 = blockIdx.x * 256;
    const int tid = threadIdx.x;
    const int wid = tid >> 5;
    const int lane = tid & 31;
    const int wr = wid >> 2;            // 0..1 -> 64 M rows
    const int wc = wid & 3;             // 0..3 -> 64 N cols
    const int r = lane >> 2;            // 0..7
    const int c = lane & 3;             // 0..3

    auto load_chunk = [&](int kc, int st) {
        const uint32_t sb = smem_base + (uint32_t)(st * ST_BYTES);
        const int k0 = kc * 32;
        #pragma unroll
        for (int p = 0; p < 4; p++) {               // A: 128 rows x 32 k
            const int u = p * 256 + tid;
            const int row = u >> 3, q = u & 7;
            const int gr = m0 + row;
            const uint32_t dst = sb + (uint32_t)((row * ST_A_PAD + q * 4) * 4);
            const float* src = A + (size_t)((gr < C_IN) ? gr : 0) * HW + k0 + q * 4;
            cp16(dst, src, (gr < C_IN) ? 16u : 0u); // sz=0 -> zero fill
        }
        #pragma unroll
        for (int p = 0; p < 8; p++) {               // B: 32 k x 256 n
            const int u = p * 256 + tid;
            const int k = u >> 6, nb = u & 63;
            const uint32_t dst = sb + ST_A_BYTES + (uint32_t)((k * ST_B_PAD + nb * 4) * 4);
            const float* src = B + (size_t)(k0 + k) * HW + n0 + nb * 4;
            cp16(dst, src, 16u);
        }
        cp_commit();
    };

    float4 acc[4][8];
    #pragma unroll
    for (int i = 0; i < 4; i++)
        #pragma unroll
        for (int j = 0; j < 8; j++) acc[i][j] = make_float4(0.f, 0.f, 0.f, 0.f);

    const int NC = HW / 32;             // 128 chunks
    load_chunk(0, 0);
    load_chunk(1, 1);

    int st = 0;
    for (int j = 0; j < NC; j++) {
        if (j + 2 < NC) cp_wait1(); else cp_wait0();
        __syncthreads();
        if (j + 2 < NC) {
            int st2 = st + 2; if (st2 >= N_STAGE) st2 -= N_STAGE;
            load_chunk(j + 2, st2);
        }

        const float* As = sm + st * (ST_BYTES / 4);
        const float* Bs = As + ST_A_BYTES / 4;
        #pragma unroll
        for (int s = 0; s < 4; s++) {
            uint32_t a[4][4], b[8][2];
            #pragma unroll
            for (int mt = 0; mt < 4; mt++) {
                const float* ap = As + (wr * 64 + mt * 16 + r) * ST_A_PAD + s * 8 + c;
                a[mt][0] = __float_as_uint(ap[0]);              // A pre-rounded to tf32
                a[mt][1] = __float_as_uint(ap[8 * ST_A_PAD]);
                a[mt][2] = __float_as_uint(ap[4]);
                a[mt][3] = __float_as_uint(ap[8 * ST_A_PAD + 4]);
            }
            #pragma unroll
            for (int nt = 0; nt < 8; nt++) {
                const float* bp = Bs + (s * 8 + c) * ST_B_PAD + wc * 64 + nt * 8 + r;
                b[nt][0] = cvt_tf32(bp[0]);
                b[nt][1] = cvt_tf32(bp[4 * ST_B_PAD]);
            }
            #pragma unroll
            for (int mt = 0; mt < 4; mt++)
                #pragma unroll
                for (int nt = 0; nt < 8; nt++)
                    mma_tf32(acc[mt][nt], a[mt], b[nt]);
        }
        if (++st >= N_STAGE) st -= N_STAGE;
    }

    // epilogue
    const int gid = lane >> 2;
    const int tig = lane & 3;
    #pragma unroll
    for (int mt = 0; mt < 4; mt++) {
        const int r0 = m0 + wr * 64 + mt * 16 + gid;
        const int r1 = r0 + 8;
        #pragma unroll
        for (int nt = 0; nt < 8; nt++) {
            const int col = n0 + wc * 64 + nt * 8 + tig * 2;
            const float4 cc = acc[mt][nt];
            if (r0 < C_IN)
                *reinterpret_cast<float2*>(C + (size_t)r0 * HW + col) = make_float2(cc.x, cc.y);
            if (r1 < C_IN)
                *reinterpret_cast<float2*>(C + (size_t)r1 * HW + col) = make_float2(cc.z, cc.w);
        }
    }
}

// ---------------- fp32 SIMT GEMM with packed f32x2 FMA (conv + energy) ----------------
#define BM 128
#define BN 128
#define BK 8
#define TM 8
#define TN 8

template<bool TRANS_A, int EPI>
__global__ __launch_bounds__(256, 2)
void sgemm2_kernel(const float* __restrict__ A0, const float* __restrict__ A1,
                   const float* __restrict__ B0, const float* __restrict__ B1,
                   const float* __restrict__ bs0, const float* __restrict__ bs1,
                   float* __restrict__ C0, float* __restrict__ C1,
                   int M, int N, int K, long sA, long sB, long sC, float alpha)
{
    __shared__ float As[BK][BM];
    __shared__ float Bs[BK][BN];

    const int sel = blockIdx.z >> 1, bat = blockIdx.z & 1;
    const float* A = (sel ? A1 : A0) + (long)bat * sA;
    const float* B = (sel ? B1 : B0) + (long)bat * sB;
    const float* bias = sel ? bs1 : bs0;
    float* C = (sel ? C1 : C0) + (long)bat * sC;

    const int m0 = blockIdx.y * BM;
    const int n0 = blockIdx.x * BN;
    const int tid = threadIdx.x;
    const int tx = tid & 15;
    const int ty = tid >> 4;
    const int idx = tid * 4;

    ull acc[4][TN];
    #pragma unroll
    for (int i = 0; i < 4; i++)
        #pragma unroll
        for (int j = 0; j < TN; j++) acc[i][j] = 0ULL;

    for (int k0 = 0; k0 < K; k0 += BK) {
        if (TRANS_A) {
            const int kk = idx / BM;
            const int mm = idx % BM;
            const float4 v = *reinterpret_cast<const float4*>(
                A + (long)(k0 + kk) * M + (m0 + mm));
            *reinterpret_cast<float4*>(&As[kk][mm]) = v;
        } else {
            const int mm = idx / BK;
            const int kk = idx % BK;
            const int row = m0 + mm;
            float4 v = make_float4(0.f, 0.f, 0.f, 0.f);
            if (row < M)
                v = *reinterpret_cast<const float4*>(A + (long)row * K + (k0 + kk));
            As[kk + 0][mm] = v.x;
            As[kk + 1][mm] = v.y;
            As[kk + 2][mm] = v.z;
            As[kk + 3][mm] = v.w;
        }
        {
            const int kk = idx / BN;
            const int nn = idx % BN;
            const float4 v = *reinterpret_cast<const float4*>(
                B + (long)(k0 + kk) * N + (n0 + nn));
            *reinterpret_cast<float4*>(&Bs[kk][nn]) = v;
        }
        __syncthreads();

        #pragma unroll
        for (int kk = 0; kk < BK; kk++) {
            const ulonglong2 a01 = *reinterpret_cast<const ulonglong2*>(&As[kk][ty * TM]);
            const ulonglong2 a23 = *reinterpret_cast<const ulonglong2*>(&As[kk][ty * TM + 4]);
            const float4 rb0 = *reinterpret_cast<const float4*>(&Bs[kk][tx * TN]);
            const float4 rb1 = *reinterpret_cast<const float4*>(&Bs[kk][tx * TN + 4]);
            ull ap[4] = { a01.x, a01.y, a23.x, a23.y };
            float rb[8] = { rb0.x, rb0.y, rb0.z, rb0.w, rb1.x, rb1.y, rb1.z, rb1.w };
            #pragma unroll
            for (int j = 0; j < TN; j++) {
                const ull bb = pack2(rb[j], rb[j]);
                #pragma unroll
                for (int i = 0; i < 4; i++)
                    ffma2u(acc[i][j], ap[i], bb);
            }
        }
        __syncthreads();
    }

    #pragma unroll
    for (int i2 = 0; i2 < 4; i2++) {
        float2 lo[TN];
        #pragma unroll
        for (int j = 0; j < TN; j++) lo[j] = unpack2(acc[i2][j]);
        #pragma unroll
        for (int half = 0; half < 2; half++) {
            const int row = m0 + ty * TM + 2 * i2 + half;
            if (row >= M) continue;
            const float bv = (EPI == 1) ? bias[row] : 0.f;
            float r[TN];
            #pragma unroll
            for (int j = 0; j < TN; j++) r[j] = half ? lo[j].y : lo[j].x;
            #pragma unroll
            for (int j = 0; j < TN; j += 4) {
                float4 v = make_float4(r[j], r[j+1], r[j+2], r[j+3]);
                if (EPI == 1) { v.x += bv; v.y += bv; v.z += bv; v.w += bv; }
                if (EPI == 2) { v.x *= alpha; v.y *= alpha; v.z *= alpha; v.w *= alpha; }
                *reinterpret_cast<float4*>(C + (long)row * N + n0 + tx * TN + j) = v;
            }
        }
    }
}

// ---------------- tf32 pre-round of raw tensors into g_traw slots ----------------
__global__ __launch_bounds__(256)
void round_tf32_kernel(const float* __restrict__ a, const float* __restrict__ b,
                       float* __restrict__ dst)
{
    const int z = blockIdx.z;
    const long slice = (long)C_IN * HW;
    const float* src = (z < 2) ? (b + z * slice) : (a + (z - 2) * slice);
    float* d = dst + z * slice;
    const long i = ((long)blockIdx.x * 256 + threadIdx.x) * 4;
    float4 v = *reinterpret_cast<const float4*>(src + i);
    v.x = cvt_tf32f(v.x); v.y = cvt_tf32f(v.y);
    v.z = cvt_tf32f(v.z); v.w = cvt_tf32f(v.w);
    *reinterpret_cast<float4*>(d + i) = v;
}

// ---------------- instance norm + LeakyReLU + re-center ----------------
__global__ __launch_bounds__(256)
void instnorm_kernel(float* __restrict__ Fa, float* __restrict__ Fb)
{
    __shared__ float sh[HW];
    __shared__ float red[8];
    float* F = blockIdx.z ? Fb : Fa;
    float* row = F + ((long)blockIdx.y * C_MID + blockIdx.x) * HW;
    const int tid = threadIdx.x;

    float s = 0.f, s2 = 0.f;
    for (int i = tid; i < HW; i += 256) {
        const float v = row[i];
        sh[i] = v; s += v; s2 += v * v;
    }
    s  = blk_sum(s,  red);
    s2 = blk_sum(s2, red);
    const float mean = s * (1.f / HW);
    const float var  = s2 * (1.f / HW) - mean * mean;
    const float inv  = rsqrtf(var + 1e-5f);

    float s3 = 0.f;
    for (int i = tid; i < HW; i += 256) {
        float v = (sh[i] - mean) * inv;
        v = (v >= 0.f) ? v : 0.2f * v;
        sh[i] = v;
        s3 += v;
    }
    s3 = blk_sum(s3, red);
    const float mean2 = s3 * (1.f / HW);
    for (int i = tid; i < HW; i += 256)
        row[i] = sh[i] - mean2;
}

// ---------------- per-column L2 normalize ----------------
__global__ __launch_bounds__(256)
void l2norm_kernel(float* __restrict__ Fa, float* __restrict__ Fb)
{
    float* F = blockIdx.z ? Fb : Fa;
    const int l = blockIdx.x * 256 + threadIdx.x;
    float* base = F + (long)blockIdx.y * C_MID * HW + l;
    float s = 0.f;
    #pragma unroll 8
    for (int cc = 0; cc < C_MID; cc++) {
        const float v = base[(long)cc * HW];
        s += v * v;
    }
    const float inv = rsqrtf(s);
    #pragma unroll 8
    for (int cc = 0; cc < C_MID; cc++)
        base[(long)cc * HW] *= inv;
}

// ---------------- in-place row softmax ----------------
__global__ __launch_bounds__(256)
void softmax_kernel(float* __restrict__ E)
{
    __shared__ float sh[HW];
    __shared__ float red[8];
    float* row = E + ((long)blockIdx.y * HW + blockIdx.x) * HW;
    const int tid = threadIdx.x;

    float mx = -3.4e38f;
    for (int i = tid; i < HW; i += 256) {
        const float v = row[i];
        sh[i] = v;
        mx = fmaxf(mx, v);
    }
    mx = blk_max(mx, red);

    float s = 0.f;
    for (int i = tid; i < HW; i += 256) {
        const float e = __expf(sh[i] - mx);
        sh[i] = e;
        s += e;
    }
    s = blk_sum(s, red);
    const float inv = 1.f / s;
    for (int i = tid; i < HW; i += 256)
        row[i] = sh[i] * inv;
}

// ---------------- launch ----------------
extern "C" void kernel_launch(void* const* d_in, const int* in_sizes, int n_in,
                              void* d_out, int out_size)
{
    const float* fa    = (const float*)d_in[0];
    const float* fb    = (const float*)d_in[1];
    const float* a_raw = (const float*)d_in[2];
    const float* b_raw = (const float*)d_in[3];
    const float* Wa    = (const float*)d_in[4];
    const float* ba    = (const float*)d_in[5];
    const float* Wb    = (const float*)d_in[6];
    const float* bb    = (const float*)d_in[7];
    float* out = (float*)d_out;

    float *pfa, *pfb, *ptraw;
    cudaGetSymbolAddress((void**)&pfa, g_fa);
    cudaGetSymbolAddress((void**)&pfb, g_fb);
    cudaGetSymbolAddress((void**)&ptraw, g_traw);

    cudaFuncSetAttribute(wgemm_mma_kernel,
                         cudaFuncAttributeMaxDynamicSharedMemorySize, WG_SMEM);

    const long CORR = (long)HW * HW;
    float* corr_ab = out;
    float* corr_ba = out + (long)N_B * CORR;
    float* a_warp  = out + 2L * N_B * CORR;
    float* b_warp  = a_warp + (long)N_B * C_IN * HW;

    const dim3 blk(256);
    const long sMID = (long)C_MID * HW;
    const long sIN  = (long)C_IN * HW;

    // 1) 1x1 conv (fp32 f32x2)
    {
        dim3 g(HW / BN, (C_MID + BM - 1) / BM, 4);
        sgemm2_kernel<false, 1><<<g, blk>>>(Wa, Wb, fa, fb, ba, bb, pfa, pfb,
                                            C_MID, HW, C_IN, 0L, sIN, sMID, 0.f);
    }
    // 2) InstanceNorm + LeakyReLU + re-center
    {
        dim3 g(C_MID, N_B, 2);
        instnorm_kernel<<<g, blk>>>(pfa, pfb);
    }
    // 3) per-column L2 normalize
    {
        dim3 g(HW / 256, N_B, 2);
        l2norm_kernel<<<g, blk>>>(pfa, pfb);
    }
    // 4) energy GEMMs (fp32 f32x2), x100 into corr regions
    {
        dim3 g(HW / BN, HW / BM, 4);
        sgemm2_kernel<true, 2><<<g, blk>>>(pfb, pfa, pfa, pfb, nullptr, nullptr,
                                           corr_ab, corr_ba,
                                           HW, HW, C_MID, sMID, sMID, CORR, 100.f);
    }
    // 5) softmax over all corr rows
    {
        dim3 g(HW, 2 * N_B);
        softmax_kernel<<<g, blk>>>(out);
    }
    // 6) pre-round raw tensors to tf32 (slots: b0,b1,a0,a1)
    {
        dim3 g((unsigned)(sIN / 4 / 256), 1, 4);
        round_tf32_kernel<<<g, blk>>>(a_raw, b_raw, ptraw);
    }
    // 7) warp GEMMs on mma.sync tf32 (CTA 128x256, 3-stage pipeline)
    {
        dim3 g(HW / 256, (C_IN + 127) / 128, 4);
        wgemm_mma_kernel<<<g, blk, WG_SMEM>>>(ptraw, out, b_warp, a_warp);
    }
}

// round 7
// speedup vs baseline: 1.0485x; 1.0485x over previous
#include <cuda_runtime.h>
#include <math.h>
#include <stdint.h>
#include <stddef.h>

// ---------------- problem constants ----------------
#define N_B   2
#define C_IN  1088
#define C_MID 136
#define HW    4096

typedef unsigned long long ull;

// ---------------- device scratch ----------------
__device__ __align__(16) float g_fa[N_B * C_MID * HW];
__device__ __align__(16) float g_fb[N_B * C_MID * HW];
// tf32-rounded raw, slot z: 0,1 = b_raw batches; 2,3 = a_raw batches
__device__ __align__(16) float g_traw[4ULL * C_IN * HW];

// ---------------- helpers ----------------
__device__ __forceinline__ ull pack2(float x, float y) {
    ull r; asm("mov.b64 %0, {%1, %2};" : "=l"(r) : "f"(x), "f"(y)); return r;
}
__device__ __forceinline__ float2 unpack2(ull v) {
    float2 f; asm("mov.b64 {%0, %1}, %2;" : "=f"(f.x), "=f"(f.y) : "l"(v)); return f;
}
__device__ __forceinline__ void ffma2u(ull& d, ull a, ull b) {
    asm("fma.rn.f32x2 %0, %1, %2, %0;" : "+l"(d) : "l"(a), "l"(b));
}
__device__ __forceinline__ uint32_t cvt_tf32(float f) {
    uint32_t u; asm("cvt.rna.tf32.f32 %0, %1;" : "=r"(u) : "f"(f)); return u;
}
__device__ __forceinline__ float cvt_tf32f(float f) {
    return __uint_as_float(cvt_tf32(f));
}
__device__ __forceinline__ void cp16(uint32_t dst, const void* src, uint32_t sz) {
    asm volatile("cp.async.ca.shared.global [%0], [%1], 16, %2;"
                 :: "r"(dst), "l"(src), "r"(sz));
}
__device__ __forceinline__ void cp_commit() { asm volatile("cp.async.commit_group;"); }
__device__ __forceinline__ void cp_wait0()  { asm volatile("cp.async.wait_group 0;" ::: "memory"); }
__device__ __forceinline__ void cp_wait1()  { asm volatile("cp.async.wait_group 1;" ::: "memory"); }

__device__ __forceinline__ float blk_sum(float v, float* red) {
    const int tid = threadIdx.x;
    #pragma unroll
    for (int o = 16; o > 0; o >>= 1) v += __shfl_down_sync(0xffffffffu, v, o);
    if ((tid & 31) == 0) red[tid >> 5] = v;
    __syncthreads();
    if (tid < 32) {
        v = (tid < 8) ? red[tid] : 0.f;
        #pragma unroll
        for (int o = 4; o > 0; o >>= 1) v += __shfl_down_sync(0xffffffffu, v, o);
        if (tid == 0) red[0] = v;
    }
    __syncthreads();
    v = red[0];
    __syncthreads();
    return v;
}

__device__ __forceinline__ float blk_max(float v, float* red) {
    const int tid = threadIdx.x;
    #pragma unroll
    for (int o = 16; o > 0; o >>= 1) v = fmaxf(v, __shfl_down_sync(0xffffffffu, v, o));
    if ((tid & 31) == 0) red[tid >> 5] = v;
    __syncthreads();
    if (tid < 32) {
        v = (tid < 8) ? red[tid] : -3.4e38f;
        #pragma unroll
        for (int o = 4; o > 0; o >>= 1) v = fmaxf(v, __shfl_down_sync(0xffffffffu, v, o));
        if (tid == 0) red[0] = v;
    }
    __syncthreads();
    v = red[0];
    __syncthreads();
    return v;
}

// ---------------- mma.sync tf32 primitive ----------------
__device__ __forceinline__ void mma_tf32(float4& c, const uint32_t a[4], const uint32_t b[2]) {
    asm volatile(
        "mma.sync.aligned.m16n8k8.row.col.f32.tf32.tf32.f32 "
        "{%0,%1,%2,%3},{%4,%5,%6,%7},{%8,%9},{%0,%1,%2,%3};"
        : "+f"(c.x), "+f"(c.y), "+f"(c.z), "+f"(c.w)
        : "r"(a[0]), "r"(a[1]), "r"(a[2]), "r"(a[3]), "r"(b[0]), "r"(b[1]));
}

// ---------------- warp-stage GEMM: mma.sync tf32, CTA 128x256, 3-stage cp.async ----------------
#define ST_A_PAD 36
#define ST_B_PAD 264
#define ST_A_BYTES (128 * ST_A_PAD * 4)      // 18432
#define ST_B_BYTES (32 * ST_B_PAD * 4)       // 33792
#define ST_BYTES   (ST_A_BYTES + ST_B_BYTES) // 52224
#define N_STAGE 3
#define WG_SMEM (N_STAGE * ST_BYTES)         // 156672

__global__ __launch_bounds__(256)
void wgemm_mma_kernel(const float* __restrict__ Araw, const float* __restrict__ corr,
                      float* __restrict__ b_warp, float* __restrict__ a_warp)
{
    extern __shared__ float sm[];
    const uint32_t smem_base = (uint32_t)__cvta_generic_to_shared(sm);

    const int z = blockIdx.z;
    const float* A = Araw + (size_t)z * C_IN * HW;
    const float* B = corr + (size_t)z * HW * HW;     // corr slots contiguous: ab0,ab1,ba0,ba1
    float* C = (z < 2) ? (b_warp + (size_t)z * C_IN * HW)
                       : (a_warp + (size_t)(z - 2) * C_IN * HW);

    const int m0 = blockIdx.y * 128;
    const int n0 = blockIdx.x * 256;
    const int tid = threadIdx.x;
    const int wid = tid >> 5;
    const int lane = tid & 31;
    const int wr = wid >> 2;
    const int wc = wid & 3;
    const int r = lane >> 2;
    const int c = lane & 3;

    auto load_chunk = [&](int kc, int st) {
        const uint32_t sb = smem_base + (uint32_t)(st * ST_BYTES);
        const int k0 = kc * 32;
        #pragma unroll
        for (int p = 0; p < 4; p++) {               // A: 128 rows x 32 k
            const int u = p * 256 + tid;
            const int row = u >> 3, q = u & 7;
            const int gr = m0 + row;
            const uint32_t dst = sb + (uint32_t)((row * ST_A_PAD + q * 4) * 4);
            const float* src = A + (size_t)((gr < C_IN) ? gr : 0) * HW + k0 + q * 4;
            cp16(dst, src, (gr < C_IN) ? 16u : 0u);
        }
        #pragma unroll
        for (int p = 0; p < 8; p++) {               // B: 32 k x 256 n
            const int u = p * 256 + tid;
            const int k = u >> 6, nb = u & 63;
            const uint32_t dst = sb + ST_A_BYTES + (uint32_t)((k * ST_B_PAD + nb * 4) * 4);
            const float* src = B + (size_t)(k0 + k) * HW + n0 + nb * 4;
            cp16(dst, src, 16u);
        }
        cp_commit();
    };

    float4 acc[4][8];
    #pragma unroll
    for (int i = 0; i < 4; i++)
        #pragma unroll
        for (int j = 0; j < 8; j++) acc[i][j] = make_float4(0.f, 0.f, 0.f, 0.f);

    const int NC = HW / 32;
    load_chunk(0, 0);
    load_chunk(1, 1);

    int st = 0;
    for (int j = 0; j < NC; j++) {
        if (j + 2 < NC) cp_wait1(); else cp_wait0();
        __syncthreads();
        if (j + 2 < NC) {
            int st2 = st + 2; if (st2 >= N_STAGE) st2 -= N_STAGE;
            load_chunk(j + 2, st2);
        }

        const float* As = sm + st * (ST_BYTES / 4);
        const float* Bs = As + ST_A_BYTES / 4;
        #pragma unroll
        for (int s = 0; s < 4; s++) {
            uint32_t a[4][4], b[8][2];
            #pragma unroll
            for (int mt = 0; mt < 4; mt++) {
                const float* ap = As + (wr * 64 + mt * 16 + r) * ST_A_PAD + s * 8 + c;
                a[mt][0] = __float_as_uint(ap[0]);
                a[mt][1] = __float_as_uint(ap[8 * ST_A_PAD]);
                a[mt][2] = __float_as_uint(ap[4]);
                a[mt][3] = __float_as_uint(ap[8 * ST_A_PAD + 4]);
            }
            #pragma unroll
            for (int nt = 0; nt < 8; nt++) {
                const float* bp = Bs + (s * 8 + c) * ST_B_PAD + wc * 64 + nt * 8 + r;
                b[nt][0] = cvt_tf32(bp[0]);
                b[nt][1] = cvt_tf32(bp[4 * ST_B_PAD]);
            }
            #pragma unroll
            for (int mt = 0; mt < 4; mt++)
                #pragma unroll
                for (int nt = 0; nt < 8; nt++)
                    mma_tf32(acc[mt][nt], a[mt], b[nt]);
        }
        if (++st >= N_STAGE) st -= N_STAGE;
    }

    const int gid = lane >> 2;
    const int tig = lane & 3;
    #pragma unroll
    for (int mt = 0; mt < 4; mt++) {
        const int r0 = m0 + wr * 64 + mt * 16 + gid;
        const int r1 = r0 + 8;
        #pragma unroll
        for (int nt = 0; nt < 8; nt++) {
            const int col = n0 + wc * 64 + nt * 8 + tig * 2;
            const float4 cc = acc[mt][nt];
            if (r0 < C_IN)
                *reinterpret_cast<float2*>(C + (size_t)r0 * HW + col) = make_float2(cc.x, cc.y);
            if (r1 < C_IN)
                *reinterpret_cast<float2*>(C + (size_t)r1 * HW + col) = make_float2(cc.z, cc.w);
        }
    }
}

// ---------------- fp32 SIMT GEMM with packed f32x2 FMA (conv main + energy) ----------------
#define BM 128
#define BN 128
#define BK 8
#define TM 8
#define TN 8

template<bool TRANS_A, int EPI>
__global__ __launch_bounds__(256, 2)
void sgemm2_kernel(const float* __restrict__ A0, const float* __restrict__ A1,
                   const float* __restrict__ B0, const float* __restrict__ B1,
                   const float* __restrict__ bs0, const float* __restrict__ bs1,
                   float* __restrict__ C0, float* __restrict__ C1,
                   int M, int N, int K, long sA, long sB, long sC, float alpha)
{
    __shared__ float As[BK][BM];
    __shared__ float Bs[BK][BN];

    const int sel = blockIdx.z >> 1, bat = blockIdx.z & 1;
    const float* A = (sel ? A1 : A0) + (long)bat * sA;
    const float* B = (sel ? B1 : B0) + (long)bat * sB;
    const float* bias = sel ? bs1 : bs0;
    float* C = (sel ? C1 : C0) + (long)bat * sC;

    const int m0 = blockIdx.y * BM;
    const int n0 = blockIdx.x * BN;
    const int tid = threadIdx.x;
    const int tx = tid & 15;
    const int ty = tid >> 4;
    const int idx = tid * 4;

    ull acc[4][TN];
    #pragma unroll
    for (int i = 0; i < 4; i++)
        #pragma unroll
        for (int j = 0; j < TN; j++) acc[i][j] = 0ULL;

    for (int k0 = 0; k0 < K; k0 += BK) {
        if (TRANS_A) {
            const int kk = idx / BM;
            const int mm = idx % BM;
            const float4 v = *reinterpret_cast<const float4*>(
                A + (long)(k0 + kk) * M + (m0 + mm));
            *reinterpret_cast<float4*>(&As[kk][mm]) = v;
        } else {
            const int mm = idx / BK;
            const int kk = idx % BK;
            const int row = m0 + mm;
            float4 v = make_float4(0.f, 0.f, 0.f, 0.f);
            if (row < M)
                v = *reinterpret_cast<const float4*>(A + (long)row * K + (k0 + kk));
            As[kk + 0][mm] = v.x;
            As[kk + 1][mm] = v.y;
            As[kk + 2][mm] = v.z;
            As[kk + 3][mm] = v.w;
        }
        {
            const int kk = idx / BN;
            const int nn = idx % BN;
            const float4 v = *reinterpret_cast<const float4*>(
                B + (long)(k0 + kk) * N + (n0 + nn));
            *reinterpret_cast<float4*>(&Bs[kk][nn]) = v;
        }
        __syncthreads();

        #pragma unroll
        for (int kk = 0; kk < BK; kk++) {
            const ulonglong2 a01 = *reinterpret_cast<const ulonglong2*>(&As[kk][ty * TM]);
            const ulonglong2 a23 = *reinterpret_cast<const ulonglong2*>(&As[kk][ty * TM + 4]);
            const float4 rb0 = *reinterpret_cast<const float4*>(&Bs[kk][tx * TN]);
            const float4 rb1 = *reinterpret_cast<const float4*>(&Bs[kk][tx * TN + 4]);
            ull ap[4] = { a01.x, a01.y, a23.x, a23.y };
            float rb[8] = { rb0.x, rb0.y, rb0.z, rb0.w, rb1.x, rb1.y, rb1.z, rb1.w };
            #pragma unroll
            for (int j = 0; j < TN; j++) {
                const ull bb = pack2(rb[j], rb[j]);
                #pragma unroll
                for (int i = 0; i < 4; i++)
                    ffma2u(acc[i][j], ap[i], bb);
            }
        }
        __syncthreads();
    }

    #pragma unroll
    for (int i2 = 0; i2 < 4; i2++) {
        float2 lo[TN];
        #pragma unroll
        for (int j = 0; j < TN; j++) lo[j] = unpack2(acc[i2][j]);
        #pragma unroll
        for (int half = 0; half < 2; half++) {
            const int row = m0 + ty * TM + 2 * i2 + half;
            if (row >= M) continue;
            const float bv = (EPI == 1) ? bias[row] : 0.f;
            float r[TN];
            #pragma unroll
            for (int j = 0; j < TN; j++) r[j] = half ? lo[j].y : lo[j].x;
            #pragma unroll
            for (int j = 0; j < TN; j += 4) {
                float4 v = make_float4(r[j], r[j+1], r[j+2], r[j+3]);
                if (EPI == 1) { v.x += bv; v.y += bv; v.z += bv; v.w += bv; }
                if (EPI == 2) { v.x *= alpha; v.y *= alpha; v.z *= alpha; v.w *= alpha; }
                *reinterpret_cast<float4*>(C + (long)row * N + n0 + tx * TN + j) = v;
            }
        }
    }
}

// ---------------- conv tail: rows 128..135 (8 rows) ----------------
// out[c, l] = bias[c] + sum_cin W[c,cin] * X[cin,l], c in [128,136)
__global__ __launch_bounds__(256)
void conv_tail_kernel(const float* __restrict__ X0, const float* __restrict__ X1,
                      const float* __restrict__ W0, const float* __restrict__ W1,
                      const float* __restrict__ b0, const float* __restrict__ b1,
                      float* __restrict__ F0, float* __restrict__ F1)
{
    __shared__ float ws[8 * C_IN];
    const int sel = blockIdx.z >> 1, bat = blockIdx.z & 1;
    const float* X = (sel ? X1 : X0) + (long)bat * C_IN * HW;
    const float* W = (sel ? W1 : W0) + 128 * C_IN;
    const float* bias = (sel ? b1 : b0) + 128;
    float* F = (sel ? F1 : F0) + (long)bat * C_MID * HW + 128L * HW;

    const int tid = threadIdx.x;
    for (int i = tid; i < 8 * C_IN; i += 256) ws[i] = W[i];
    __syncthreads();

    const int l = blockIdx.x * 256 + tid;
    float acc[8];
    #pragma unroll
    for (int r2 = 0; r2 < 8; r2++) acc[r2] = 0.f;

    #pragma unroll 8
    for (int cin = 0; cin < C_IN; cin++) {
        const float x = X[(long)cin * HW + l];
        #pragma unroll
        for (int r2 = 0; r2 < 8; r2++)
            acc[r2] = fmaf(ws[r2 * C_IN + cin], x, acc[r2]);
    }
    #pragma unroll
    for (int r2 = 0; r2 < 8; r2++)
        F[(long)r2 * HW + l] = acc[r2] + bias[r2];
}

// ---------------- tiled transpose: corr_ba[k,l] = corr_ab_energy[l,k] ----------------
__global__ __launch_bounds__(256)
void etrans_kernel(const float* __restrict__ in, float* __restrict__ outT)
{
    __shared__ float t[32][33];
    const size_t off = (size_t)blockIdx.z * HW * HW;
    const int x0 = blockIdx.x * 32, y0 = blockIdx.y * 32;
    const int tx = threadIdx.x & 31, ty = threadIdx.x >> 5;   // 32 x 8
    #pragma unroll
    for (int i = 0; i < 32; i += 8)
        t[ty + i][tx] = in[off + (size_t)(y0 + ty + i) * HW + x0 + tx];
    __syncthreads();
    #pragma unroll
    for (int i = 0; i < 32; i += 8)
        outT[off + (size_t)(x0 + ty + i) * HW + y0 + tx] = t[tx][ty + i];
}

// ---------------- tf32 pre-round of raw tensors into g_traw slots ----------------
__global__ __launch_bounds__(256)
void round_tf32_kernel(const float* __restrict__ a, const float* __restrict__ b,
                       float* __restrict__ dst)
{
    const int z = blockIdx.z;
    const long slice = (long)C_IN * HW;
    const float* src = (z < 2) ? (b + z * slice) : (a + (z - 2) * slice);
    float* d = dst + z * slice;
    const long i = ((long)blockIdx.x * 256 + threadIdx.x) * 4;
    float4 v = *reinterpret_cast<const float4*>(src + i);
    v.x = cvt_tf32f(v.x); v.y = cvt_tf32f(v.y);
    v.z = cvt_tf32f(v.z); v.w = cvt_tf32f(v.w);
    *reinterpret_cast<float4*>(d + i) = v;
}

// ---------------- instance norm + LeakyReLU + re-center ----------------
__global__ __launch_bounds__(256)
void instnorm_kernel(float* __restrict__ Fa, float* __restrict__ Fb)
{
    __shared__ float sh[HW];
    __shared__ float red[8];
    float* F = blockIdx.z ? Fb : Fa;
    float* row = F + ((long)blockIdx.y * C_MID + blockIdx.x) * HW;
    const int tid = threadIdx.x;

    float s = 0.f, s2 = 0.f;
    for (int i = tid; i < HW; i += 256) {
        const float v = row[i];
        sh[i] = v; s += v; s2 += v * v;
    }
    s  = blk_sum(s,  red);
    s2 = blk_sum(s2, red);
    const float mean = s * (1.f / HW);
    const float var  = s2 * (1.f / HW) - mean * mean;
    const float inv  = rsqrtf(var + 1e-5f);

    float s3 = 0.f;
    for (int i = tid; i < HW; i += 256) {
        float v = (sh[i] - mean) * inv;
        v = (v >= 0.f) ? v : 0.2f * v;
        sh[i] = v;
        s3 += v;
    }
    s3 = blk_sum(s3, red);
    const float mean2 = s3 * (1.f / HW);
    for (int i = tid; i < HW; i += 256)
        row[i] = sh[i] - mean2;
}

// ---------------- per-column L2 normalize ----------------
__global__ __launch_bounds__(256)
void l2norm_kernel(float* __restrict__ Fa, float* __restrict__ Fb)
{
    float* F = blockIdx.z ? Fb : Fa;
    const int l = blockIdx.x * 256 + threadIdx.x;
    float* base = F + (long)blockIdx.y * C_MID * HW + l;
    float s = 0.f;
    #pragma unroll 8
    for (int cc = 0; cc < C_MID; cc++) {
        const float v = base[(long)cc * HW];
        s += v * v;
    }
    const float inv = rsqrtf(s);
    #pragma unroll 8
    for (int cc = 0; cc < C_MID; cc++)
        base[(long)cc * HW] *= inv;
}

// ---------------- in-place row softmax ----------------
__global__ __launch_bounds__(256)
void softmax_kernel(float* __restrict__ E)
{
    __shared__ float sh[HW];
    __shared__ float red[8];
    float* row = E + ((long)blockIdx.y * HW + blockIdx.x) * HW;
    const int tid = threadIdx.x;

    float mx = -3.4e38f;
    for (int i = tid; i < HW; i += 256) {
        const float v = row[i];
        sh[i] = v;
        mx = fmaxf(mx, v);
    }
    mx = blk_max(mx, red);

    float s = 0.f;
    for (int i = tid; i < HW; i += 256) {
        const float e = __expf(sh[i] - mx);
        sh[i] = e;
        s += e;
    }
    s = blk_sum(s, red);
    const float inv = 1.f / s;
    for (int i = tid; i < HW; i += 256)
        row[i] = sh[i] * inv;
}

// ---------------- launch ----------------
extern "C" void kernel_launch(void* const* d_in, const int* in_sizes, int n_in,
                              void* d_out, int out_size)
{
    const float* fa    = (const float*)d_in[0];
    const float* fb    = (const float*)d_in[1];
    const float* a_raw = (const float*)d_in[2];
    const float* b_raw = (const float*)d_in[3];
    const float* Wa    = (const float*)d_in[4];
    const float* ba    = (const float*)d_in[5];
    const float* Wb    = (const float*)d_in[6];
    const float* bb    = (const float*)d_in[7];
    float* out = (float*)d_out;

    float *pfa, *pfb, *ptraw;
    cudaGetSymbolAddress((void**)&pfa, g_fa);
    cudaGetSymbolAddress((void**)&pfb, g_fb);
    cudaGetSymbolAddress((void**)&ptraw, g_traw);

    cudaFuncSetAttribute(wgemm_mma_kernel,
                         cudaFuncAttributeMaxDynamicSharedMemorySize, WG_SMEM);

    const long CORR = (long)HW * HW;
    float* corr_ab = out;
    float* corr_ba = out + (long)N_B * CORR;
    float* a_warp  = out + 2L * N_B * CORR;
    float* b_warp  = a_warp + (long)N_B * C_IN * HW;

    const dim3 blk(256);
    const long sMID = (long)C_MID * HW;
    const long sIN  = (long)C_IN * HW;

    // 1) 1x1 conv main tile: rows 0..127 only (no padded second tile)
    {
        dim3 g(HW / BN, 1, 4);
        sgemm2_kernel<false, 1><<<g, blk>>>(Wa, Wb, fa, fb, ba, bb, pfa, pfb,
                                            C_MID, HW, C_IN, 0L, sIN, sMID, 0.f);
    }
    // 1b) conv tail: rows 128..135
    {
        dim3 g(HW / 256, 1, 4);
        conv_tail_kernel<<<g, blk>>>(fa, fb, Wa, Wb, ba, bb, pfa, pfb);
    }
    // 2) InstanceNorm + LeakyReLU + re-center
    {
        dim3 g(C_MID, N_B, 2);
        instnorm_kernel<<<g, blk>>>(pfa, pfb);
    }
    // 3) per-column L2 normalize
    {
        dim3 g(HW / 256, N_B, 2);
        l2norm_kernel<<<g, blk>>>(pfa, pfb);
    }
    // 4) energy GEMM — ab direction ONLY (ba is its transpose), x100 into corr_ab
    {
        dim3 g(HW / BN, HW / BM, 2);
        sgemm2_kernel<true, 2><<<g, blk>>>(pfb, pfb, pfa, pfa, nullptr, nullptr,
                                           corr_ab, corr_ab,
                                           HW, HW, C_MID, sMID, sMID, CORR, 100.f);
    }
    // 4b) transpose E into corr_ba region (energy_ba = energy_ab^T)
    {
        dim3 g(HW / 32, HW / 32, 2);
        etrans_kernel<<<g, blk>>>(corr_ab, corr_ba);
    }
    // 5) softmax over all corr rows (both directions, both batches)
    {
        dim3 g(HW, 2 * N_B);
        softmax_kernel<<<g, blk>>>(out);
    }
    // 6) pre-round raw tensors to tf32 (slots: b0,b1,a0,a1)
    {
        dim3 g((unsigned)(sIN / 4 / 256), 1, 4);
        round_tf32_kernel<<<g, blk>>>(a_raw, b_raw, ptraw);
    }
    // 7) warp GEMMs on mma.sync tf32 (CTA 128x256, 3-stage pipeline)
    {
        dim3 g(HW / 256, (C_IN + 127) / 128, 4);
        wgemm_mma_kernel<<<g, blk, WG_SMEM>>>(ptraw, out, b_warp, a_warp);
    }
}

// round 8
// speedup vs baseline: 1.2379x; 1.1807x over previous
#include <cuda_runtime.h>
#include <cuda_fp16.h>
#include <math.h>
#include <stdint.h>
#include <stddef.h>

// ---------------- problem constants ----------------
#define N_B   2
#define C_IN  1088
#define C_MID 136
#define HW    4096

typedef unsigned long long ull;

// ---------------- device scratch ----------------
__device__ __align__(16) float g_fa[N_B * C_MID * HW];
__device__ __align__(16) float g_fb[N_B * C_MID * HW];
// fp16 raw, slot z: 0,1 = b_raw batches; 2,3 = a_raw batches
__device__ __align__(16) __half g_rawh[4ULL * C_IN * HW];
// fp16 transposed softmaxed corr: [4][n=HW][k=HW]
__device__ __align__(16) __half g_ch[4ULL * HW * HW];

// ---------------- helpers ----------------
__device__ __forceinline__ ull pack2(float x, float y) {
    ull r; asm("mov.b64 %0, {%1, %2};" : "=l"(r) : "f"(x), "f"(y)); return r;
}
__device__ __forceinline__ float2 unpack2(ull v) {
    float2 f; asm("mov.b64 {%0, %1}, %2;" : "=f"(f.x), "=f"(f.y) : "l"(v)); return f;
}
__device__ __forceinline__ void ffma2u(ull& d, ull a, ull b) {
    asm("fma.rn.f32x2 %0, %1, %2, %0;" : "+l"(d) : "l"(a), "l"(b));
}
__device__ __forceinline__ void cp16(uint32_t dst, const void* src, uint32_t sz) {
    asm volatile("cp.async.ca.shared.global [%0], [%1], 16, %2;"
                 :: "r"(dst), "l"(src), "r"(sz));
}
__device__ __forceinline__ void cp_commit() { asm volatile("cp.async.commit_group;"); }
__device__ __forceinline__ void cp_wait0()  { asm volatile("cp.async.wait_group 0;" ::: "memory"); }
__device__ __forceinline__ void cp_wait1()  { asm volatile("cp.async.wait_group 1;" ::: "memory"); }

__device__ __forceinline__ float blk_sum(float v, float* red) {
    const int tid = threadIdx.x;
    #pragma unroll
    for (int o = 16; o > 0; o >>= 1) v += __shfl_down_sync(0xffffffffu, v, o);
    if ((tid & 31) == 0) red[tid >> 5] = v;
    __syncthreads();
    if (tid < 32) {
        v = (tid < 8) ? red[tid] : 0.f;
        #pragma unroll
        for (int o = 4; o > 0; o >>= 1) v += __shfl_down_sync(0xffffffffu, v, o);
        if (tid == 0) red[0] = v;
    }
    __syncthreads();
    v = red[0];
    __syncthreads();
    return v;
}

__device__ __forceinline__ float blk_max(float v, float* red) {
    const int tid = threadIdx.x;
    #pragma unroll
    for (int o = 16; o > 0; o >>= 1) v = fmaxf(v, __shfl_down_sync(0xffffffffu, v, o));
    if ((tid & 31) == 0) red[tid >> 5] = v;
    __syncthreads();
    if (tid < 32) {
        v = (tid < 8) ? red[tid] : -3.4e38f;
        #pragma unroll
        for (int o = 4; o > 0; o >>= 1) v = fmaxf(v, __shfl_down_sync(0xffffffffu, v, o));
        if (tid == 0) red[0] = v;
    }
    __syncthreads();
    v = red[0];
    __syncthreads();
    return v;
}

// ---------------- mma.sync fp16 primitive (f32 accumulate) ----------------
__device__ __forceinline__ void mma_f16(float4& c, const uint32_t a[4], const uint32_t b[2]) {
    asm volatile(
        "mma.sync.aligned.m16n8k16.row.col.f32.f16.f16.f32 "
        "{%0,%1,%2,%3},{%4,%5,%6,%7},{%8,%9},{%0,%1,%2,%3};"
        : "+f"(c.x), "+f"(c.y), "+f"(c.z), "+f"(c.w)
        : "r"(a[0]), "r"(a[1]), "r"(a[2]), "r"(a[3]), "r"(b[0]), "r"(b[1]));
}

// ---------------- warp-stage GEMM: fp16 mma, CTA 128x256, 3-stage cp.async ----------------
// C[z][1088,4096] = rawh[z] @ ch[z]^T ; A fp16 [m][k], B fp16 [n][k] (pre-transposed).
#define HA_PITCH 40                         // halfs per A smem row
#define HB_PITCH 40
#define HA_BYTES (128 * HA_PITCH * 2)       // 10240
#define HB_BYTES (256 * HB_PITCH * 2)       // 20480
#define HST_BYTES (HA_BYTES + HB_BYTES)     // 30720
#define HN_STAGE 3
#define WH_SMEM (HN_STAGE * HST_BYTES)      // 92160

__global__ __launch_bounds__(256)
void wgemm_f16_kernel(const __half* __restrict__ Ah, const __half* __restrict__ Bh,
                      float* __restrict__ b_warp, float* __restrict__ a_warp)
{
    extern __shared__ char smc[];
    const uint32_t smem_base = (uint32_t)__cvta_generic_to_shared(smc);

    const int z = blockIdx.z;
    const __half* A = Ah + (size_t)z * C_IN * HW;
    const __half* B = Bh + (size_t)z * HW * HW;
    float* C = (z < 2) ? (b_warp + (size_t)z * C_IN * HW)
                       : (a_warp + (size_t)(z - 2) * C_IN * HW);

    const int m0 = blockIdx.y * 128;
    const int n0 = blockIdx.x * 256;
    const int tid = threadIdx.x;
    const int wid = tid >> 5;
    const int lane = tid & 31;
    const int wr = wid >> 2;              // 0..1 -> 64 M rows
    const int wc = wid & 3;               // 0..3 -> 64 N cols
    const int g = lane >> 2;              // 0..7
    const int tig = lane & 3;             // 0..3

    auto load_chunk = [&](int kc, int st) {
        const uint32_t sb = smem_base + (uint32_t)(st * HST_BYTES);
        const int k0 = kc * 32;
        #pragma unroll
        for (int p = 0; p < 2; p++) {     // A: 128 rows x 32 halfs (4x 16B per row)
            const int u = p * 256 + tid;
            const int row = u >> 2, q = u & 3;
            const int gr = m0 + row;
            const uint32_t dst = sb + (uint32_t)(row * HA_PITCH * 2 + q * 16);
            const __half* src = A + (size_t)((gr < C_IN) ? gr : 0) * HW + k0 + q * 8;
            cp16(dst, src, (gr < C_IN) ? 16u : 0u);
        }
        #pragma unroll
        for (int p = 0; p < 4; p++) {     // B: 256 n-rows x 32 halfs
            const int u = p * 256 + tid;
            const int row = u >> 2, q = u & 3;
            const uint32_t dst = sb + HA_BYTES + (uint32_t)(row * HB_PITCH * 2 + q * 16);
            const __half* src = B + (size_t)(n0 + row) * HW + k0 + q * 8;
            cp16(dst, src, 16u);
        }
        cp_commit();
    };

    float4 acc[4][8];
    #pragma unroll
    for (int i = 0; i < 4; i++)
        #pragma unroll
        for (int j = 0; j < 8; j++) acc[i][j] = make_float4(0.f, 0.f, 0.f, 0.f);

    const int NC = HW / 32;
    load_chunk(0, 0);
    load_chunk(1, 1);

    int st = 0;
    for (int j = 0; j < NC; j++) {
        if (j + 2 < NC) cp_wait1(); else cp_wait0();
        __syncthreads();
        if (j + 2 < NC) {
            int st2 = st + 2; if (st2 >= HN_STAGE) st2 -= HN_STAGE;
            load_chunk(j + 2, st2);
        }

        const __half* As = (const __half*)(smc + st * HST_BYTES);
        const __half* Bs = (const __half*)(smc + st * HST_BYTES + HA_BYTES);
        #pragma unroll
        for (int ks = 0; ks < 2; ks++) {
            uint32_t a[4][4], b[8][2];
            #pragma unroll
            for (int mt = 0; mt < 4; mt++) {
                const __half* ap = As + (wr * 64 + mt * 16 + g) * HA_PITCH + ks * 16 + 2 * tig;
                a[mt][0] = *reinterpret_cast<const uint32_t*>(ap);
                a[mt][1] = *reinterpret_cast<const uint32_t*>(ap + 8 * HA_PITCH);
                a[mt][2] = *reinterpret_cast<const uint32_t*>(ap + 8);
                a[mt][3] = *reinterpret_cast<const uint32_t*>(ap + 8 * HA_PITCH + 8);
            }
            #pragma unroll
            for (int nt = 0; nt < 8; nt++) {
                const __half* bp = Bs + (wc * 64 + nt * 8 + g) * HB_PITCH + ks * 16 + 2 * tig;
                b[nt][0] = *reinterpret_cast<const uint32_t*>(bp);
                b[nt][1] = *reinterpret_cast<const uint32_t*>(bp + 8);
            }
            #pragma unroll
            for (int mt = 0; mt < 4; mt++)
                #pragma unroll
                for (int nt = 0; nt < 8; nt++)
                    mma_f16(acc[mt][nt], a[mt], b[nt]);
        }
        if (++st >= HN_STAGE) st -= HN_STAGE;
    }

    #pragma unroll
    for (int mt = 0; mt < 4; mt++) {
        const int r0 = m0 + wr * 64 + mt * 16 + g;
        const int r1 = r0 + 8;
        #pragma unroll
        for (int nt = 0; nt < 8; nt++) {
            const int col = n0 + wc * 64 + nt * 8 + tig * 2;
            const float4 cc = acc[mt][nt];
            if (r0 < C_IN)
                *reinterpret_cast<float2*>(C + (size_t)r0 * HW + col) = make_float2(cc.x, cc.y);
            if (r1 < C_IN)
                *reinterpret_cast<float2*>(C + (size_t)r1 * HW + col) = make_float2(cc.z, cc.w);
        }
    }
}

// ---------------- fp32 SIMT GEMM with packed f32x2 FMA (conv main + energy) ----------------
#define BM 128
#define BN 128
#define BK 8
#define TM 8
#define TN 8

template<bool TRANS_A, int EPI>
__global__ __launch_bounds__(256, 2)
void sgemm2_kernel(const float* __restrict__ A0, const float* __restrict__ A1,
                   const float* __restrict__ B0, const float* __restrict__ B1,
                   const float* __restrict__ bs0, const float* __restrict__ bs1,
                   float* __restrict__ C0, float* __restrict__ C1,
                   int M, int N, int K, long sA, long sB, long sC, float alpha)
{
    __shared__ float As[BK][BM];
    __shared__ float Bs[BK][BN];

    const int sel = blockIdx.z >> 1, bat = blockIdx.z & 1;
    const float* A = (sel ? A1 : A0) + (long)bat * sA;
    const float* B = (sel ? B1 : B0) + (long)bat * sB;
    const float* bias = sel ? bs1 : bs0;
    float* C = (sel ? C1 : C0) + (long)bat * sC;

    const int m0 = blockIdx.y * BM;
    const int n0 = blockIdx.x * BN;
    const int tid = threadIdx.x;
    const int tx = tid & 15;
    const int ty = tid >> 4;
    const int idx = tid * 4;

    ull acc[4][TN];
    #pragma unroll
    for (int i = 0; i < 4; i++)
        #pragma unroll
        for (int j = 0; j < TN; j++) acc[i][j] = 0ULL;

    for (int k0 = 0; k0 < K; k0 += BK) {
        if (TRANS_A) {
            const int kk = idx / BM;
            const int mm = idx % BM;
            const float4 v = *reinterpret_cast<const float4*>(
                A + (long)(k0 + kk) * M + (m0 + mm));
            *reinterpret_cast<float4*>(&As[kk][mm]) = v;
        } else {
            const int mm = idx / BK;
            const int kk = idx % BK;
            const int row = m0 + mm;
            float4 v = make_float4(0.f, 0.f, 0.f, 0.f);
            if (row < M)
                v = *reinterpret_cast<const float4*>(A + (long)row * K + (k0 + kk));
            As[kk + 0][mm] = v.x;
            As[kk + 1][mm] = v.y;
            As[kk + 2][mm] = v.z;
            As[kk + 3][mm] = v.w;
        }
        {
            const int kk = idx / BN;
            const int nn = idx % BN;
            const float4 v = *reinterpret_cast<const float4*>(
                B + (long)(k0 + kk) * N + (n0 + nn));
            *reinterpret_cast<float4*>(&Bs[kk][nn]) = v;
        }
        __syncthreads();

        #pragma unroll
        for (int kk = 0; kk < BK; kk++) {
            const ulonglong2 a01 = *reinterpret_cast<const ulonglong2*>(&As[kk][ty * TM]);
            const ulonglong2 a23 = *reinterpret_cast<const ulonglong2*>(&As[kk][ty * TM + 4]);
            const float4 rb0 = *reinterpret_cast<const float4*>(&Bs[kk][tx * TN]);
            const float4 rb1 = *reinterpret_cast<const float4*>(&Bs[kk][tx * TN + 4]);
            ull ap[4] = { a01.x, a01.y, a23.x, a23.y };
            float rb[8] = { rb0.x, rb0.y, rb0.z, rb0.w, rb1.x, rb1.y, rb1.z, rb1.w };
            #pragma unroll
            for (int j = 0; j < TN; j++) {
                const ull bb = pack2(rb[j], rb[j]);
                #pragma unroll
                for (int i = 0; i < 4; i++)
                    ffma2u(acc[i][j], ap[i], bb);
            }
        }
        __syncthreads();
    }

    #pragma unroll
    for (int i2 = 0; i2 < 4; i2++) {
        float2 lo[TN];
        #pragma unroll
        for (int j = 0; j < TN; j++) lo[j] = unpack2(acc[i2][j]);
        #pragma unroll
        for (int half = 0; half < 2; half++) {
            const int row = m0 + ty * TM + 2 * i2 + half;
            if (row >= M) continue;
            const float bv = (EPI == 1) ? bias[row] : 0.f;
            float r[TN];
            #pragma unroll
            for (int j = 0; j < TN; j++) r[j] = half ? lo[j].y : lo[j].x;
            #pragma unroll
            for (int j = 0; j < TN; j += 4) {
                float4 v = make_float4(r[j], r[j+1], r[j+2], r[j+3]);
                if (EPI == 1) { v.x += bv; v.y += bv; v.z += bv; v.w += bv; }
                if (EPI == 2) { v.x *= alpha; v.y *= alpha; v.z *= alpha; v.w *= alpha; }
                *reinterpret_cast<float4*>(C + (long)row * N + n0 + tx * TN + j) = v;
            }
        }
    }
}

// ---------------- conv tail: rows 128..135 ----------------
__global__ __launch_bounds__(256)
void conv_tail_kernel(const float* __restrict__ X0, const float* __restrict__ X1,
                      const float* __restrict__ W0, const float* __restrict__ W1,
                      const float* __restrict__ b0, const float* __restrict__ b1,
                      float* __restrict__ F0, float* __restrict__ F1)
{
    __shared__ float ws[8 * C_IN];
    const int sel = blockIdx.z >> 1, bat = blockIdx.z & 1;
    const float* X = (sel ? X1 : X0) + (long)bat * C_IN * HW;
    const float* W = (sel ? W1 : W0) + 128 * C_IN;
    const float* bias = (sel ? b1 : b0) + 128;
    float* F = (sel ? F1 : F0) + (long)bat * C_MID * HW + 128L * HW;

    const int tid = threadIdx.x;
    for (int i = tid; i < 8 * C_IN; i += 256) ws[i] = W[i];
    __syncthreads();

    const int l = blockIdx.x * 256 + tid;
    float acc[8];
    #pragma unroll
    for (int r2 = 0; r2 < 8; r2++) acc[r2] = 0.f;

    #pragma unroll 8
    for (int cin = 0; cin < C_IN; cin++) {
        const float x = X[(long)cin * HW + l];
        #pragma unroll
        for (int r2 = 0; r2 < 8; r2++)
            acc[r2] = fmaf(ws[r2 * C_IN + cin], x, acc[r2]);
    }
    #pragma unroll
    for (int r2 = 0; r2 < 8; r2++)
        F[(long)r2 * HW + l] = acc[r2] + bias[r2];
}

// ---------------- tiled transpose (fp32): corr_ba_energy = E^T ----------------
__global__ __launch_bounds__(256)
void etrans_kernel(const float* __restrict__ in, float* __restrict__ outT)
{
    __shared__ float t[32][33];
    const size_t off = (size_t)blockIdx.z * HW * HW;
    const int x0 = blockIdx.x * 32, y0 = blockIdx.y * 32;
    const int tx = threadIdx.x & 31, ty = threadIdx.x >> 5;
    #pragma unroll
    for (int i = 0; i < 32; i += 8)
        t[ty + i][tx] = in[off + (size_t)(y0 + ty + i) * HW + x0 + tx];
    __syncthreads();
    #pragma unroll
    for (int i = 0; i < 32; i += 8)
        outT[off + (size_t)(x0 + ty + i) * HW + y0 + tx] = t[tx][ty + i];
}

// ---------------- corr fp32 [k][n] -> fp16 transposed [n][k] ----------------
__global__ __launch_bounds__(256)
void corrcvt_kernel(const float* __restrict__ in, __half* __restrict__ outT)
{
    __shared__ float t[32][33];
    const size_t off = (size_t)blockIdx.z * HW * HW;
    const int k0 = blockIdx.y * 32, n0 = blockIdx.x * 32;
    const int tx = threadIdx.x & 31, ty = threadIdx.x >> 5;
    #pragma unroll
    for (int i = 0; i < 32; i += 8)
        t[ty + i][tx] = in[off + (size_t)(k0 + ty + i) * HW + n0 + tx];
    __syncthreads();
    #pragma unroll
    for (int i = 0; i < 2; i++) {
        const int u = i * 256 + threadIdx.x;
        const int r = u >> 4, cp = (u & 15) * 2;
        const __half2 h = __floats2half2_rn(t[cp][r], t[cp + 1][r]);
        *reinterpret_cast<__half2*>(&outT[off + (size_t)(n0 + r) * HW + k0 + cp]) = h;
    }
}

// ---------------- raw fp32 -> fp16 slots (b0,b1,a0,a1) ----------------
__global__ __launch_bounds__(256)
void rawcvt_kernel(const float* __restrict__ a, const float* __restrict__ b,
                   __half* __restrict__ dst)
{
    const int z = blockIdx.z;
    const long slice = (long)C_IN * HW;
    const float* src = (z < 2) ? (b + z * slice) : (a + (z - 2) * slice);
    __half* d = dst + z * slice;
    const long i = ((long)blockIdx.x * 256 + threadIdx.x) * 8;
    const float4 v0 = *reinterpret_cast<const float4*>(src + i);
    const float4 v1 = *reinterpret_cast<const float4*>(src + i + 4);
    __half2 h[4];
    h[0] = __floats2half2_rn(v0.x, v0.y);
    h[1] = __floats2half2_rn(v0.z, v0.w);
    h[2] = __floats2half2_rn(v1.x, v1.y);
    h[3] = __floats2half2_rn(v1.z, v1.w);
    *reinterpret_cast<uint4*>(d + i) = *reinterpret_cast<const uint4*>(h);
}

// ---------------- instance norm + LeakyReLU + re-center ----------------
__global__ __launch_bounds__(256)
void instnorm_kernel(float* __restrict__ Fa, float* __restrict__ Fb)
{
    __shared__ float sh[HW];
    __shared__ float red[8];
    float* F = blockIdx.z ? Fb : Fa;
    float* row = F + ((long)blockIdx.y * C_MID + blockIdx.x) * HW;
    const int tid = threadIdx.x;

    float s = 0.f, s2 = 0.f;
    for (int i = tid; i < HW; i += 256) {
        const float v = row[i];
        sh[i] = v; s += v; s2 += v * v;
    }
    s  = blk_sum(s,  red);
    s2 = blk_sum(s2, red);
    const float mean = s * (1.f / HW);
    const float var  = s2 * (1.f / HW) - mean * mean;
    const float inv  = rsqrtf(var + 1e-5f);

    float s3 = 0.f;
    for (int i = tid; i < HW; i += 256) {
        float v = (sh[i] - mean) * inv;
        v = (v >= 0.f) ? v : 0.2f * v;
        sh[i] = v;
        s3 += v;
    }
    s3 = blk_sum(s3, red);
    const float mean2 = s3 * (1.f / HW);
    for (int i = tid; i < HW; i += 256)
        row[i] = sh[i] - mean2;
}

// ---------------- per-column L2 normalize ----------------
__global__ __launch_bounds__(256)
void l2norm_kernel(float* __restrict__ Fa, float* __restrict__ Fb)
{
    float* F = blockIdx.z ? Fb : Fa;
    const int l = blockIdx.x * 256 + threadIdx.x;
    float* base = F + (long)blockIdx.y * C_MID * HW + l;
    float s = 0.f;
    #pragma unroll 8
    for (int cc = 0; cc < C_MID; cc++) {
        const float v = base[(long)cc * HW];
        s += v * v;
    }
    const float inv = rsqrtf(s);
    #pragma unroll 8
    for (int cc = 0; cc < C_MID; cc++)
        base[(long)cc * HW] *= inv;
}

// ---------------- in-place row softmax ----------------
__global__ __launch_bounds__(256)
void softmax_kernel(float* __restrict__ E)
{
    __shared__ float sh[HW];
    __shared__ float red[8];
    float* row = E + ((long)blockIdx.y * HW + blockIdx.x) * HW;
    const int tid = threadIdx.x;

    float mx = -3.4e38f;
    for (int i = tid; i < HW; i += 256) {
        const float v = row[i];
        sh[i] = v;
        mx = fmaxf(mx, v);
    }
    mx = blk_max(mx, red);

    float s = 0.f;
    for (int i = tid; i < HW; i += 256) {
        const float e = __expf(sh[i] - mx);
        sh[i] = e;
        s += e;
    }
    s = blk_sum(s, red);
    const float inv = 1.f / s;
    for (int i = tid; i < HW; i += 256)
        row[i] = sh[i] * inv;
}

// ---------------- launch ----------------
extern "C" void kernel_launch(void* const* d_in, const int* in_sizes, int n_in,
                              void* d_out, int out_size)
{
    const float* fa    = (const float*)d_in[0];
    const float* fb    = (const float*)d_in[1];
    const float* a_raw = (const float*)d_in[2];
    const float* b_raw = (const float*)d_in[3];
    const float* Wa    = (const float*)d_in[4];
    const float* ba    = (const float*)d_in[5];
    const float* Wb    = (const float*)d_in[6];
    const float* bb    = (const float*)d_in[7];
    float* out = (float*)d_out;

    float *pfa, *pfb;
    __half *prawh, *pch;
    cudaGetSymbolAddress((void**)&pfa, g_fa);
    cudaGetSymbolAddress((void**)&pfb, g_fb);
    cudaGetSymbolAddress((void**)&prawh, g_rawh);
    cudaGetSymbolAddress((void**)&pch, g_ch);

    cudaFuncSetAttribute(wgemm_f16_kernel,
                         cudaFuncAttributeMaxDynamicSharedMemorySize, WH_SMEM);

    const long CORR = (long)HW * HW;
    float* corr_ab = out;
    float* corr_ba = out + (long)N_B * CORR;
    float* a_warp  = out + 2L * N_B * CORR;
    float* b_warp  = a_warp + (long)N_B * C_IN * HW;

    const dim3 blk(256);
    const long sMID = (long)C_MID * HW;
    const long sIN  = (long)C_IN * HW;

    // 1) 1x1 conv main tile: rows 0..127
    {
        dim3 g(HW / BN, 1, 4);
        sgemm2_kernel<false, 1><<<g, blk>>>(Wa, Wb, fa, fb, ba, bb, pfa, pfb,
                                            C_MID, HW, C_IN, 0L, sIN, sMID, 0.f);
    }
    // 1b) conv tail: rows 128..135
    {
        dim3 g(HW / 256, 1, 4);
        conv_tail_kernel<<<g, blk>>>(fa, fb, Wa, Wb, ba, bb, pfa, pfb);
    }
    // 2) InstanceNorm + LeakyReLU + re-center
    {
        dim3 g(C_MID, N_B, 2);
        instnorm_kernel<<<g, blk>>>(pfa, pfb);
    }
    // 3) per-column L2 normalize
    {
        dim3 g(HW / 256, N_B, 2);
        l2norm_kernel<<<g, blk>>>(pfa, pfb);
    }
    // 4) energy GEMM — ab direction only (x100) into corr_ab
    {
        dim3 g(HW / BN, HW / BM, 2);
        sgemm2_kernel<true, 2><<<g, blk>>>(pfb, pfb, pfa, pfa, nullptr, nullptr,
                                           corr_ab, corr_ab,
                                           HW, HW, C_MID, sMID, sMID, CORR, 100.f);
    }
    // 4b) transpose E into corr_ba region
    {
        dim3 g(HW / 32, HW / 32, 2);
        etrans_kernel<<<g, blk>>>(corr_ab, corr_ba);
    }
    // 5) softmax over all corr rows
    {
        dim3 g(HW, 2 * N_B);
        softmax_kernel<<<g, blk>>>(out);
    }
    // 6) convert softmaxed corr -> fp16 transposed [n][k]
    {
        dim3 g(HW / 32, HW / 32, 4);
        corrcvt_kernel<<<g, blk>>>(out, pch);
    }
    // 6b) convert raw -> fp16 slots
    {
        dim3 g((unsigned)(sIN / 8 / 256), 1, 4);
        rawcvt_kernel<<<g, blk>>>(a_raw, b_raw, prawh);
    }
    // 7) warp GEMMs on fp16 mma (CTA 128x256, 3-stage pipeline)
    {
        dim3 g(HW / 256, (C_IN + 127) / 128, 4);
        wgemm_f16_kernel<<<g, blk, WH_SMEM>>>(prawh, pch, b_warp, a_warp);
    }
}

// round 11
// speedup vs baseline: 1.3365x; 1.0796x over previous
#include <cuda_runtime.h>
#include <cuda_fp16.h>
#include <math.h>
#include <stdint.h>
#include <stddef.h>

// ---------------- problem constants ----------------
#define N_B   2
#define C_IN  1088
#define C_MID 136
#define HW    4096

typedef unsigned long long ull;

// ---------------- device scratch ----------------
__device__ __align__(16) float g_fa[N_B * C_MID * HW];
__device__ __align__(16) float g_fb[N_B * C_MID * HW];
// fp16 raw, slot z: 0,1 = b_raw batches; 2,3 = a_raw batches
__device__ __align__(16) __half g_rawh[4ULL * C_IN * HW];
// fp16 transposed softmaxed corr: [4][n=HW][k=HW]
__device__ __align__(16) __half g_ch[4ULL * HW * HW];
// fp16 hi/lo-split features for energy: slots 0,1 = fb' (bat0,1), 2,3 = fa'
#define E_K 432
__device__ __align__(16) __half g_eh[4ULL * HW * E_K];

// ---------------- helpers ----------------
__device__ __forceinline__ ull pack2(float x, float y) {
    ull r; asm("mov.b64 %0, {%1, %2};" : "=l"(r) : "f"(x), "f"(y)); return r;
}
__device__ __forceinline__ float2 unpack2(ull v) {
    float2 f; asm("mov.b64 {%0, %1}, %2;" : "=f"(f.x), "=f"(f.y) : "l"(v)); return f;
}
__device__ __forceinline__ void ffma2u(ull& d, ull a, ull b) {
    asm("fma.rn.f32x2 %0, %1, %2, %0;" : "+l"(d) : "l"(a), "l"(b));
}
__device__ __forceinline__ void cp16(uint32_t dst, const void* src, uint32_t sz) {
    asm volatile("cp.async.ca.shared.global [%0], [%1], 16, %2;"
                 :: "r"(dst), "l"(src), "r"(sz));
}
__device__ __forceinline__ void cp_commit() { asm volatile("cp.async.commit_group;"); }
__device__ __forceinline__ void cp_wait0()  { asm volatile("cp.async.wait_group 0;" ::: "memory"); }
__device__ __forceinline__ void cp_wait1()  { asm volatile("cp.async.wait_group 1;" ::: "memory"); }

__device__ __forceinline__ float blk_sum(float v, float* red) {
    const int tid = threadIdx.x;
    #pragma unroll
    for (int o = 16; o > 0; o >>= 1) v += __shfl_down_sync(0xffffffffu, v, o);
    if ((tid & 31) == 0) red[tid >> 5] = v;
    __syncthreads();
    if (tid < 32) {
        v = (tid < 8) ? red[tid] : 0.f;
        #pragma unroll
        for (int o = 4; o > 0; o >>= 1) v += __shfl_down_sync(0xffffffffu, v, o);
        if (tid == 0) red[0] = v;
    }
    __syncthreads();
    v = red[0];
    __syncthreads();
    return v;
}

__device__ __forceinline__ float blk_max(float v, float* red) {
    const int tid = threadIdx.x;
    #pragma unroll
    for (int o = 16; o > 0; o >>= 1) v = fmaxf(v, __shfl_down_sync(0xffffffffu, v, o));
    if ((tid & 31) == 0) red[tid >> 5] = v;
    __syncthreads();
    if (tid < 32) {
        v = (tid < 8) ? red[tid] : -3.4e38f;
        #pragma unroll
        for (int o = 4; o > 0; o >>= 1) v = fmaxf(v, __shfl_down_sync(0xffffffffu, v, o));
        if (tid == 0) red[0] = v;
    }
    __syncthreads();
    v = red[0];
    __syncthreads();
    return v;
}

// ---------------- mma.sync fp16 primitive (f32 accumulate) ----------------
__device__ __forceinline__ void mma_f16(float4& c, const uint32_t a[4], const uint32_t b[2]) {
    asm volatile(
        "mma.sync.aligned.m16n8k16.row.col.f32.f16.f16.f32 "
        "{%0,%1,%2,%3},{%4,%5,%6,%7},{%8,%9},{%0,%1,%2,%3};"
        : "+f"(c.x), "+f"(c.y), "+f"(c.z), "+f"(c.w)
        : "r"(a[0]), "r"(a[1]), "r"(a[2]), "r"(a[3]), "r"(b[0]), "r"(b[1]));
}

// ---------------- warp-stage GEMM: fp16 mma, CTA 128x256, 3-stage cp.async ----------------
#define HA_PITCH 40
#define HB_PITCH 40
#define HA_BYTES (128 * HA_PITCH * 2)       // 10240
#define HB_BYTES (256 * HB_PITCH * 2)       // 20480
#define HST_BYTES (HA_BYTES + HB_BYTES)     // 30720
#define HN_STAGE 3
#define WH_SMEM (HN_STAGE * HST_BYTES)      // 92160

__global__ __launch_bounds__(256)
void wgemm_f16_kernel(const __half* __restrict__ Ah, const __half* __restrict__ Bh,
                      float* __restrict__ b_warp, float* __restrict__ a_warp)
{
    extern __shared__ char smc[];
    const uint32_t smem_base = (uint32_t)__cvta_generic_to_shared(smc);

    const int z = blockIdx.z;
    const __half* A = Ah + (size_t)z * C_IN * HW;
    const __half* B = Bh + (size_t)z * HW * HW;
    float* C = (z < 2) ? (b_warp + (size_t)z * C_IN * HW)
                       : (a_warp + (size_t)(z - 2) * C_IN * HW);

    const int m0 = blockIdx.y * 128;
    const int n0 = blockIdx.x * 256;
    const int tid = threadIdx.x;
    const int wid = tid >> 5;
    const int lane = tid & 31;
    const int wr = wid >> 2;
    const int wc = wid & 3;
    const int g = lane >> 2;
    const int tig = lane & 3;

    auto load_chunk = [&](int kc, int st) {
        const uint32_t sb = smem_base + (uint32_t)(st * HST_BYTES);
        const int k0 = kc * 32;
        #pragma unroll
        for (int p = 0; p < 2; p++) {
            const int u = p * 256 + tid;
            const int row = u >> 2, q = u & 3;
            const int gr = m0 + row;
            const uint32_t dst = sb + (uint32_t)(row * HA_PITCH * 2 + q * 16);
            const __half* src = A + (size_t)((gr < C_IN) ? gr : 0) * HW + k0 + q * 8;
            cp16(dst, src, (gr < C_IN) ? 16u : 0u);
        }
        #pragma unroll
        for (int p = 0; p < 4; p++) {
            const int u = p * 256 + tid;
            const int row = u >> 2, q = u & 3;
            const uint32_t dst = sb + HA_BYTES + (uint32_t)(row * HB_PITCH * 2 + q * 16);
            const __half* src = B + (size_t)(n0 + row) * HW + k0 + q * 8;
            cp16(dst, src, 16u);
        }
        cp_commit();
    };

    float4 acc[4][8];
    #pragma unroll
    for (int i = 0; i < 4; i++)
        #pragma unroll
        for (int j = 0; j < 8; j++) acc[i][j] = make_float4(0.f, 0.f, 0.f, 0.f);

    const int NC = HW / 32;
    load_chunk(0, 0);
    load_chunk(1, 1);

    int st = 0;
    for (int j = 0; j < NC; j++) {
        if (j + 2 < NC) cp_wait1(); else cp_wait0();
        __syncthreads();
        if (j + 2 < NC) {
            int st2 = st + 2; if (st2 >= HN_STAGE) st2 -= HN_STAGE;
            load_chunk(j + 2, st2);
        }

        const __half* As = (const __half*)(smc + st * HST_BYTES);
        const __half* Bs = (const __half*)(smc + st * HST_BYTES + HA_BYTES);
        #pragma unroll
        for (int ks = 0; ks < 2; ks++) {
            uint32_t a[4][4], b[8][2];
            #pragma unroll
            for (int mt = 0; mt < 4; mt++) {
                const __half* ap = As + (wr * 64 + mt * 16 + g) * HA_PITCH + ks * 16 + 2 * tig;
                a[mt][0] = *reinterpret_cast<const uint32_t*>(ap);
                a[mt][1] = *reinterpret_cast<const uint32_t*>(ap + 8 * HA_PITCH);
                a[mt][2] = *reinterpret_cast<const uint32_t*>(ap + 8);
                a[mt][3] = *reinterpret_cast<const uint32_t*>(ap + 8 * HA_PITCH + 8);
            }
            #pragma unroll
            for (int nt = 0; nt < 8; nt++) {
                const __half* bp = Bs + (wc * 64 + nt * 8 + g) * HB_PITCH + ks * 16 + 2 * tig;
                b[nt][0] = *reinterpret_cast<const uint32_t*>(bp);
                b[nt][1] = *reinterpret_cast<const uint32_t*>(bp + 8);
            }
            #pragma unroll
            for (int mt = 0; mt < 4; mt++)
                #pragma unroll
                for (int nt = 0; nt < 8; nt++)
                    mma_f16(acc[mt][nt], a[mt], b[nt]);
        }
        if (++st >= HN_STAGE) st -= HN_STAGE;
    }

    #pragma unroll
    for (int mt = 0; mt < 4; mt++) {
        const int r0 = m0 + wr * 64 + mt * 16 + g;
        const int r1 = r0 + 8;
        #pragma unroll
        for (int nt = 0; nt < 8; nt++) {
            const int col = n0 + wc * 64 + nt * 8 + tig * 2;
            const float4 cc = acc[mt][nt];
            if (r0 < C_IN)
                *reinterpret_cast<float2*>(C + (size_t)r0 * HW + col) = make_float2(cc.x, cc.y);
            if (r1 < C_IN)
                *reinterpret_cast<float2*>(C + (size_t)r1 * HW + col) = make_float2(cc.z, cc.w);
        }
    }
}

// ---------------- energy GEMM: fp16 hi/lo split, K=432, dual-orientation epilogue ----------------
// E[k,l] = 100 * sum_j fb'[k][j] * fa'[l][j];  writes E to Eab and E^T to Eba.
#define E_CH 48
#define E_NC (E_K / E_CH)                 // 9
#define E_PITCH 56
#define E_A_BYTES (128 * E_PITCH * 2)     // 14336
#define E_ST_BYTES (2 * E_A_BYTES)        // 28672
#define E_SMEM (3 * E_ST_BYTES)           // 86016 (also covers 128*132*4=67584 epilogue)
#define EP_PITCH 132                      // divisible by 4: float4-aligned rows

__global__ __launch_bounds__(256)
void energy_f16_kernel(const __half* __restrict__ eh,
                       float* __restrict__ Eab, float* __restrict__ Eba)
{
    extern __shared__ char smc[];
    const uint32_t smem_base = (uint32_t)__cvta_generic_to_shared(smc);
    const int bat = blockIdx.z;
    const __half* A = eh + (size_t)bat * HW * E_K;          // fb' slot
    const __half* B = eh + (size_t)(2 + bat) * HW * E_K;    // fa' slot
    float* EA = Eab + (size_t)bat * HW * HW;
    float* EB = Eba + (size_t)bat * HW * HW;

    const int m0 = blockIdx.y * 128;      // k tile
    const int n0 = blockIdx.x * 128;      // l tile
    const int tid = threadIdx.x;
    const int wid = tid >> 5, lane = tid & 31;
    const int wr = wid >> 2, wc = wid & 3;
    const int g = lane >> 2, tig = lane & 3;

    auto load_chunk = [&](int kc, int st) {
        const uint32_t sb = smem_base + (uint32_t)(st * E_ST_BYTES);
        const int k0 = kc * E_CH;
        #pragma unroll
        for (int p = 0; p < 3; p++) {
            const int u = p * 256 + tid;
            const int row = u / 6, q = u % 6;
            cp16(sb + (uint32_t)(row * (E_PITCH * 2) + q * 16),
                 A + (size_t)(m0 + row) * E_K + k0 + q * 8, 16u);
        }
        #pragma unroll
        for (int p = 0; p < 3; p++) {
            const int u = p * 256 + tid;
            const int row = u / 6, q = u % 6;
            cp16(sb + E_A_BYTES + (uint32_t)(row * (E_PITCH * 2) + q * 16),
                 B + (size_t)(n0 + row) * E_K + k0 + q * 8, 16u);
        }
        cp_commit();
    };

    float4 acc[4][4];
    #pragma unroll
    for (int i = 0; i < 4; i++)
        #pragma unroll
        for (int j = 0; j < 4; j++) acc[i][j] = make_float4(0.f, 0.f, 0.f, 0.f);

    load_chunk(0, 0);
    load_chunk(1, 1);

    int st = 0;
    for (int j = 0; j < E_NC; j++) {
        if (j + 2 < E_NC) cp_wait1(); else cp_wait0();
        __syncthreads();
        if (j + 2 < E_NC) {
            int st2 = st + 2; if (st2 >= 3) st2 -= 3;
            load_chunk(j + 2, st2);
        }

        const __half* As = (const __half*)(smc + st * E_ST_BYTES);
        const __half* Bs = (const __half*)(smc + st * E_ST_BYTES + E_A_BYTES);
        #pragma unroll
        for (int ks = 0; ks < 3; ks++) {
            uint32_t a[4][4], b[4][2];
            #pragma unroll
            for (int mt = 0; mt < 4; mt++) {
                const __half* ap = As + (wr * 64 + mt * 16 + g) * E_PITCH + ks * 16 + 2 * tig;
                a[mt][0] = *reinterpret_cast<const uint32_t*>(ap);
                a[mt][1] = *reinterpret_cast<const uint32_t*>(ap + 8 * E_PITCH);
                a[mt][2] = *reinterpret_cast<const uint32_t*>(ap + 8);
                a[mt][3] = *reinterpret_cast<const uint32_t*>(ap + 8 * E_PITCH + 8);
            }
            #pragma unroll
            for (int nt = 0; nt < 4; nt++) {
                const __half* bp = Bs + (wc * 32 + nt * 8 + g) * E_PITCH + ks * 16 + 2 * tig;
                b[nt][0] = *reinterpret_cast<const uint32_t*>(bp);
                b[nt][1] = *reinterpret_cast<const uint32_t*>(bp + 8);
            }
            #pragma unroll
            for (int mt = 0; mt < 4; mt++)
                #pragma unroll
                for (int nt = 0; nt < 4; nt++)
                    mma_f16(acc[mt][nt], a[mt], b[nt]);
        }
        if (++st >= 3) st -= 3;
    }

    // scale by alpha=100
    #pragma unroll
    for (int mt = 0; mt < 4; mt++)
        #pragma unroll
        for (int nt = 0; nt < 4; nt++) {
            acc[mt][nt].x *= 100.f; acc[mt][nt].y *= 100.f;
            acc[mt][nt].z *= 100.f; acc[mt][nt].w *= 100.f;
        }

    float* ep = (float*)smc;
    __syncthreads();
    // pass 1: direct orientation
    #pragma unroll
    for (int mt = 0; mt < 4; mt++) {
        const int r0 = wr * 64 + mt * 16 + g, r1 = r0 + 8;
        #pragma unroll
        for (int nt = 0; nt < 4; nt++) {
            const int col = wc * 32 + nt * 8 + tig * 2;
            const float4 cc = acc[mt][nt];
            ep[r0 * EP_PITCH + col] = cc.x; ep[r0 * EP_PITCH + col + 1] = cc.y;
            ep[r1 * EP_PITCH + col] = cc.z; ep[r1 * EP_PITCH + col + 1] = cc.w;
        }
    }
    __syncthreads();
    #pragma unroll
    for (int it = 0; it < 16; it++) {
        const int e = it * 256 + tid;
        const int rr = e >> 5, c4 = (e & 31) * 4;
        *reinterpret_cast<float4*>(EA + (size_t)(m0 + rr) * HW + n0 + c4) =
            *reinterpret_cast<const float4*>(ep + rr * EP_PITCH + c4);
    }
    __syncthreads();
    // pass 2: transposed orientation
    #pragma unroll
    for (int mt = 0; mt < 4; mt++) {
        const int r0 = wr * 64 + mt * 16 + g, r1 = r0 + 8;
        #pragma unroll
        for (int nt = 0; nt < 4; nt++) {
            const int col = wc * 32 + nt * 8 + tig * 2;
            const float4 cc = acc[mt][nt];
            ep[col * EP_PITCH + r0] = cc.x; ep[(col + 1) * EP_PITCH + r0] = cc.y;
            ep[col * EP_PITCH + r1] = cc.z; ep[(col + 1) * EP_PITCH + r1] = cc.w;
        }
    }
    __syncthreads();
    #pragma unroll
    for (int it = 0; it < 16; it++) {
        const int e = it * 256 + tid;
        const int rr = e >> 5, c4 = (e & 31) * 4;
        *reinterpret_cast<float4*>(EB + (size_t)(n0 + rr) * HW + m0 + c4) =
            *reinterpret_cast<const float4*>(ep + rr * EP_PITCH + c4);
    }
}

// ---------------- feature hi/lo split + transpose: f [c][l] -> f' [l][432] ----------------
// z 0,1: fb batches -> layout [hi,hi,lo]; z 2,3: fa batches -> layout [hi,lo,hi]
__global__ __launch_bounds__(256)
void fcvt_kernel(const float* __restrict__ Fa, const float* __restrict__ Fb,
                 __half* __restrict__ outp)
{
    __shared__ float t[32][33];
    const int z = blockIdx.z;
    const int bat = z & 1;
    const bool is_fb = (z < 2);
    const float* src = (is_fb ? Fb : Fa) + (size_t)bat * C_MID * HW;
    __half* dst = outp + (size_t)z * HW * E_K;

    const int l0 = blockIdx.x * 32;
    const int c0 = blockIdx.y * 32;
    const int tx = threadIdx.x & 31, ty = threadIdx.x >> 5;

    #pragma unroll
    for (int i = 0; i < 32; i += 8) {
        const int cg = c0 + ty + i;
        t[ty + i][tx] = (cg < C_MID) ? src[(size_t)cg * HW + l0 + tx] : 0.f;
    }
    __syncthreads();

    const int cl = (threadIdx.x & 15) * 2;       // local c (even)
    const int lt = threadIdx.x >> 4;             // 0..15
    #pragma unroll
    for (int i = 0; i < 2; i++) {
        const int ll = lt + i * 16;
        const int cg = c0 + cl;
        if (cg >= 144) continue;
        const float v0 = t[cl][ll], v1 = t[cl + 1][ll];
        const __half h0 = __float2half_rn(v0), h1 = __float2half_rn(v1);
        const __half l0h = __float2half_rn(v0 - __half2float(h0));
        const __half l1h = __float2half_rn(v1 - __half2float(h1));
        const __half2 hh = __halves2half2(h0, h1);
        const __half2 llh = __halves2half2(l0h, l1h);
        __half* base = dst + (size_t)(l0 + ll) * E_K;
        if (is_fb) {
            *reinterpret_cast<__half2*>(base + cg) = hh;
            *reinterpret_cast<__half2*>(base + 144 + cg) = hh;
            *reinterpret_cast<__half2*>(base + 288 + cg) = llh;
        } else {
            *reinterpret_cast<__half2*>(base + cg) = hh;
            *reinterpret_cast<__half2*>(base + 144 + cg) = llh;
            *reinterpret_cast<__half2*>(base + 288 + cg) = hh;
        }
    }
}

// ---------------- fp32 SIMT GEMM with packed f32x2 FMA (conv main) ----------------
#define BM 128
#define BN 128
#define BK 8
#define TM 8
#define TN 8

template<bool TRANS_A, int EPI>
__global__ __launch_bounds__(256, 2)
void sgemm2_kernel(const float* __restrict__ A0, const float* __restrict__ A1,
                   const float* __restrict__ B0, const float* __restrict__ B1,
                   const float* __restrict__ bs0, const float* __restrict__ bs1,
                   float* __restrict__ C0, float* __restrict__ C1,
                   int M, int N, int K, long sA, long sB, long sC, float alpha)
{
    __shared__ float As[BK][BM];
    __shared__ float Bs[BK][BN];

    const int sel = blockIdx.z >> 1, bat = blockIdx.z & 1;
    const float* A = (sel ? A1 : A0) + (long)bat * sA;
    const float* B = (sel ? B1 : B0) + (long)bat * sB;
    const float* bias = sel ? bs1 : bs0;
    float* C = (sel ? C1 : C0) + (long)bat * sC;

    const int m0 = blockIdx.y * BM;
    const int n0 = blockIdx.x * BN;
    const int tid = threadIdx.x;
    const int tx = tid & 15;
    const int ty = tid >> 4;
    const int idx = tid * 4;

    ull acc[4][TN];
    #pragma unroll
    for (int i = 0; i < 4; i++)
        #pragma unroll
        for (int j = 0; j < TN; j++) acc[i][j] = 0ULL;

    for (int k0 = 0; k0 < K; k0 += BK) {
        if (TRANS_A) {
            const int kk = idx / BM;
            const int mm = idx % BM;
            const float4 v = *reinterpret_cast<const float4*>(
                A + (long)(k0 + kk) * M + (m0 + mm));
            *reinterpret_cast<float4*>(&As[kk][mm]) = v;
        } else {
            const int mm = idx / BK;
            const int kk = idx % BK;
            const int row = m0 + mm;
            float4 v = make_float4(0.f, 0.f, 0.f, 0.f);
            if (row < M)
                v = *reinterpret_cast<const float4*>(A + (long)row * K + (k0 + kk));
            As[kk + 0][mm] = v.x;
            As[kk + 1][mm] = v.y;
            As[kk + 2][mm] = v.z;
            As[kk + 3][mm] = v.w;
        }
        {
            const int kk = idx / BN;
            const int nn = idx % BN;
            const float4 v = *reinterpret_cast<const float4*>(
                B + (long)(k0 + kk) * N + (n0 + nn));
            *reinterpret_cast<float4*>(&Bs[kk][nn]) = v;
        }
        __syncthreads();

        #pragma unroll
        for (int kk = 0; kk < BK; kk++) {
            const ulonglong2 a01 = *reinterpret_cast<const ulonglong2*>(&As[kk][ty * TM]);
            const ulonglong2 a23 = *reinterpret_cast<const ulonglong2*>(&As[kk][ty * TM + 4]);
            const float4 rb0 = *reinterpret_cast<const float4*>(&Bs[kk][tx * TN]);
            const float4 rb1 = *reinterpret_cast<const float4*>(&Bs[kk][tx * TN + 4]);
            ull ap[4] = { a01.x, a01.y, a23.x, a23.y };
            float rb[8] = { rb0.x, rb0.y, rb0.z, rb0.w, rb1.x, rb1.y, rb1.z, rb1.w };
            #pragma unroll
            for (int j = 0; j < TN; j++) {
                const ull bb = pack2(rb[j], rb[j]);
                #pragma unroll
                for (int i = 0; i < 4; i++)
                    ffma2u(acc[i][j], ap[i], bb);
            }
        }
        __syncthreads();
    }

    #pragma unroll
    for (int i2 = 0; i2 < 4; i2++) {
        float2 lo[TN];
        #pragma unroll
        for (int j = 0; j < TN; j++) lo[j] = unpack2(acc[i2][j]);
        #pragma unroll
        for (int half = 0; half < 2; half++) {
            const int row = m0 + ty * TM + 2 * i2 + half;
            if (row >= M) continue;
            const float bv = (EPI == 1) ? bias[row] : 0.f;
            float r[TN];
            #pragma unroll
            for (int j = 0; j < TN; j++) r[j] = half ? lo[j].y : lo[j].x;
            #pragma unroll
            for (int j = 0; j < TN; j += 4) {
                float4 v = make_float4(r[j], r[j+1], r[j+2], r[j+3]);
                if (EPI == 1) { v.x += bv; v.y += bv; v.z += bv; v.w += bv; }
                if (EPI == 2) { v.x *= alpha; v.y *= alpha; v.z *= alpha; v.w *= alpha; }
                *reinterpret_cast<float4*>(C + (long)row * N + n0 + tx * TN + j) = v;
            }
        }
    }
}

// ---------------- conv tail: rows 128..135 ----------------
__global__ __launch_bounds__(256)
void conv_tail_kernel(const float* __restrict__ X0, const float* __restrict__ X1,
                      const float* __restrict__ W0, const float* __restrict__ W1,
                      const float* __restrict__ b0, const float* __restrict__ b1,
                      float* __restrict__ F0, float* __restrict__ F1)
{
    __shared__ float ws[8 * C_IN];
    const int sel = blockIdx.z >> 1, bat = blockIdx.z & 1;
    const float* X = (sel ? X1 : X0) + (long)bat * C_IN * HW;
    const float* W = (sel ? W1 : W0) + 128 * C_IN;
    const float* bias = (sel ? b1 : b0) + 128;
    float* F = (sel ? F1 : F0) + (long)bat * C_MID * HW + 128L * HW;

    const int tid = threadIdx.x;
    for (int i = tid; i < 8 * C_IN; i += 256) ws[i] = W[i];
    __syncthreads();

    const int l = blockIdx.x * 256 + tid;
    float acc[8];
    #pragma unroll
    for (int r2 = 0; r2 < 8; r2++) acc[r2] = 0.f;

    #pragma unroll 8
    for (int cin = 0; cin < C_IN; cin++) {
        const float x = X[(long)cin * HW + l];
        #pragma unroll
        for (int r2 = 0; r2 < 8; r2++)
            acc[r2] = fmaf(ws[r2 * C_IN + cin], x, acc[r2]);
    }
    #pragma unroll
    for (int r2 = 0; r2 < 8; r2++)
        F[(long)r2 * HW + l] = acc[r2] + bias[r2];
}

// ---------------- corr fp32 [k][n] -> fp16 transposed [n][k] ----------------
__global__ __launch_bounds__(256)
void corrcvt_kernel(const float* __restrict__ in, __half* __restrict__ outT)
{
    __shared__ float t[32][33];
    const size_t off = (size_t)blockIdx.z * HW * HW;
    const int k0 = blockIdx.y * 32, n0 = blockIdx.x * 32;
    const int tx = threadIdx.x & 31, ty = threadIdx.x >> 5;
    #pragma unroll
    for (int i = 0; i < 32; i += 8)
        t[ty + i][tx] = in[off + (size_t)(k0 + ty + i) * HW + n0 + tx];
    __syncthreads();
    #pragma unroll
    for (int i = 0; i < 2; i++) {
        const int u = i * 256 + threadIdx.x;
        const int r = u >> 4, cp = (u & 15) * 2;
        const __half2 h = __floats2half2_rn(t[cp][r], t[cp + 1][r]);
        *reinterpret_cast<__half2*>(&outT[off + (size_t)(n0 + r) * HW + k0 + cp]) = h;
    }
}

// ---------------- raw fp32 -> fp16 slots (b0,b1,a0,a1) ----------------
__global__ __launch_bounds__(256)
void rawcvt_kernel(const float* __restrict__ a, const float* __restrict__ b,
                   __half* __restrict__ dst)
{
    const int z = blockIdx.z;
    const long slice = (long)C_IN * HW;
    const float* src = (z < 2) ? (b + z * slice) : (a + (z - 2) * slice);
    __half* d = dst + z * slice;
    const long i = ((long)blockIdx.x * 256 + threadIdx.x) * 8;
    const float4 v0 = *reinterpret_cast<const float4*>(src + i);
    const float4 v1 = *reinterpret_cast<const float4*>(src + i + 4);
    __half2 h[4];
    h[0] = __floats2half2_rn(v0.x, v0.y);
    h[1] = __floats2half2_rn(v0.z, v0.w);
    h[2] = __floats2half2_rn(v1.x, v1.y);
    h[3] = __floats2half2_rn(v1.z, v1.w);
    *reinterpret_cast<uint4*>(d + i) = *reinterpret_cast<const uint4*>(h);
}

// ---------------- instance norm + LeakyReLU + re-center ----------------
__global__ __launch_bounds__(256)
void instnorm_kernel(float* __restrict__ Fa, float* __restrict__ Fb)
{
    __shared__ float sh[HW];
    __shared__ float red[8];
    float* F = blockIdx.z ? Fb : Fa;
    float* row = F + ((long)blockIdx.y * C_MID + blockIdx.x) * HW;
    const int tid = threadIdx.x;

    float s = 0.f, s2 = 0.f;
    for (int i = tid; i < HW; i += 256) {
        const float v = row[i];
        sh[i] = v; s += v; s2 += v * v;
    }
    s  = blk_sum(s,  red);
    s2 = blk_sum(s2, red);
    const float mean = s * (1.f / HW);
    const float var  = s2 * (1.f / HW) - mean * mean;
    const float inv  = rsqrtf(var + 1e-5f);

    float s3 = 0.f;
    for (int i = tid; i < HW; i += 256) {
        float v = (sh[i] - mean) * inv;
        v = (v >= 0.f) ? v : 0.2f * v;
        sh[i] = v;
        s3 += v;
    }
    s3 = blk_sum(s3, red);
    const float mean2 = s3 * (1.f / HW);
    for (int i = tid; i < HW; i += 256)
        row[i] = sh[i] - mean2;
}

// ---------------- per-column L2 normalize ----------------
__global__ __launch_bounds__(256)
void l2norm_kernel(float* __restrict__ Fa, float* __restrict__ Fb)
{
    float* F = blockIdx.z ? Fb : Fa;
    const int l = blockIdx.x * 256 + threadIdx.x;
    float* base = F + (long)blockIdx.y * C_MID * HW + l;
    float s = 0.f;
    #pragma unroll 8
    for (int cc = 0; cc < C_MID; cc++) {
        const float v = base[(long)cc * HW];
        s += v * v;
    }
    const float inv = rsqrtf(s);
    #pragma unroll 8
    for (int cc = 0; cc < C_MID; cc++)
        base[(long)cc * HW] *= inv;
}

// ---------------- in-place row softmax ----------------
__global__ __launch_bounds__(256)
void softmax_kernel(float* __restrict__ E)
{
    __shared__ float sh[HW];
    __shared__ float red[8];
    float* row = E + ((long)blockIdx.y * HW + blockIdx.x) * HW;
    const int tid = threadIdx.x;

    float mx = -3.4e38f;
    for (int i = tid; i < HW; i += 256) {
        const float v = row[i];
        sh[i] = v;
        mx = fmaxf(mx, v);
    }
    mx = blk_max(mx, red);

    float s = 0.f;
    for (int i = tid; i < HW; i += 256) {
        const float e = __expf(sh[i] - mx);
        sh[i] = e;
        s += e;
    }
    s = blk_sum(s, red);
    const float inv = 1.f / s;
    for (int i = tid; i < HW; i += 256)
        row[i] = sh[i] * inv;
}

// ---------------- launch ----------------
extern "C" void kernel_launch(void* const* d_in, const int* in_sizes, int n_in,
                              void* d_out, int out_size)
{
    const float* fa    = (const float*)d_in[0];
    const float* fb    = (const float*)d_in[1];
    const float* a_raw = (const float*)d_in[2];
    const float* b_raw = (const float*)d_in[3];
    const float* Wa    = (const float*)d_in[4];
    const float* ba    = (const float*)d_in[5];
    const float* Wb    = (const float*)d_in[6];
    const float* bb    = (const float*)d_in[7];
    float* out = (float*)d_out;

    float *pfa, *pfb;
    __half *prawh, *pch, *peh;
    cudaGetSymbolAddress((void**)&pfa, g_fa);
    cudaGetSymbolAddress((void**)&pfb, g_fb);
    cudaGetSymbolAddress((void**)&prawh, g_rawh);
    cudaGetSymbolAddress((void**)&pch, g_ch);
    cudaGetSymbolAddress((void**)&peh, g_eh);

    cudaFuncSetAttribute(wgemm_f16_kernel,
                         cudaFuncAttributeMaxDynamicSharedMemorySize, WH_SMEM);
    cudaFuncSetAttribute(energy_f16_kernel,
                         cudaFuncAttributeMaxDynamicSharedMemorySize, E_SMEM);

    const long CORR = (long)HW * HW;
    float* corr_ab = out;
    float* corr_ba = out + (long)N_B * CORR;
    float* a_warp  = out + 2L * N_B * CORR;
    float* b_warp  = a_warp + (long)N_B * C_IN * HW;

    const dim3 blk(256);
    const long sMID = (long)C_MID * HW;
    const long sIN  = (long)C_IN * HW;

    // 1) 1x1 conv main tile: rows 0..127
    {
        dim3 g(HW / BN, 1, 4);
        sgemm2_kernel<false, 1><<<g, blk>>>(Wa, Wb, fa, fb, ba, bb, pfa, pfb,
                                            C_MID, HW, C_IN, 0L, sIN, sMID, 0.f);
    }
    // 1b) conv tail: rows 128..135
    {
        dim3 g(HW / 256, 1, 4);
        conv_tail_kernel<<<g, blk>>>(fa, fb, Wa, Wb, ba, bb, pfa, pfb);
    }
    // 2) InstanceNorm + LeakyReLU + re-center
    {
        dim3 g(C_MID, N_B, 2);
        instnorm_kernel<<<g, blk>>>(pfa, pfb);
    }
    // 3) per-column L2 normalize
    {
        dim3 g(HW / 256, N_B, 2);
        l2norm_kernel<<<g, blk>>>(pfa, pfb);
    }
    // 4) feature hi/lo split + transpose for tensor-core energy
    {
        dim3 g(HW / 32, 5, 4);
        fcvt_kernel<<<g, blk>>>(pfa, pfb, peh);
    }
    // 4b) energy GEMM on fp16 mma (K=432 split), writes E and E^T (x100)
    {
        dim3 g(HW / 128, HW / 128, 2);
        energy_f16_kernel<<<g, blk, E_SMEM>>>(peh, corr_ab, corr_ba);
    }
    // 5) softmax over all corr rows
    {
        dim3 g(HW, 2 * N_B);
        softmax_kernel<<<g, blk>>>(out);
    }
    // 6) convert softmaxed corr -> fp16 transposed [n][k]
    {
        dim3 g(HW / 32, HW / 32, 4);
        corrcvt_kernel<<<g, blk>>>(out, pch);
    }
    // 6b) convert raw -> fp16 slots
    {
        dim3 g((unsigned)(sIN / 8 / 256), 1, 4);
        rawcvt_kernel<<<g, blk>>>(a_raw, b_raw, prawh);
    }
    // 7) warp GEMMs on fp16 mma (CTA 128x256, 3-stage pipeline)
    {
        dim3 g(HW / 256, (C_IN + 127) / 128, 4);
        wgemm_f16_kernel<<<g, blk, WH_SMEM>>>(prawh, pch, b_warp, a_warp);
    }
}

// round 12
// speedup vs baseline: 1.4363x; 1.0747x over previous
#include <cuda_runtime.h>
#include <cuda_fp16.h>
#include <math.h>
#include <stdint.h>
#include <stddef.h>

// ---------------- problem constants ----------------
#define N_B   2
#define C_IN  1088
#define C_MID 136
#define HW    4096

typedef unsigned long long ull;

// ---------------- device scratch ----------------
__device__ __align__(16) float g_fa[N_B * C_MID * HW];
__device__ __align__(16) float g_fb[N_B * C_MID * HW];
// fp16 raw, slot z: 0,1 = b_raw batches; 2,3 = a_raw batches
__device__ __align__(16) __half g_rawh[4ULL * C_IN * HW];
// fp16 softmaxed corr, natural [k][n] layout, slots = [ab0, ab1, ba0, ba1]
__device__ __align__(16) __half g_ch[4ULL * HW * HW];
// fp16 hi/lo-split features for energy: slots 0,1 = fb' (bat0,1), 2,3 = fa'
#define E_K 432
__device__ __align__(16) __half g_eh[4ULL * HW * E_K];

// ---------------- helpers ----------------
__device__ __forceinline__ ull pack2(float x, float y) {
    ull r; asm("mov.b64 %0, {%1, %2};" : "=l"(r) : "f"(x), "f"(y)); return r;
}
__device__ __forceinline__ float2 unpack2(ull v) {
    float2 f; asm("mov.b64 {%0, %1}, %2;" : "=f"(f.x), "=f"(f.y) : "l"(v)); return f;
}
__device__ __forceinline__ void ffma2u(ull& d, ull a, ull b) {
    asm("fma.rn.f32x2 %0, %1, %2, %0;" : "+l"(d) : "l"(a), "l"(b));
}
__device__ __forceinline__ void cp16(uint32_t dst, const void* src, uint32_t sz) {
    asm volatile("cp.async.ca.shared.global [%0], [%1], 16, %2;"
                 :: "r"(dst), "l"(src), "r"(sz));
}
__device__ __forceinline__ void cp_commit() { asm volatile("cp.async.commit_group;"); }
__device__ __forceinline__ void cp_wait0()  { asm volatile("cp.async.wait_group 0;" ::: "memory"); }
__device__ __forceinline__ void cp_wait1()  { asm volatile("cp.async.wait_group 1;" ::: "memory"); }

__device__ __forceinline__ float blk_sum(float v, float* red) {
    const int tid = threadIdx.x;
    #pragma unroll
    for (int o = 16; o > 0; o >>= 1) v += __shfl_down_sync(0xffffffffu, v, o);
    if ((tid & 31) == 0) red[tid >> 5] = v;
    __syncthreads();
    if (tid < 32) {
        v = (tid < 8) ? red[tid] : 0.f;
        #pragma unroll
        for (int o = 4; o > 0; o >>= 1) v += __shfl_down_sync(0xffffffffu, v, o);
        if (tid == 0) red[0] = v;
    }
    __syncthreads();
    v = red[0];
    __syncthreads();
    return v;
}

__device__ __forceinline__ float blk_max(float v, float* red) {
    const int tid = threadIdx.x;
    #pragma unroll
    for (int o = 16; o > 0; o >>= 1) v = fmaxf(v, __shfl_down_sync(0xffffffffu, v, o));
    if ((tid & 31) == 0) red[tid >> 5] = v;
    __syncthreads();
    if (tid < 32) {
        v = (tid < 8) ? red[tid] : -3.4e38f;
        #pragma unroll
        for (int o = 4; o > 0; o >>= 1) v = fmaxf(v, __shfl_down_sync(0xffffffffu, v, o));
        if (tid == 0) red[0] = v;
    }
    __syncthreads();
    v = red[0];
    __syncthreads();
    return v;
}

// ---------------- mma.sync fp16 primitive (f32 accumulate) ----------------
__device__ __forceinline__ void mma_f16(float4& c, const uint32_t a[4], const uint32_t b[2]) {
    asm volatile(
        "mma.sync.aligned.m16n8k16.row.col.f32.f16.f16.f32 "
        "{%0,%1,%2,%3},{%4,%5,%6,%7},{%8,%9},{%0,%1,%2,%3};"
        : "+f"(c.x), "+f"(c.y), "+f"(c.z), "+f"(c.w)
        : "r"(a[0]), "r"(a[1]), "r"(a[2]), "r"(a[3]), "r"(b[0]), "r"(b[1]));
}

__device__ __forceinline__ void ldsm4t(uint32_t& r0, uint32_t& r1, uint32_t& r2, uint32_t& r3,
                                       uint32_t addr) {
    asm volatile("ldmatrix.sync.aligned.m8n8.x4.trans.shared.b16 {%0,%1,%2,%3}, [%4];"
                 : "=r"(r0), "=r"(r1), "=r"(r2), "=r"(r3) : "r"(addr));
}

// ---------------- warp-stage GEMM: fp16 mma, CTA 128x256, 3-stage cp.async ----------------
// C[z][1088,4096] = rawh[z] @ corr[z] ; A fp16 [m][k], B fp16 [k][n] (natural corr layout).
// B fragments come from ldmatrix.x4.trans on k-major smem tiles.
#define HA_PITCH 40
#define HB_PITCH 264                        // halfs per B smem row (256 + 8 pad)
#define HA_BYTES (128 * HA_PITCH * 2)       // 10240
#define HB_BYTES (32 * HB_PITCH * 2)        // 16896
#define HST_BYTES (HA_BYTES + HB_BYTES)     // 27136
#define HN_STAGE 3
#define WH_SMEM (HN_STAGE * HST_BYTES)      // 81408

__global__ __launch_bounds__(256)
void wgemm_f16_kernel(const __half* __restrict__ Ah, const __half* __restrict__ Bh,
                      float* __restrict__ b_warp, float* __restrict__ a_warp)
{
    extern __shared__ char smc[];
    const uint32_t smem_base = (uint32_t)__cvta_generic_to_shared(smc);

    const int z = blockIdx.z;
    const __half* A = Ah + (size_t)z * C_IN * HW;
    const __half* B = Bh + (size_t)z * HW * HW;
    float* C = (z < 2) ? (b_warp + (size_t)z * C_IN * HW)
                       : (a_warp + (size_t)(z - 2) * C_IN * HW);

    const int m0 = blockIdx.y * 128;
    const int n0 = blockIdx.x * 256;
    const int tid = threadIdx.x;
    const int wid = tid >> 5;
    const int lane = tid & 31;
    const int wr = wid >> 2;              // 0..1 -> 64 M rows
    const int wc = wid & 3;               // 0..3 -> 64 N cols
    const int g = lane >> 2;              // 0..7
    const int tig = lane & 3;             // 0..3

    auto load_chunk = [&](int kc, int st) {
        const uint32_t sb = smem_base + (uint32_t)(st * HST_BYTES);
        const int k0 = kc * 32;
        #pragma unroll
        for (int p = 0; p < 2; p++) {     // A: 128 m-rows x 32 k
            const int u = p * 256 + tid;
            const int row = u >> 2, q = u & 3;
            const int gr = m0 + row;
            const uint32_t dst = sb + (uint32_t)(row * HA_PITCH * 2 + q * 16);
            const __half* src = A + (size_t)((gr < C_IN) ? gr : 0) * HW + k0 + q * 8;
            cp16(dst, src, (gr < C_IN) ? 16u : 0u);
        }
        #pragma unroll
        for (int p = 0; p < 4; p++) {     // B: 32 k-rows x 256 n
            const int u = p * 256 + tid;
            const int row = u >> 5, q = u & 31;
            const uint32_t dst = sb + HA_BYTES + (uint32_t)(row * HB_PITCH * 2 + q * 16);
            const __half* src = B + (size_t)(k0 + row) * HW + n0 + q * 8;
            cp16(dst, src, 16u);
        }
        cp_commit();
    };

    float4 acc[4][8];
    #pragma unroll
    for (int i = 0; i < 4; i++)
        #pragma unroll
        for (int j = 0; j < 8; j++) acc[i][j] = make_float4(0.f, 0.f, 0.f, 0.f);

    const int NC = HW / 32;
    load_chunk(0, 0);
    load_chunk(1, 1);

    int st = 0;
    for (int j = 0; j < NC; j++) {
        if (j + 2 < NC) cp_wait1(); else cp_wait0();
        __syncthreads();
        if (j + 2 < NC) {
            int st2 = st + 2; if (st2 >= HN_STAGE) st2 -= HN_STAGE;
            load_chunk(j + 2, st2);
        }

        const __half* As = (const __half*)(smc + st * HST_BYTES);
        const uint32_t Bs = smem_base + (uint32_t)(st * HST_BYTES + HA_BYTES);

        // B fragments: one ldmatrix.x4.trans per nt covers all 32 k (both ks halves).
        // lane i -> k-row i, n-cols [wc*64 + nt*8, +8)
        uint32_t b[8][4];
        #pragma unroll
        for (int nt = 0; nt < 8; nt++) {
            const uint32_t addr = Bs + (uint32_t)(lane * (HB_PITCH * 2) +
                                                  (wc * 64 + nt * 8) * 2);
            ldsm4t(b[nt][0], b[nt][1], b[nt][2], b[nt][3], addr);
        }
        #pragma unroll
        for (int ks = 0; ks < 2; ks++) {
            uint32_t a[4][4];
            #pragma unroll
            for (int mt = 0; mt < 4; mt++) {
                const __half* ap = As + (wr * 64 + mt * 16 + g) * HA_PITCH + ks * 16 + 2 * tig;
                a[mt][0] = *reinterpret_cast<const uint32_t*>(ap);
                a[mt][1] = *reinterpret_cast<const uint32_t*>(ap + 8 * HA_PITCH);
                a[mt][2] = *reinterpret_cast<const uint32_t*>(ap + 8);
                a[mt][3] = *reinterpret_cast<const uint32_t*>(ap + 8 * HA_PITCH + 8);
            }
            #pragma unroll
            for (int mt = 0; mt < 4; mt++)
                #pragma unroll
                for (int nt = 0; nt < 8; nt++)
                    mma_f16(acc[mt][nt], a[mt], &b[nt][ks * 2]);
        }
        if (++st >= HN_STAGE) st -= HN_STAGE;
    }

    #pragma unroll
    for (int mt = 0; mt < 4; mt++) {
        const int r0 = m0 + wr * 64 + mt * 16 + g;
        const int r1 = r0 + 8;
        #pragma unroll
        for (int nt = 0; nt < 8; nt++) {
            const int col = n0 + wc * 64 + nt * 8 + tig * 2;
            const float4 cc = acc[mt][nt];
            if (r0 < C_IN)
                *reinterpret_cast<float2*>(C + (size_t)r0 * HW + col) = make_float2(cc.x, cc.y);
            if (r1 < C_IN)
                *reinterpret_cast<float2*>(C + (size_t)r1 * HW + col) = make_float2(cc.z, cc.w);
        }
    }
}

// ---------------- energy GEMM: fp16 hi/lo split, K=432, dual-orientation epilogue ----------------
#define E_CH 48
#define E_NC (E_K / E_CH)                 // 9
#define E_PITCH 56
#define E_A_BYTES (128 * E_PITCH * 2)     // 14336
#define E_ST_BYTES (2 * E_A_BYTES)        // 28672
#define E_SMEM (3 * E_ST_BYTES)           // 86016 (covers 128*132*4=67584 epilogue)
#define EP_PITCH 132                      // divisible by 4: float4-aligned

__global__ __launch_bounds__(256)
void energy_f16_kernel(const __half* __restrict__ eh,
                       float* __restrict__ Eab, float* __restrict__ Eba)
{
    extern __shared__ char smc[];
    const uint32_t smem_base = (uint32_t)__cvta_generic_to_shared(smc);
    const int bat = blockIdx.z;
    const __half* A = eh + (size_t)bat * HW * E_K;          // fb'
    const __half* B = eh + (size_t)(2 + bat) * HW * E_K;    // fa'
    float* EA = Eab + (size_t)bat * HW * HW;
    float* EB = Eba + (size_t)bat * HW * HW;

    const int m0 = blockIdx.y * 128;
    const int n0 = blockIdx.x * 128;
    const int tid = threadIdx.x;
    const int wid = tid >> 5, lane = tid & 31;
    const int wr = wid >> 2, wc = wid & 3;
    const int g = lane >> 2, tig = lane & 3;

    auto load_chunk = [&](int kc, int st) {
        const uint32_t sb = smem_base + (uint32_t)(st * E_ST_BYTES);
        const int k0 = kc * E_CH;
        #pragma unroll
        for (int p = 0; p < 3; p++) {
            const int u = p * 256 + tid;
            const int row = u / 6, q = u % 6;
            cp16(sb + (uint32_t)(row * (E_PITCH * 2) + q * 16),
                 A + (size_t)(m0 + row) * E_K + k0 + q * 8, 16u);
        }
        #pragma unroll
        for (int p = 0; p < 3; p++) {
            const int u = p * 256 + tid;
            const int row = u / 6, q = u % 6;
            cp16(sb + E_A_BYTES + (uint32_t)(row * (E_PITCH * 2) + q * 16),
                 B + (size_t)(n0 + row) * E_K + k0 + q * 8, 16u);
        }
        cp_commit();
    };

    float4 acc[4][4];
    #pragma unroll
    for (int i = 0; i < 4; i++)
        #pragma unroll
        for (int j = 0; j < 4; j++) acc[i][j] = make_float4(0.f, 0.f, 0.f, 0.f);

    load_chunk(0, 0);
    load_chunk(1, 1);

    int st = 0;
    for (int j = 0; j < E_NC; j++) {
        if (j + 2 < E_NC) cp_wait1(); else cp_wait0();
        __syncthreads();
        if (j + 2 < E_NC) {
            int st2 = st + 2; if (st2 >= 3) st2 -= 3;
            load_chunk(j + 2, st2);
        }

        const __half* As = (const __half*)(smc + st * E_ST_BYTES);
        const __half* Bs = (const __half*)(smc + st * E_ST_BYTES + E_A_BYTES);
        #pragma unroll
        for (int ks = 0; ks < 3; ks++) {
            uint32_t a[4][4], b[4][2];
            #pragma unroll
            for (int mt = 0; mt < 4; mt++) {
                const __half* ap = As + (wr * 64 + mt * 16 + g) * E_PITCH + ks * 16 + 2 * tig;
                a[mt][0] = *reinterpret_cast<const uint32_t*>(ap);
                a[mt][1] = *reinterpret_cast<const uint32_t*>(ap + 8 * E_PITCH);
                a[mt][2] = *reinterpret_cast<const uint32_t*>(ap + 8);
                a[mt][3] = *reinterpret_cast<const uint32_t*>(ap + 8 * E_PITCH + 8);
            }
            #pragma unroll
            for (int nt = 0; nt < 4; nt++) {
                const __half* bp = Bs + (wc * 32 + nt * 8 + g) * E_PITCH + ks * 16 + 2 * tig;
                b[nt][0] = *reinterpret_cast<const uint32_t*>(bp);
                b[nt][1] = *reinterpret_cast<const uint32_t*>(bp + 8);
            }
            #pragma unroll
            for (int mt = 0; mt < 4; mt++)
                #pragma unroll
                for (int nt = 0; nt < 4; nt++)
                    mma_f16(acc[mt][nt], a[mt], b[nt]);
        }
        if (++st >= 3) st -= 3;
    }

    #pragma unroll
    for (int mt = 0; mt < 4; mt++)
        #pragma unroll
        for (int nt = 0; nt < 4; nt++) {
            acc[mt][nt].x *= 100.f; acc[mt][nt].y *= 100.f;
            acc[mt][nt].z *= 100.f; acc[mt][nt].w *= 100.f;
        }

    float* ep = (float*)smc;
    __syncthreads();
    // pass 1: direct orientation
    #pragma unroll
    for (int mt = 0; mt < 4; mt++) {
        const int r0 = wr * 64 + mt * 16 + g, r1 = r0 + 8;
        #pragma unroll
        for (int nt = 0; nt < 4; nt++) {
            const int col = wc * 32 + nt * 8 + tig * 2;
            const float4 cc = acc[mt][nt];
            ep[r0 * EP_PITCH + col] = cc.x; ep[r0 * EP_PITCH + col + 1] = cc.y;
            ep[r1 * EP_PITCH + col] = cc.z; ep[r1 * EP_PITCH + col + 1] = cc.w;
        }
    }
    __syncthreads();
    #pragma unroll
    for (int it = 0; it < 16; it++) {
        const int e = it * 256 + tid;
        const int rr = e >> 5, c4 = (e & 31) * 4;
        *reinterpret_cast<float4*>(EA + (size_t)(m0 + rr) * HW + n0 + c4) =
            *reinterpret_cast<const float4*>(ep + rr * EP_PITCH + c4);
    }
    __syncthreads();
    // pass 2: transposed orientation
    #pragma unroll
    for (int mt = 0; mt < 4; mt++) {
        const int r0 = wr * 64 + mt * 16 + g, r1 = r0 + 8;
        #pragma unroll
        for (int nt = 0; nt < 4; nt++) {
            const int col = wc * 32 + nt * 8 + tig * 2;
            const float4 cc = acc[mt][nt];
            ep[col * EP_PITCH + r0] = cc.x; ep[(col + 1) * EP_PITCH + r0] = cc.y;
            ep[col * EP_PITCH + r1] = cc.z; ep[(col + 1) * EP_PITCH + r1] = cc.w;
        }
    }
    __syncthreads();
    #pragma unroll
    for (int it = 0; it < 16; it++) {
        const int e = it * 256 + tid;
        const int rr = e >> 5, c4 = (e & 31) * 4;
        *reinterpret_cast<float4*>(EB + (size_t)(n0 + rr) * HW + m0 + c4) =
            *reinterpret_cast<const float4*>(ep + rr * EP_PITCH + c4);
    }
}

// ---------------- feature hi/lo split + transpose: f [c][l] -> f' [l][432] ----------------
__global__ __launch_bounds__(256)
void fcvt_kernel(const float* __restrict__ Fa, const float* __restrict__ Fb,
                 __half* __restrict__ outp)
{
    __shared__ float t[32][33];
    const int z = blockIdx.z;
    const int bat = z & 1;
    const bool is_fb = (z < 2);
    const float* src = (is_fb ? Fb : Fa) + (size_t)bat * C_MID * HW;
    __half* dst = outp + (size_t)z * HW * E_K;

    const int l0 = blockIdx.x * 32;
    const int c0 = blockIdx.y * 32;
    const int tx = threadIdx.x & 31, ty = threadIdx.x >> 5;

    #pragma unroll
    for (int i = 0; i < 32; i += 8) {
        const int cg = c0 + ty + i;
        t[ty + i][tx] = (cg < C_MID) ? src[(size_t)cg * HW + l0 + tx] : 0.f;
    }
    __syncthreads();

    const int cl = (threadIdx.x & 15) * 2;
    const int lt = threadIdx.x >> 4;
    #pragma unroll
    for (int i = 0; i < 2; i++) {
        const int ll = lt + i * 16;
        const int cg = c0 + cl;
        if (cg >= 144) continue;
        const float v0 = t[cl][ll], v1 = t[cl + 1][ll];
        const __half h0 = __float2half_rn(v0), h1 = __float2half_rn(v1);
        const __half l0h = __float2half_rn(v0 - __half2float(h0));
        const __half l1h = __float2half_rn(v1 - __half2float(h1));
        const __half2 hh = __halves2half2(h0, h1);
        const __half2 llh = __halves2half2(l0h, l1h);
        __half* base = dst + (size_t)(l0 + ll) * E_K;
        if (is_fb) {
            *reinterpret_cast<__half2*>(base + cg) = hh;
            *reinterpret_cast<__half2*>(base + 144 + cg) = hh;
            *reinterpret_cast<__half2*>(base + 288 + cg) = llh;
        } else {
            *reinterpret_cast<__half2*>(base + cg) = hh;
            *reinterpret_cast<__half2*>(base + 144 + cg) = llh;
            *reinterpret_cast<__half2*>(base + 288 + cg) = hh;
        }
    }
}

// ---------------- fp32 SIMT GEMM with packed f32x2 FMA (conv main) ----------------
#define BM 128
#define BN 128
#define BK 8
#define TM 8
#define TN 8

template<bool TRANS_A, int EPI>
__global__ __launch_bounds__(256, 2)
void sgemm2_kernel(const float* __restrict__ A0, const float* __restrict__ A1,
                   const float* __restrict__ B0, const float* __restrict__ B1,
                   const float* __restrict__ bs0, const float* __restrict__ bs1,
                   float* __restrict__ C0, float* __restrict__ C1,
                   int M, int N, int K, long sA, long sB, long sC, float alpha)
{
    __shared__ float As[BK][BM];
    __shared__ float Bs[BK][BN];

    const int sel = blockIdx.z >> 1, bat = blockIdx.z & 1;
    const float* A = (sel ? A1 : A0) + (long)bat * sA;
    const float* B = (sel ? B1 : B0) + (long)bat * sB;
    const float* bias = sel ? bs1 : bs0;
    float* C = (sel ? C1 : C0) + (long)bat * sC;

    const int m0 = blockIdx.y * BM;
    const int n0 = blockIdx.x * BN;
    const int tid = threadIdx.x;
    const int tx = tid & 15;
    const int ty = tid >> 4;
    const int idx = tid * 4;

    ull acc[4][TN];
    #pragma unroll
    for (int i = 0; i < 4; i++)
        #pragma unroll
        for (int j = 0; j < TN; j++) acc[i][j] = 0ULL;

    for (int k0 = 0; k0 < K; k0 += BK) {
        if (TRANS_A) {
            const int kk = idx / BM;
            const int mm = idx % BM;
            const float4 v = *reinterpret_cast<const float4*>(
                A + (long)(k0 + kk) * M + (m0 + mm));
            *reinterpret_cast<float4*>(&As[kk][mm]) = v;
        } else {
            const int mm = idx / BK;
            const int kk = idx % BK;
            const int row = m0 + mm;
            float4 v = make_float4(0.f, 0.f, 0.f, 0.f);
            if (row < M)
                v = *reinterpret_cast<const float4*>(A + (long)row * K + (k0 + kk));
            As[kk + 0][mm] = v.x;
            As[kk + 1][mm] = v.y;
            As[kk + 2][mm] = v.z;
            As[kk + 3][mm] = v.w;
        }
        {
            const int kk = idx / BN;
            const int nn = idx % BN;
            const float4 v = *reinterpret_cast<const float4*>(
                B + (long)(k0 + kk) * N + (n0 + nn));
            *reinterpret_cast<float4*>(&Bs[kk][nn]) = v;
        }
        __syncthreads();

        #pragma unroll
        for (int kk = 0; kk < BK; kk++) {
            const ulonglong2 a01 = *reinterpret_cast<const ulonglong2*>(&As[kk][ty * TM]);
            const ulonglong2 a23 = *reinterpret_cast<const ulonglong2*>(&As[kk][ty * TM + 4]);
            const float4 rb0 = *reinterpret_cast<const float4*>(&Bs[kk][tx * TN]);
            const float4 rb1 = *reinterpret_cast<const float4*>(&Bs[kk][tx * TN + 4]);
            ull ap[4] = { a01.x, a01.y, a23.x, a23.y };
            float rb[8] = { rb0.x, rb0.y, rb0.z, rb0.w, rb1.x, rb1.y, rb1.z, rb1.w };
            #pragma unroll
            for (int j = 0; j < TN; j++) {
                const ull bb = pack2(rb[j], rb[j]);
                #pragma unroll
                for (int i = 0; i < 4; i++)
                    ffma2u(acc[i][j], ap[i], bb);
            }
        }
        __syncthreads();
    }

    #pragma unroll
    for (int i2 = 0; i2 < 4; i2++) {
        float2 lo[TN];
        #pragma unroll
        for (int j = 0; j < TN; j++) lo[j] = unpack2(acc[i2][j]);
        #pragma unroll
        for (int half = 0; half < 2; half++) {
            const int row = m0 + ty * TM + 2 * i2 + half;
            if (row >= M) continue;
            const float bv = (EPI == 1) ? bias[row] : 0.f;
            float r[TN];
            #pragma unroll
            for (int j = 0; j < TN; j++) r[j] = half ? lo[j].y : lo[j].x;
            #pragma unroll
            for (int j = 0; j < TN; j += 4) {
                float4 v = make_float4(r[j], r[j+1], r[j+2], r[j+3]);
                if (EPI == 1) { v.x += bv; v.y += bv; v.z += bv; v.w += bv; }
                if (EPI == 2) { v.x *= alpha; v.y *= alpha; v.z *= alpha; v.w *= alpha; }
                *reinterpret_cast<float4*>(C + (long)row * N + n0 + tx * TN + j) = v;
            }
        }
    }
}

// ---------------- conv tail: rows 128..135 ----------------
__global__ __launch_bounds__(256)
void conv_tail_kernel(const float* __restrict__ X0, const float* __restrict__ X1,
                      const float* __restrict__ W0, const float* __restrict__ W1,
                      const float* __restrict__ b0, const float* __restrict__ b1,
                      float* __restrict__ F0, float* __restrict__ F1)
{
    __shared__ float ws[8 * C_IN];
    const int sel = blockIdx.z >> 1, bat = blockIdx.z & 1;
    const float* X = (sel ? X1 : X0) + (long)bat * C_IN * HW;
    const float* W = (sel ? W1 : W0) + 128 * C_IN;
    const float* bias = (sel ? b1 : b0) + 128;
    float* F = (sel ? F1 : F0) + (long)bat * C_MID * HW + 128L * HW;

    const int tid = threadIdx.x;
    for (int i = tid; i < 8 * C_IN; i += 256) ws[i] = W[i];
    __syncthreads();

    const int l = blockIdx.x * 256 + tid;
    float acc[8];
    #pragma unroll
    for (int r2 = 0; r2 < 8; r2++) acc[r2] = 0.f;

    #pragma unroll 8
    for (int cin = 0; cin < C_IN; cin++) {
        const float x = X[(long)cin * HW + l];
        #pragma unroll
        for (int r2 = 0; r2 < 8; r2++)
            acc[r2] = fmaf(ws[r2 * C_IN + cin], x, acc[r2]);
    }
    #pragma unroll
    for (int r2 = 0; r2 < 8; r2++)
        F[(long)r2 * HW + l] = acc[r2] + bias[r2];
}

// ---------------- raw fp32 -> fp16 slots (b0,b1,a0,a1) ----------------
__global__ __launch_bounds__(256)
void rawcvt_kernel(const float* __restrict__ a, const float* __restrict__ b,
                   __half* __restrict__ dst)
{
    const int z = blockIdx.z;
    const long slice = (long)C_IN * HW;
    const float* src = (z < 2) ? (b + z * slice) : (a + (z - 2) * slice);
    __half* d = dst + z * slice;
    const long i = ((long)blockIdx.x * 256 + threadIdx.x) * 8;
    const float4 v0 = *reinterpret_cast<const float4*>(src + i);
    const float4 v1 = *reinterpret_cast<const float4*>(src + i + 4);
    __half2 h[4];
    h[0] = __floats2half2_rn(v0.x, v0.y);
    h[1] = __floats2half2_rn(v0.z, v0.w);
    h[2] = __floats2half2_rn(v1.x, v1.y);
    h[3] = __floats2half2_rn(v1.z, v1.w);
    *reinterpret_cast<uint4*>(d + i) = *reinterpret_cast<const uint4*>(h);
}

// ---------------- instance norm + LeakyReLU + re-center ----------------
__global__ __launch_bounds__(256)
void instnorm_kernel(float* __restrict__ Fa, float* __restrict__ Fb)
{
    __shared__ float sh[HW];
    __shared__ float red[8];
    float* F = blockIdx.z ? Fb : Fa;
    float* row = F + ((long)blockIdx.y * C_MID + blockIdx.x) * HW;
    const int tid = threadIdx.x;

    float s = 0.f, s2 = 0.f;
    for (int i = tid; i < HW; i += 256) {
        const float v = row[i];
        sh[i] = v; s += v; s2 += v * v;
    }
    s  = blk_sum(s,  red);
    s2 = blk_sum(s2, red);
    const float mean = s * (1.f / HW);
    const float var  = s2 * (1.f / HW) - mean * mean;
    const float inv  = rsqrtf(var + 1e-5f);

    float s3 = 0.f;
    for (int i = tid; i < HW; i += 256) {
        float v = (sh[i] - mean) * inv;
        v = (v >= 0.f) ? v : 0.2f * v;
        sh[i] = v;
        s3 += v;
    }
    s3 = blk_sum(s3, red);
    const float mean2 = s3 * (1.f / HW);
    for (int i = tid; i < HW; i += 256)
        row[i] = sh[i] - mean2;
}

// ---------------- per-column L2 normalize ----------------
__global__ __launch_bounds__(256)
void l2norm_kernel(float* __restrict__ Fa, float* __restrict__ Fb)
{
    float* F = blockIdx.z ? Fb : Fa;
    const int l = blockIdx.x * 256 + threadIdx.x;
    float* base = F + (long)blockIdx.y * C_MID * HW + l;
    float s = 0.f;
    #pragma unroll 8
    for (int cc = 0; cc < C_MID; cc++) {
        const float v = base[(long)cc * HW];
        s += v * v;
    }
    const float inv = rsqrtf(s);
    #pragma unroll 8
    for (int cc = 0; cc < C_MID; cc++)
        base[(long)cc * HW] *= inv;
}

// ---------------- in-place row softmax + fp16 emit ([k][n] natural layout) ----------------
__global__ __launch_bounds__(256)
void softmax_kernel(float* __restrict__ E, __half* __restrict__ ch)
{
    __shared__ float sh[HW];
    __shared__ float red[8];
    const size_t roff = (size_t)blockIdx.y * HW * HW + (size_t)blockIdx.x * HW;
    float* row = E + roff;
    __half* hrow = ch + roff;
    const int tid = threadIdx.x;

    float mx = -3.4e38f;
    for (int i = tid; i < HW; i += 256) {
        const float v = row[i];
        sh[i] = v;
        mx = fmaxf(mx, v);
    }
    mx = blk_max(mx, red);

    float s = 0.f;
    for (int i = tid; i < HW; i += 256) {
        const float e = __expf(sh[i] - mx);
        sh[i] = e;
        s += e;
    }
    s = blk_sum(s, red);
    const float inv = 1.f / s;
    for (int i = tid * 2; i < HW; i += 512) {
        const float p0 = sh[i] * inv;
        const float p1 = sh[i + 1] * inv;
        *reinterpret_cast<float2*>(row + i) = make_float2(p0, p1);
        *reinterpret_cast<__half2*>(hrow + i) = __floats2half2_rn(p0, p1);
    }
}

// ---------------- launch ----------------
extern "C" void kernel_launch(void* const* d_in, const int* in_sizes, int n_in,
                              void* d_out, int out_size)
{
    const float* fa    = (const float*)d_in[0];
    const float* fb    = (const float*)d_in[1];
    const float* a_raw = (const float*)d_in[2];
    const float* b_raw = (const float*)d_in[3];
    const float* Wa    = (const float*)d_in[4];
    const float* ba    = (const float*)d_in[5];
    const float* Wb    = (const float*)d_in[6];
    const float* bb    = (const float*)d_in[7];
    float* out = (float*)d_out;

    float *pfa, *pfb;
    __half *prawh, *pch, *peh;
    cudaGetSymbolAddress((void**)&pfa, g_fa);
    cudaGetSymbolAddress((void**)&pfb, g_fb);
    cudaGetSymbolAddress((void**)&prawh, g_rawh);
    cudaGetSymbolAddress((void**)&pch, g_ch);
    cudaGetSymbolAddress((void**)&peh, g_eh);

    cudaFuncSetAttribute(wgemm_f16_kernel,
                         cudaFuncAttributeMaxDynamicSharedMemorySize, WH_SMEM);
    cudaFuncSetAttribute(energy_f16_kernel,
                         cudaFuncAttributeMaxDynamicSharedMemorySize, E_SMEM);

    const long CORR = (long)HW * HW;
    float* corr_ab = out;
    float* corr_ba = out + (long)N_B * CORR;
    float* a_warp  = out + 2L * N_B * CORR;
    float* b_warp  = a_warp + (long)N_B * C_IN * HW;

    const dim3 blk(256);
    const long sMID = (long)C_MID * HW;
    const long sIN  = (long)C_IN * HW;

    // 1) 1x1 conv main tile: rows 0..127
    {
        dim3 g(HW / BN, 1, 4);
        sgemm2_kernel<false, 1><<<g, blk>>>(Wa, Wb, fa, fb, ba, bb, pfa, pfb,
                                            C_MID, HW, C_IN, 0L, sIN, sMID, 0.f);
    }
    // 1b) conv tail: rows 128..135
    {
        dim3 g(HW / 256, 1, 4);
        conv_tail_kernel<<<g, blk>>>(fa, fb, Wa, Wb, ba, bb, pfa, pfb);
    }
    // 2) InstanceNorm + LeakyReLU + re-center
    {
        dim3 g(C_MID, N_B, 2);
        instnorm_kernel<<<g, blk>>>(pfa, pfb);
    }
    // 3) per-column L2 normalize
    {
        dim3 g(HW / 256, N_B, 2);
        l2norm_kernel<<<g, blk>>>(pfa, pfb);
    }
    // 4) feature hi/lo split + transpose for tensor-core energy
    {
        dim3 g(HW / 32, 5, 4);
        fcvt_kernel<<<g, blk>>>(pfa, pfb, peh);
    }
    // 4b) energy GEMM on fp16 mma (K=432 split), writes E and E^T (x100)
    {
        dim3 g(HW / 128, HW / 128, 2);
        energy_f16_kernel<<<g, blk, E_SMEM>>>(peh, corr_ab, corr_ba);
    }
    // 5) softmax over all corr rows; emits fp32 output + fp16 copy for wgemm
    {
        dim3 g(HW, 2 * N_B);
        softmax_kernel<<<g, blk>>>(out, pch);
    }
    // 6) convert raw -> fp16 slots
    {
        dim3 g((unsigned)(sIN / 8 / 256), 1, 4);
        rawcvt_kernel<<<g, blk>>>(a_raw, b_raw, prawh);
    }
    // 7) warp GEMMs on fp16 mma (B via ldmatrix.trans from natural [k][n] corr)
    {
        dim3 g(HW / 256, (C_IN + 127) / 128, 4);
        wgemm_f16_kernel<<<g, blk, WH_SMEM>>>(prawh, pch, b_warp, a_warp);
    }
}

// round 13
// speedup vs baseline: 1.4373x; 1.0007x over previous
#include <cuda_runtime.h>
#include <cuda_fp16.h>
#include <math.h>
#include <stdint.h>
#include <stddef.h>

// ---------------- problem constants ----------------
#define N_B   2
#define C_IN  1088
#define C_MID 136
#define HW    4096

typedef unsigned long long ull;

// ---------------- device scratch ----------------
__device__ __align__(16) float g_fa[N_B * C_MID * HW];
__device__ __align__(16) float g_fb[N_B * C_MID * HW];
// fp16 raw, slot z: 0,1 = b_raw batches; 2,3 = a_raw batches
__device__ __align__(16) __half g_rawh[4ULL * C_IN * HW];
// fp16 softmaxed corr, natural [k][n] layout, slots = [ab0, ab1, ba0, ba1]
__device__ __align__(16) __half g_ch[4ULL * HW * HW];
// fp16 hi/lo-split features for energy: slots 0,1 = fb' (bat0,1), 2,3 = fa'
#define E_K 432
__device__ __align__(16) __half g_eh[4ULL * HW * E_K];

// ---------------- helpers ----------------
__device__ __forceinline__ ull pack2(float x, float y) {
    ull r; asm("mov.b64 %0, {%1, %2};" : "=l"(r) : "f"(x), "f"(y)); return r;
}
__device__ __forceinline__ float2 unpack2(ull v) {
    float2 f; asm("mov.b64 {%0, %1}, %2;" : "=f"(f.x), "=f"(f.y) : "l"(v)); return f;
}
__device__ __forceinline__ void ffma2u(ull& d, ull a, ull b) {
    asm("fma.rn.f32x2 %0, %1, %2, %0;" : "+l"(d) : "l"(a), "l"(b));
}
__device__ __forceinline__ void cp16(uint32_t dst, const void* src, uint32_t sz) {
    asm volatile("cp.async.ca.shared.global [%0], [%1], 16, %2;"
                 :: "r"(dst), "l"(src), "r"(sz));
}
__device__ __forceinline__ void cp_commit() { asm volatile("cp.async.commit_group;"); }
__device__ __forceinline__ void cp_wait0()  { asm volatile("cp.async.wait_group 0;" ::: "memory"); }
__device__ __forceinline__ void cp_wait1()  { asm volatile("cp.async.wait_group 1;" ::: "memory"); }

__device__ __forceinline__ float blk_sum(float v, float* red) {
    const int tid = threadIdx.x;
    #pragma unroll
    for (int o = 16; o > 0; o >>= 1) v += __shfl_down_sync(0xffffffffu, v, o);
    if ((tid & 31) == 0) red[tid >> 5] = v;
    __syncthreads();
    if (tid < 32) {
        v = (tid < 8) ? red[tid] : 0.f;
        #pragma unroll
        for (int o = 4; o > 0; o >>= 1) v += __shfl_down_sync(0xffffffffu, v, o);
        if (tid == 0) red[0] = v;
    }
    __syncthreads();
    v = red[0];
    __syncthreads();
    return v;
}

__device__ __forceinline__ float blk_max(float v, float* red) {
    const int tid = threadIdx.x;
    #pragma unroll
    for (int o = 16; o > 0; o >>= 1) v = fmaxf(v, __shfl_down_sync(0xffffffffu, v, o));
    if ((tid & 31) == 0) red[tid >> 5] = v;
    __syncthreads();
    if (tid < 32) {
        v = (tid < 8) ? red[tid] : -3.4e38f;
        #pragma unroll
        for (int o = 4; o > 0; o >>= 1) v = fmaxf(v, __shfl_down_sync(0xffffffffu, v, o));
        if (tid == 0) red[0] = v;
    }
    __syncthreads();
    v = red[0];
    __syncthreads();
    return v;
}

// ---------------- mma.sync fp16 primitive (f32 accumulate) ----------------
__device__ __forceinline__ void mma_f16(float4& c, const uint32_t a[4], const uint32_t b[2]) {
    asm volatile(
        "mma.sync.aligned.m16n8k16.row.col.f32.f16.f16.f32 "
        "{%0,%1,%2,%3},{%4,%5,%6,%7},{%8,%9},{%0,%1,%2,%3};"
        : "+f"(c.x), "+f"(c.y), "+f"(c.z), "+f"(c.w)
        : "r"(a[0]), "r"(a[1]), "r"(a[2]), "r"(a[3]), "r"(b[0]), "r"(b[1]));
}

__device__ __forceinline__ void ldsm4t(uint32_t& r0, uint32_t& r1, uint32_t& r2, uint32_t& r3,
                                       uint32_t addr) {
    asm volatile("ldmatrix.sync.aligned.m8n8.x4.trans.shared.b16 {%0,%1,%2,%3}, [%4];"
                 : "=r"(r0), "=r"(r1), "=r"(r2), "=r"(r3) : "r"(addr));
}

// ---------------- warp-stage GEMM: fp16 mma, CTA 128x256, 3-stage cp.async ----------------
#define HA_PITCH 40
#define HB_PITCH 264
#define HA_BYTES (128 * HA_PITCH * 2)       // 10240
#define HB_BYTES (32 * HB_PITCH * 2)        // 16896
#define HST_BYTES (HA_BYTES + HB_BYTES)     // 27136
#define HN_STAGE 3
#define WH_SMEM (HN_STAGE * HST_BYTES)      // 81408

__global__ __launch_bounds__(256)
void wgemm_f16_kernel(const __half* __restrict__ Ah, const __half* __restrict__ Bh,
                      float* __restrict__ b_warp, float* __restrict__ a_warp)
{
    extern __shared__ char smc[];
    const uint32_t smem_base = (uint32_t)__cvta_generic_to_shared(smc);

    const int z = blockIdx.z;
    const __half* A = Ah + (size_t)z * C_IN * HW;
    const __half* B = Bh + (size_t)z * HW * HW;
    float* C = (z < 2) ? (b_warp + (size_t)z * C_IN * HW)
                       : (a_warp + (size_t)(z - 2) * C_IN * HW);

    const int m0 = blockIdx.y * 128;
    const int n0 = blockIdx.x * 256;
    const int tid = threadIdx.x;
    const int wid = tid >> 5;
    const int lane = tid & 31;
    const int wr = wid >> 2;
    const int wc = wid & 3;
    const int g = lane >> 2;
    const int tig = lane & 3;

    auto load_chunk = [&](int kc, int st) {
        const uint32_t sb = smem_base + (uint32_t)(st * HST_BYTES);
        const int k0 = kc * 32;
        #pragma unroll
        for (int p = 0; p < 2; p++) {
            const int u = p * 256 + tid;
            const int row = u >> 2, q = u & 3;
            const int gr = m0 + row;
            const uint32_t dst = sb + (uint32_t)(row * HA_PITCH * 2 + q * 16);
            const __half* src = A + (size_t)((gr < C_IN) ? gr : 0) * HW + k0 + q * 8;
            cp16(dst, src, (gr < C_IN) ? 16u : 0u);
        }
        #pragma unroll
        for (int p = 0; p < 4; p++) {
            const int u = p * 256 + tid;
            const int row = u >> 5, q = u & 31;
            const uint32_t dst = sb + HA_BYTES + (uint32_t)(row * HB_PITCH * 2 + q * 16);
            const __half* src = B + (size_t)(k0 + row) * HW + n0 + q * 8;
            cp16(dst, src, 16u);
        }
        cp_commit();
    };

    float4 acc[4][8];
    #pragma unroll
    for (int i = 0; i < 4; i++)
        #pragma unroll
        for (int j = 0; j < 8; j++) acc[i][j] = make_float4(0.f, 0.f, 0.f, 0.f);

    const int NC = HW / 32;
    load_chunk(0, 0);
    load_chunk(1, 1);

    int st = 0;
    for (int j = 0; j < NC; j++) {
        if (j + 2 < NC) cp_wait1(); else cp_wait0();
        __syncthreads();
        if (j + 2 < NC) {
            int st2 = st + 2; if (st2 >= HN_STAGE) st2 -= HN_STAGE;
            load_chunk(j + 2, st2);
        }

        const __half* As = (const __half*)(smc + st * HST_BYTES);
        const uint32_t Bs = smem_base + (uint32_t)(st * HST_BYTES + HA_BYTES);

        uint32_t b[8][4];
        #pragma unroll
        for (int nt = 0; nt < 8; nt++) {
            const uint32_t addr = Bs + (uint32_t)(lane * (HB_PITCH * 2) +
                                                  (wc * 64 + nt * 8) * 2);
            ldsm4t(b[nt][0], b[nt][1], b[nt][2], b[nt][3], addr);
        }
        #pragma unroll
        for (int ks = 0; ks < 2; ks++) {
            uint32_t a[4][4];
            #pragma unroll
            for (int mt = 0; mt < 4; mt++) {
                const __half* ap = As + (wr * 64 + mt * 16 + g) * HA_PITCH + ks * 16 + 2 * tig;
                a[mt][0] = *reinterpret_cast<const uint32_t*>(ap);
                a[mt][1] = *reinterpret_cast<const uint32_t*>(ap + 8 * HA_PITCH);
                a[mt][2] = *reinterpret_cast<const uint32_t*>(ap + 8);
                a[mt][3] = *reinterpret_cast<const uint32_t*>(ap + 8 * HA_PITCH + 8);
            }
            #pragma unroll
            for (int mt = 0; mt < 4; mt++)
                #pragma unroll
                for (int nt = 0; nt < 8; nt++)
                    mma_f16(acc[mt][nt], a[mt], &b[nt][ks * 2]);
        }
        if (++st >= HN_STAGE) st -= HN_STAGE;
    }

    #pragma unroll
    for (int mt = 0; mt < 4; mt++) {
        const int r0 = m0 + wr * 64 + mt * 16 + g;
        const int r1 = r0 + 8;
        #pragma unroll
        for (int nt = 0; nt < 8; nt++) {
            const int col = n0 + wc * 64 + nt * 8 + tig * 2;
            const float4 cc = acc[mt][nt];
            if (r0 < C_IN)
                *reinterpret_cast<float2*>(C + (size_t)r0 * HW + col) = make_float2(cc.x, cc.y);
            if (r1 < C_IN)
                *reinterpret_cast<float2*>(C + (size_t)r1 * HW + col) = make_float2(cc.z, cc.w);
        }
    }
}

// ---------------- energy GEMM: fp16 hi/lo split, K=432, dual-orientation epilogue ----------------
#define E_CH 48
#define E_NC (E_K / E_CH)                 // 9
#define E_PITCH 56
#define E_A_BYTES (128 * E_PITCH * 2)     // 14336
#define E_ST_BYTES (2 * E_A_BYTES)        // 28672
#define E_SMEM (3 * E_ST_BYTES)           // 86016
#define EP_PITCH 132

__global__ __launch_bounds__(256)
void energy_f16_kernel(const __half* __restrict__ eh,
                       float* __restrict__ Eab, float* __restrict__ Eba)
{
    extern __shared__ char smc[];
    const uint32_t smem_base = (uint32_t)__cvta_generic_to_shared(smc);
    const int bat = blockIdx.z;
    const __half* A = eh + (size_t)bat * HW * E_K;
    const __half* B = eh + (size_t)(2 + bat) * HW * E_K;
    float* EA = Eab + (size_t)bat * HW * HW;
    float* EB = Eba + (size_t)bat * HW * HW;

    const int m0 = blockIdx.y * 128;
    const int n0 = blockIdx.x * 128;
    const int tid = threadIdx.x;
    const int wid = tid >> 5, lane = tid & 31;
    const int wr = wid >> 2, wc = wid & 3;
    const int g = lane >> 2, tig = lane & 3;

    auto load_chunk = [&](int kc, int st) {
        const uint32_t sb = smem_base + (uint32_t)(st * E_ST_BYTES);
        const int k0 = kc * E_CH;
        #pragma unroll
        for (int p = 0; p < 3; p++) {
            const int u = p * 256 + tid;
            const int row = u / 6, q = u % 6;
            cp16(sb + (uint32_t)(row * (E_PITCH * 2) + q * 16),
                 A + (size_t)(m0 + row) * E_K + k0 + q * 8, 16u);
        }
        #pragma unroll
        for (int p = 0; p < 3; p++) {
            const int u = p * 256 + tid;
            const int row = u / 6, q = u % 6;
            cp16(sb + E_A_BYTES + (uint32_t)(row * (E_PITCH * 2) + q * 16),
                 B + (size_t)(n0 + row) * E_K + k0 + q * 8, 16u);
        }
        cp_commit();
    };

    float4 acc[4][4];
    #pragma unroll
    for (int i = 0; i < 4; i++)
        #pragma unroll
        for (int j = 0; j < 4; j++) acc[i][j] = make_float4(0.f, 0.f, 0.f, 0.f);

    load_chunk(0, 0);
    load_chunk(1, 1);

    int st = 0;
    for (int j = 0; j < E_NC; j++) {
        if (j + 2 < E_NC) cp_wait1(); else cp_wait0();
        __syncthreads();
        if (j + 2 < E_NC) {
            int st2 = st + 2; if (st2 >= 3) st2 -= 3;
            load_chunk(j + 2, st2);
        }

        const __half* As = (const __half*)(smc + st * E_ST_BYTES);
        const __half* Bs = (const __half*)(smc + st * E_ST_BYTES + E_A_BYTES);
        #pragma unroll
        for (int ks = 0; ks < 3; ks++) {
            uint32_t a[4][4], b[4][2];
            #pragma unroll
            for (int mt = 0; mt < 4; mt++) {
                const __half* ap = As + (wr * 64 + mt * 16 + g) * E_PITCH + ks * 16 + 2 * tig;
                a[mt][0] = *reinterpret_cast<const uint32_t*>(ap);
                a[mt][1] = *reinterpret_cast<const uint32_t*>(ap + 8 * E_PITCH);
                a[mt][2] = *reinterpret_cast<const uint32_t*>(ap + 8);
                a[mt][3] = *reinterpret_cast<const uint32_t*>(ap + 8 * E_PITCH + 8);
            }
            #pragma unroll
            for (int nt = 0; nt < 4; nt++) {
                const __half* bp = Bs + (wc * 32 + nt * 8 + g) * E_PITCH + ks * 16 + 2 * tig;
                b[nt][0] = *reinterpret_cast<const uint32_t*>(bp);
                b[nt][1] = *reinterpret_cast<const uint32_t*>(bp + 8);
            }
            #pragma unroll
            for (int mt = 0; mt < 4; mt++)
                #pragma unroll
                for (int nt = 0; nt < 4; nt++)
                    mma_f16(acc[mt][nt], a[mt], b[nt]);
        }
        if (++st >= 3) st -= 3;
    }

    #pragma unroll
    for (int mt = 0; mt < 4; mt++)
        #pragma unroll
        for (int nt = 0; nt < 4; nt++) {
            acc[mt][nt].x *= 100.f; acc[mt][nt].y *= 100.f;
            acc[mt][nt].z *= 100.f; acc[mt][nt].w *= 100.f;
        }

    float* ep = (float*)smc;
    __syncthreads();
    #pragma unroll
    for (int mt = 0; mt < 4; mt++) {
        const int r0 = wr * 64 + mt * 16 + g, r1 = r0 + 8;
        #pragma unroll
        for (int nt = 0; nt < 4; nt++) {
            const int col = wc * 32 + nt * 8 + tig * 2;
            const float4 cc = acc[mt][nt];
            ep[r0 * EP_PITCH + col] = cc.x; ep[r0 * EP_PITCH + col + 1] = cc.y;
            ep[r1 * EP_PITCH + col] = cc.z; ep[r1 * EP_PITCH + col + 1] = cc.w;
        }
    }
    __syncthreads();
    #pragma unroll
    for (int it = 0; it < 16; it++) {
        const int e = it * 256 + tid;
        const int rr = e >> 5, c4 = (e & 31) * 4;
        *reinterpret_cast<float4*>(EA + (size_t)(m0 + rr) * HW + n0 + c4) =
            *reinterpret_cast<const float4*>(ep + rr * EP_PITCH + c4);
    }
    __syncthreads();
    #pragma unroll
    for (int mt = 0; mt < 4; mt++) {
        const int r0 = wr * 64 + mt * 16 + g, r1 = r0 + 8;
        #pragma unroll
        for (int nt = 0; nt < 4; nt++) {
            const int col = wc * 32 + nt * 8 + tig * 2;
            const float4 cc = acc[mt][nt];
            ep[col * EP_PITCH + r0] = cc.x; ep[(col + 1) * EP_PITCH + r0] = cc.y;
            ep[col * EP_PITCH + r1] = cc.z; ep[(col + 1) * EP_PITCH + r1] = cc.w;
        }
    }
    __syncthreads();
    #pragma unroll
    for (int it = 0; it < 16; it++) {
        const int e = it * 256 + tid;
        const int rr = e >> 5, c4 = (e & 31) * 4;
        *reinterpret_cast<float4*>(EB + (size_t)(n0 + rr) * HW + m0 + c4) =
            *reinterpret_cast<const float4*>(ep + rr * EP_PITCH + c4);
    }
}

// ---------------- fused L2-normalize + hi/lo split + transpose ----------------
// Reads raw features F [c][l]; computes per-l inverse L2 norm over c; writes
// fp16 split f' [l][432] directly. Slices z: 0,1 = fb batches ([hi,hi,lo]),
// 2,3 = fa batches ([hi,lo,hi]). F is NOT written back (only consumer is this).
__global__ __launch_bounds__(256)
void l2fcvt_kernel(const float* __restrict__ Fa, const float* __restrict__ Fb,
                   __half* __restrict__ outp)
{
    __shared__ float t[C_MID][33];
    __shared__ float inv_s[32];
    const int z = blockIdx.y;
    const int bat = z & 1;
    const bool is_fb = (z < 2);
    const float* src = (is_fb ? Fb : Fa) + (size_t)bat * C_MID * HW;
    __half* dst = outp + (size_t)z * HW * E_K;

    const int l0 = blockIdx.x * 32;
    const int tid = threadIdx.x;
    const int lane = tid & 31;
    const int wrow = tid >> 5;

    for (int c = wrow; c < C_MID; c += 8)
        t[c][lane] = src[(size_t)c * HW + l0 + lane];
    __syncthreads();

    const int ln = tid >> 3;      // 0..31 local l
    const int j = tid & 7;
    float s = 0.f;
    for (int c = j; c < C_MID; c += 8) { const float v = t[c][ln]; s += v * v; }
    s += __shfl_down_sync(0xffffffffu, s, 4);
    s += __shfl_down_sync(0xffffffffu, s, 2);
    s += __shfl_down_sync(0xffffffffu, s, 1);
    if (j == 0) inv_s[ln] = rsqrtf(s);
    __syncthreads();

    const float inv = inv_s[ln];
    __half* base = dst + (size_t)(l0 + ln) * E_K;
    #pragma unroll
    for (int p = 0; p < 9; p++) {
        const int cp = j + p * 8;          // pair index 0..71
        if (cp >= 72) break;
        const int c = cp * 2;
        const float v0 = (c < C_MID) ? t[c][ln] * inv : 0.f;
        const float v1 = (c + 1 < C_MID) ? t[c + 1][ln] * inv : 0.f;
        const __half h0 = __float2half_rn(v0), h1 = __float2half_rn(v1);
        const __half l0h = __float2half_rn(v0 - __half2float(h0));
        const __half l1h = __float2half_rn(v1 - __half2float(h1));
        const __half2 hh = __halves2half2(h0, h1);
        const __half2 llh = __halves2half2(l0h, l1h);
        *reinterpret_cast<__half2*>(base + c) = hh;
        if (is_fb) {
            *reinterpret_cast<__half2*>(base + 144 + c) = hh;
            *reinterpret_cast<__half2*>(base + 288 + c) = llh;
        } else {
            *reinterpret_cast<__half2*>(base + 144 + c) = llh;
            *reinterpret_cast<__half2*>(base + 288 + c) = hh;
        }
    }
}

// ---------------- fp32 SIMT GEMM with packed f32x2 FMA (conv main) ----------------
#define BM 128
#define BN 128
#define BK 8
#define TM 8
#define TN 8

template<bool TRANS_A, int EPI>
__global__ __launch_bounds__(256, 2)
void sgemm2_kernel(const float* __restrict__ A0, const float* __restrict__ A1,
                   const float* __restrict__ B0, const float* __restrict__ B1,
                   const float* __restrict__ bs0, const float* __restrict__ bs1,
                   float* __restrict__ C0, float* __restrict__ C1,
                   int M, int N, int K, long sA, long sB, long sC, float alpha)
{
    __shared__ float As[BK][BM];
    __shared__ float Bs[BK][BN];

    const int sel = blockIdx.z >> 1, bat = blockIdx.z & 1;
    const float* A = (sel ? A1 : A0) + (long)bat * sA;
    const float* B = (sel ? B1 : B0) + (long)bat * sB;
    const float* bias = sel ? bs1 : bs0;
    float* C = (sel ? C1 : C0) + (long)bat * sC;

    const int m0 = blockIdx.y * BM;
    const int n0 = blockIdx.x * BN;
    const int tid = threadIdx.x;
    const int tx = tid & 15;
    const int ty = tid >> 4;
    const int idx = tid * 4;

    ull acc[4][TN];
    #pragma unroll
    for (int i = 0; i < 4; i++)
        #pragma unroll
        for (int j = 0; j < TN; j++) acc[i][j] = 0ULL;

    for (int k0 = 0; k0 < K; k0 += BK) {
        if (TRANS_A) {
            const int kk = idx / BM;
            const int mm = idx % BM;
            const float4 v = *reinterpret_cast<const float4*>(
                A + (long)(k0 + kk) * M + (m0 + mm));
            *reinterpret_cast<float4*>(&As[kk][mm]) = v;
        } else {
            const int mm = idx / BK;
            const int kk = idx % BK;
            const int row = m0 + mm;
            float4 v = make_float4(0.f, 0.f, 0.f, 0.f);
            if (row < M)
                v = *reinterpret_cast<const float4*>(A + (long)row * K + (k0 + kk));
            As[kk + 0][mm] = v.x;
            As[kk + 1][mm] = v.y;
            As[kk + 2][mm] = v.z;
            As[kk + 3][mm] = v.w;
        }
        {
            const int kk = idx / BN;
            const int nn = idx % BN;
            const float4 v = *reinterpret_cast<const float4*>(
                B + (long)(k0 + kk) * N + (n0 + nn));
            *reinterpret_cast<float4*>(&Bs[kk][nn]) = v;
        }
        __syncthreads();

        #pragma unroll
        for (int kk = 0; kk < BK; kk++) {
            const ulonglong2 a01 = *reinterpret_cast<const ulonglong2*>(&As[kk][ty * TM]);
            const ulonglong2 a23 = *reinterpret_cast<const ulonglong2*>(&As[kk][ty * TM + 4]);
            const float4 rb0 = *reinterpret_cast<const float4*>(&Bs[kk][tx * TN]);
            const float4 rb1 = *reinterpret_cast<const float4*>(&Bs[kk][tx * TN + 4]);
            ull ap[4] = { a01.x, a01.y, a23.x, a23.y };
            float rb[8] = { rb0.x, rb0.y, rb0.z, rb0.w, rb1.x, rb1.y, rb1.z, rb1.w };
            #pragma unroll
            for (int j = 0; j < TN; j++) {
                const ull bb = pack2(rb[j], rb[j]);
                #pragma unroll
                for (int i = 0; i < 4; i++)
                    ffma2u(acc[i][j], ap[i], bb);
            }
        }
        __syncthreads();
    }

    #pragma unroll
    for (int i2 = 0; i2 < 4; i2++) {
        float2 lo[TN];
        #pragma unroll
        for (int j = 0; j < TN; j++) lo[j] = unpack2(acc[i2][j]);
        #pragma unroll
        for (int half = 0; half < 2; half++) {
            const int row = m0 + ty * TM + 2 * i2 + half;
            if (row >= M) continue;
            const float bv = (EPI == 1) ? bias[row] : 0.f;
            float r[TN];
            #pragma unroll
            for (int j = 0; j < TN; j++) r[j] = half ? lo[j].y : lo[j].x;
            #pragma unroll
            for (int j = 0; j < TN; j += 4) {
                float4 v = make_float4(r[j], r[j+1], r[j+2], r[j+3]);
                if (EPI == 1) { v.x += bv; v.y += bv; v.z += bv; v.w += bv; }
                if (EPI == 2) { v.x *= alpha; v.y *= alpha; v.z *= alpha; v.w *= alpha; }
                *reinterpret_cast<float4*>(C + (long)row * N + n0 + tx * TN + j) = v;
            }
        }
    }
}

// ---------------- conv tail: rows 128..135 ----------------
__global__ __launch_bounds__(256)
void conv_tail_kernel(const float* __restrict__ X0, const float* __restrict__ X1,
                      const float* __restrict__ W0, const float* __restrict__ W1,
                      const float* __restrict__ b0, const float* __restrict__ b1,
                      float* __restrict__ F0, float* __restrict__ F1)
{
    __shared__ float ws[8 * C_IN];
    const int sel = blockIdx.z >> 1, bat = blockIdx.z & 1;
    const float* X = (sel ? X1 : X0) + (long)bat * C_IN * HW;
    const float* W = (sel ? W1 : W0) + 128 * C_IN;
    const float* bias = (sel ? b1 : b0) + 128;
    float* F = (sel ? F1 : F0) + (long)bat * C_MID * HW + 128L * HW;

    const int tid = threadIdx.x;
    for (int i = tid; i < 8 * C_IN; i += 256) ws[i] = W[i];
    __syncthreads();

    const int l = blockIdx.x * 256 + tid;
    float acc[8];
    #pragma unroll
    for (int r2 = 0; r2 < 8; r2++) acc[r2] = 0.f;

    #pragma unroll 8
    for (int cin = 0; cin < C_IN; cin++) {
        const float x = X[(long)cin * HW + l];
        #pragma unroll
        for (int r2 = 0; r2 < 8; r2++)
            acc[r2] = fmaf(ws[r2 * C_IN + cin], x, acc[r2]);
    }
    #pragma unroll
    for (int r2 = 0; r2 < 8; r2++)
        F[(long)r2 * HW + l] = acc[r2] + bias[r2];
}

// ---------------- raw fp32 -> fp16 slots (b0,b1,a0,a1) ----------------
__global__ __launch_bounds__(256)
void rawcvt_kernel(const float* __restrict__ a, const float* __restrict__ b,
                   __half* __restrict__ dst)
{
    const int z = blockIdx.z;
    const long slice = (long)C_IN * HW;
    const float* src = (z < 2) ? (b + z * slice) : (a + (z - 2) * slice);
    __half* d = dst + z * slice;
    const long i = ((long)blockIdx.x * 256 + threadIdx.x) * 8;
    const float4 v0 = *reinterpret_cast<const float4*>(src + i);
    const float4 v1 = *reinterpret_cast<const float4*>(src + i + 4);
    __half2 h[4];
    h[0] = __floats2half2_rn(v0.x, v0.y);
    h[1] = __floats2half2_rn(v0.z, v0.w);
    h[2] = __floats2half2_rn(v1.x, v1.y);
    h[3] = __floats2half2_rn(v1.z, v1.w);
    *reinterpret_cast<uint4*>(d + i) = *reinterpret_cast<const uint4*>(h);
}

// ---------------- instance norm + LeakyReLU + re-center ----------------
__global__ __launch_bounds__(256)
void instnorm_kernel(float* __restrict__ Fa, float* __restrict__ Fb)
{
    __shared__ float sh[HW];
    __shared__ float red[8];
    float* F = blockIdx.z ? Fb : Fa;
    float* row = F + ((long)blockIdx.y * C_MID + blockIdx.x) * HW;
    const int tid = threadIdx.x;

    float s = 0.f, s2 = 0.f;
    for (int i = tid; i < HW; i += 256) {
        const float v = row[i];
        sh[i] = v; s += v; s2 += v * v;
    }
    s  = blk_sum(s,  red);
    s2 = blk_sum(s2, red);
    const float mean = s * (1.f / HW);
    const float var  = s2 * (1.f / HW) - mean * mean;
    const float inv  = rsqrtf(var + 1e-5f);

    float s3 = 0.f;
    for (int i = tid; i < HW; i += 256) {
        float v = (sh[i] - mean) * inv;
        v = (v >= 0.f) ? v : 0.2f * v;
        sh[i] = v;
        s3 += v;
    }
    s3 = blk_sum(s3, red);
    const float mean2 = s3 * (1.f / HW);
    for (int i = tid; i < HW; i += 256)
        row[i] = sh[i] - mean2;
}

// ---------------- in-place row softmax + fp16 emit ([k][n] natural layout) ----------------
__global__ __launch_bounds__(256)
void softmax_kernel(float* __restrict__ E, __half* __restrict__ ch)
{
    __shared__ float sh[HW];
    __shared__ float red[8];
    const size_t roff = (size_t)blockIdx.y * HW * HW + (size_t)blockIdx.x * HW;
    float* row = E + roff;
    __half* hrow = ch + roff;
    const int tid = threadIdx.x;

    float mx = -3.4e38f;
    for (int i = tid; i < HW; i += 256) {
        const float v = row[i];
        sh[i] = v;
        mx = fmaxf(mx, v);
    }
    mx = blk_max(mx, red);

    float s = 0.f;
    for (int i = tid; i < HW; i += 256) {
        const float e = __expf(sh[i] - mx);
        sh[i] = e;
        s += e;
    }
    s = blk_sum(s, red);
    const float inv = 1.f / s;
    for (int i = tid * 4; i < HW; i += 1024) {
        const float4 p = make_float4(sh[i] * inv, sh[i + 1] * inv,
                                     sh[i + 2] * inv, sh[i + 3] * inv);
        *reinterpret_cast<float4*>(row + i) = p;
        *reinterpret_cast<__half2*>(hrow + i) = __floats2half2_rn(p.x, p.y);
        *reinterpret_cast<__half2*>(hrow + i + 2) = __floats2half2_rn(p.z, p.w);
    }
}

// ---------------- launch ----------------
extern "C" void kernel_launch(void* const* d_in, const int* in_sizes, int n_in,
                              void* d_out, int out_size)
{
    const float* fa    = (const float*)d_in[0];
    const float* fb    = (const float*)d_in[1];
    const float* a_raw = (const float*)d_in[2];
    const float* b_raw = (const float*)d_in[3];
    const float* Wa    = (const float*)d_in[4];
    const float* ba    = (const float*)d_in[5];
    const float* Wb    = (const float*)d_in[6];
    const float* bb    = (const float*)d_in[7];
    float* out = (float*)d_out;

    float *pfa, *pfb;
    __half *prawh, *pch, *peh;
    cudaGetSymbolAddress((void**)&pfa, g_fa);
    cudaGetSymbolAddress((void**)&pfb, g_fb);
    cudaGetSymbolAddress((void**)&prawh, g_rawh);
    cudaGetSymbolAddress((void**)&pch, g_ch);
    cudaGetSymbolAddress((void**)&peh, g_eh);

    cudaFuncSetAttribute(wgemm_f16_kernel,
                         cudaFuncAttributeMaxDynamicSharedMemorySize, WH_SMEM);
    cudaFuncSetAttribute(energy_f16_kernel,
                         cudaFuncAttributeMaxDynamicSharedMemorySize, E_SMEM);

    const long CORR = (long)HW * HW;
    float* corr_ab = out;
    float* corr_ba = out + (long)N_B * CORR;
    float* a_warp  = out + 2L * N_B * CORR;
    float* b_warp  = a_warp + (long)N_B * C_IN * HW;

    const dim3 blk(256);
    const long sMID = (long)C_MID * HW;
    const long sIN  = (long)C_IN * HW;

    // 1) 1x1 conv main tile: rows 0..127
    {
        dim3 g(HW / BN, 1, 4);
        sgemm2_kernel<false, 1><<<g, blk>>>(Wa, Wb, fa, fb, ba, bb, pfa, pfb,
                                            C_MID, HW, C_IN, 0L, sIN, sMID, 0.f);
    }
    // 1b) conv tail: rows 128..135
    {
        dim3 g(HW / 256, 1, 4);
        conv_tail_kernel<<<g, blk>>>(fa, fb, Wa, Wb, ba, bb, pfa, pfb);
    }
    // 2) InstanceNorm + LeakyReLU + re-center
    {
        dim3 g(C_MID, N_B, 2);
        instnorm_kernel<<<g, blk>>>(pfa, pfb);
    }
    // 3) fused per-column L2 normalize + hi/lo split + transpose -> g_eh
    {
        dim3 g(HW / 32, 4);
        l2fcvt_kernel<<<g, blk>>>(pfa, pfb, peh);
    }
    // 4) energy GEMM on fp16 mma (K=432 split), writes E and E^T (x100)
    {
        dim3 g(HW / 128, HW / 128, 2);
        energy_f16_kernel<<<g, blk, E_SMEM>>>(peh, corr_ab, corr_ba);
    }
    // 5) softmax over all corr rows; emits fp32 output + fp16 copy for wgemm
    {
        dim3 g(HW, 2 * N_B);
        softmax_kernel<<<g, blk>>>(out, pch);
    }
    // 6) convert raw -> fp16 slots
    {
        dim3 g((unsigned)(sIN / 8 / 256), 1, 4);
        rawcvt_kernel<<<g, blk>>>(a_raw, b_raw, prawh);
    }
    // 7) warp GEMMs on fp16 mma (B via ldmatrix.trans from natural [k][n] corr)
    {
        dim3 g(HW / 256, (C_IN + 127) / 128, 4);
        wgemm_f16_kernel<<<g, blk, WH_SMEM>>>(prawh, pch, b_warp, a_warp);
    }
}

// round 16
// speedup vs baseline: 1.4459x; 1.0060x over previous
#include <cuda_runtime.h>
#include <cuda_fp16.h>
#include <math.h>
#include <stdint.h>
#include <stddef.h>

// ---------------- problem constants ----------------
#define N_B   2
#define C_IN  1088
#define C_MID 136
#define HW    4096
#define CV_K  (3 * C_IN)     // 3264 : [hi | lo | hi] split-K for conv

typedef unsigned long long ull;

// ---------------- device scratch ----------------
__device__ __align__(16) float g_fa[N_B * C_MID * HW];
__device__ __align__(16) float g_fb[N_B * C_MID * HW];
// fp16 raw, slot z: 0,1 = b_raw batches; 2,3 = a_raw batches
__device__ __align__(16) __half g_rawh[4ULL * C_IN * HW];
// fp16 softmaxed corr, natural [k][n] layout, slots = [ab0, ab1, ba0, ba1]
__device__ __align__(16) __half g_ch[4ULL * HW * HW];
// fp16 hi/lo-split features for energy: slots 0,1 = fb' (bat0,1), 2,3 = fa'
#define E_K 432
__device__ __align__(16) __half g_eh[4ULL * HW * E_K];
// fp16 split conv inputs: slot z = sel*2+bat, [3264][HW] = [Xhi; Xlo; Xhi]
__device__ __align__(16) __half g_xh[4ULL * CV_K * HW];
// fp16 split conv weights per tensor: [136][3264] = [Whi | Whi | Wlo]
__device__ __align__(16) __half g_wh[2ULL * C_MID * CV_K];

// ---------------- helpers ----------------
__device__ __forceinline__ void cp16(uint32_t dst, const void* src, uint32_t sz) {
    asm volatile("cp.async.ca.shared.global [%0], [%1], 16, %2;"
                 :: "r"(dst), "l"(src), "r"(sz));
}
__device__ __forceinline__ void cp_commit() { asm volatile("cp.async.commit_group;"); }
__device__ __forceinline__ void cp_wait0()  { asm volatile("cp.async.wait_group 0;" ::: "memory"); }
__device__ __forceinline__ void cp_wait1()  { asm volatile("cp.async.wait_group 1;" ::: "memory"); }

__device__ __forceinline__ float blk_sum(float v, float* red) {
    const int tid = threadIdx.x;
    #pragma unroll
    for (int o = 16; o > 0; o >>= 1) v += __shfl_down_sync(0xffffffffu, v, o);
    if ((tid & 31) == 0) red[tid >> 5] = v;
    __syncthreads();
    if (tid < 32) {
        v = (tid < 8) ? red[tid] : 0.f;
        #pragma unroll
        for (int o = 4; o > 0; o >>= 1) v += __shfl_down_sync(0xffffffffu, v, o);
        if (tid == 0) red[0] = v;
    }
    __syncthreads();
    v = red[0];
    __syncthreads();
    return v;
}

__device__ __forceinline__ float blk_max(float v, float* red) {
    const int tid = threadIdx.x;
    #pragma unroll
    for (int o = 16; o > 0; o >>= 1) v = fmaxf(v, __shfl_down_sync(0xffffffffu, v, o));
    if ((tid & 31) == 0) red[tid >> 5] = v;
    __syncthreads();
    if (tid < 32) {
        v = (tid < 8) ? red[tid] : -3.4e38f;
        #pragma unroll
        for (int o = 4; o > 0; o >>= 1) v = fmaxf(v, __shfl_down_sync(0xffffffffu, v, o));
        if (tid == 0) red[0] = v;
    }
    __syncthreads();
    v = red[0];
    __syncthreads();
    return v;
}

// ---------------- mma.sync fp16 primitive (f32 accumulate) ----------------
__device__ __forceinline__ void mma_f16(float4& c, const uint32_t a[4], const uint32_t b[2]) {
    asm volatile(
        "mma.sync.aligned.m16n8k16.row.col.f32.f16.f16.f32 "
        "{%0,%1,%2,%3},{%4,%5,%6,%7},{%8,%9},{%0,%1,%2,%3};"
        : "+f"(c.x), "+f"(c.y), "+f"(c.z), "+f"(c.w)
        : "r"(a[0]), "r"(a[1]), "r"(a[2]), "r"(a[3]), "r"(b[0]), "r"(b[1]));
}

__device__ __forceinline__ void ldsm4t(uint32_t& r0, uint32_t& r1, uint32_t& r2, uint32_t& r3,
                                       uint32_t addr) {
    asm volatile("ldmatrix.sync.aligned.m8n8.x4.trans.shared.b16 {%0,%1,%2,%3}, [%4];"
                 : "=r"(r0), "=r"(r1), "=r"(r2), "=r"(r3) : "r"(addr));
}

// ---------------- shared tile geometry for wgemm/conv kernels ----------------
#define HA_PITCH 40
#define HB_PITCH 264
#define HA_BYTES (128 * HA_PITCH * 2)       // 10240
#define HB_BYTES (32 * HB_PITCH * 2)        // 16896
#define HST_BYTES (HA_BYTES + HB_BYTES)     // 27136
#define HN_STAGE 3
#define WH_SMEM (HN_STAGE * HST_BYTES)      // 81408

// ---------------- warp-stage GEMM: fp16 mma, CTA 128x256, 3-stage cp.async ----------------
__global__ __launch_bounds__(256)
void wgemm_f16_kernel(const __half* __restrict__ Ah, const __half* __restrict__ Bh,
                      float* __restrict__ b_warp, float* __restrict__ a_warp)
{
    extern __shared__ char smc[];
    const uint32_t smem_base = (uint32_t)__cvta_generic_to_shared(smc);

    const int z = blockIdx.z;
    const __half* A = Ah + (size_t)z * C_IN * HW;
    const __half* B = Bh + (size_t)z * HW * HW;
    float* C = (z < 2) ? (b_warp + (size_t)z * C_IN * HW)
                       : (a_warp + (size_t)(z - 2) * C_IN * HW);

    const int m0 = blockIdx.y * 128;
    const int n0 = blockIdx.x * 256;
    const int tid = threadIdx.x;
    const int wid = tid >> 5;
    const int lane = tid & 31;
    const int wr = wid >> 2;
    const int wc = wid & 3;
    const int g = lane >> 2;
    const int tig = lane & 3;

    auto load_chunk = [&](int kc, int st) {
        const uint32_t sb = smem_base + (uint32_t)(st * HST_BYTES);
        const int k0 = kc * 32;
        #pragma unroll
        for (int p = 0; p < 2; p++) {
            const int u = p * 256 + tid;
            const int row = u >> 2, q = u & 3;
            const int gr = m0 + row;
            const uint32_t dst = sb + (uint32_t)(row * HA_PITCH * 2 + q * 16);
            const __half* src = A + (size_t)((gr < C_IN) ? gr : 0) * HW + k0 + q * 8;
            cp16(dst, src, (gr < C_IN) ? 16u : 0u);
        }
        #pragma unroll
        for (int p = 0; p < 4; p++) {
            const int u = p * 256 + tid;
            const int row = u >> 5, q = u & 31;
            const uint32_t dst = sb + HA_BYTES + (uint32_t)(row * HB_PITCH * 2 + q * 16);
            const __half* src = B + (size_t)(k0 + row) * HW + n0 + q * 8;
            cp16(dst, src, 16u);
        }
        cp_commit();
    };

    float4 acc[4][8];
    #pragma unroll
    for (int i = 0; i < 4; i++)
        #pragma unroll
        for (int j = 0; j < 8; j++) acc[i][j] = make_float4(0.f, 0.f, 0.f, 0.f);

    const int NC = HW / 32;
    load_chunk(0, 0);
    load_chunk(1, 1);

    int st = 0;
    for (int j = 0; j < NC; j++) {
        if (j + 2 < NC) cp_wait1(); else cp_wait0();
        __syncthreads();
        if (j + 2 < NC) {
            int st2 = st + 2; if (st2 >= HN_STAGE) st2 -= HN_STAGE;
            load_chunk(j + 2, st2);
        }

        const __half* As = (const __half*)(smc + st * HST_BYTES);
        const uint32_t Bs = smem_base + (uint32_t)(st * HST_BYTES + HA_BYTES);

        uint32_t b[8][4];
        #pragma unroll
        for (int nt = 0; nt < 8; nt++) {
            const uint32_t addr = Bs + (uint32_t)(lane * (HB_PITCH * 2) +
                                                  (wc * 64 + nt * 8) * 2);
            ldsm4t(b[nt][0], b[nt][1], b[nt][2], b[nt][3], addr);
        }
        #pragma unroll
        for (int ks = 0; ks < 2; ks++) {
            uint32_t a[4][4];
            #pragma unroll
            for (int mt = 0; mt < 4; mt++) {
                const __half* ap = As + (wr * 64 + mt * 16 + g) * HA_PITCH + ks * 16 + 2 * tig;
                a[mt][0] = *reinterpret_cast<const uint32_t*>(ap);
                a[mt][1] = *reinterpret_cast<const uint32_t*>(ap + 8 * HA_PITCH);
                a[mt][2] = *reinterpret_cast<const uint32_t*>(ap + 8);
                a[mt][3] = *reinterpret_cast<const uint32_t*>(ap + 8 * HA_PITCH + 8);
            }
            #pragma unroll
            for (int mt = 0; mt < 4; mt++)
                #pragma unroll
                for (int nt = 0; nt < 8; nt++)
                    mma_f16(acc[mt][nt], a[mt], &b[nt][ks * 2]);
        }
        if (++st >= HN_STAGE) st -= HN_STAGE;
    }

    #pragma unroll
    for (int mt = 0; mt < 4; mt++) {
        const int r0 = m0 + wr * 64 + mt * 16 + g;
        const int r1 = r0 + 8;
        #pragma unroll
        for (int nt = 0; nt < 8; nt++) {
            const int col = n0 + wc * 64 + nt * 8 + tig * 2;
            const float4 cc = acc[mt][nt];
            if (r0 < C_IN)
                *reinterpret_cast<float2*>(C + (size_t)r0 * HW + col) = make_float2(cc.x, cc.y);
            if (r1 < C_IN)
                *reinterpret_cast<float2*>(C + (size_t)r1 * HW + col) = make_float2(cc.z, cc.w);
        }
    }
}

// ---------------- conv GEMM: fp16 split, rows 0..127, bias epilogue ----------------
// F[c,l] = bias[c] + sum_k W'[c][k] * X'[k][l], K'=3264. Same skeleton as wgemm.
__global__ __launch_bounds__(256)
void conv_f16_kernel(const __half* __restrict__ Wh, const __half* __restrict__ Xh,
                     const float* __restrict__ ba, const float* __restrict__ bb,
                     float* __restrict__ Fa, float* __restrict__ Fb)
{
    extern __shared__ char smc[];
    const uint32_t smem_base = (uint32_t)__cvta_generic_to_shared(smc);

    const int z = blockIdx.z;
    const int sel = z >> 1, bat = z & 1;
    const __half* A = Wh + (size_t)sel * C_MID * CV_K;
    const __half* B = Xh + (size_t)z * CV_K * HW;
    const float* bias = sel ? bb : ba;
    float* C = (sel ? Fb : Fa) + (size_t)bat * C_MID * HW;

    const int n0 = blockIdx.x * 256;
    const int tid = threadIdx.x;
    const int wid = tid >> 5;
    const int lane = tid & 31;
    const int wr = wid >> 2;
    const int wc = wid & 3;
    const int g = lane >> 2;
    const int tig = lane & 3;

    auto load_chunk = [&](int kc, int st) {
        const uint32_t sb = smem_base + (uint32_t)(st * HST_BYTES);
        const int k0 = kc * 32;
        #pragma unroll
        for (int p = 0; p < 2; p++) {
            const int u = p * 256 + tid;
            const int row = u >> 2, q = u & 3;
            const uint32_t dst = sb + (uint32_t)(row * HA_PITCH * 2 + q * 16);
            cp16(dst, A + (size_t)row * CV_K + k0 + q * 8, 16u);
        }
        #pragma unroll
        for (int p = 0; p < 4; p++) {
            const int u = p * 256 + tid;
            const int row = u >> 5, q = u & 31;
            const uint32_t dst = sb + HA_BYTES + (uint32_t)(row * HB_PITCH * 2 + q * 16);
            cp16(dst, B + (size_t)(k0 + row) * HW + n0 + q * 8, 16u);
        }
        cp_commit();
    };

    float4 acc[4][8];
    #pragma unroll
    for (int i = 0; i < 4; i++)
        #pragma unroll
        for (int j = 0; j < 8; j++) acc[i][j] = make_float4(0.f, 0.f, 0.f, 0.f);

    const int NC = CV_K / 32;   // 102
    load_chunk(0, 0);
    load_chunk(1, 1);

    int st = 0;
    for (int j = 0; j < NC; j++) {
        if (j + 2 < NC) cp_wait1(); else cp_wait0();
        __syncthreads();
        if (j + 2 < NC) {
            int st2 = st + 2; if (st2 >= HN_STAGE) st2 -= HN_STAGE;
            load_chunk(j + 2, st2);
        }

        const __half* As = (const __half*)(smc + st * HST_BYTES);
        const uint32_t Bs = smem_base + (uint32_t)(st * HST_BYTES + HA_BYTES);

        uint32_t b[8][4];
        #pragma unroll
        for (int nt = 0; nt < 8; nt++) {
            const uint32_t addr = Bs + (uint32_t)(lane * (HB_PITCH * 2) +
                                                  (wc * 64 + nt * 8) * 2);
            ldsm4t(b[nt][0], b[nt][1], b[nt][2], b[nt][3], addr);
        }
        #pragma unroll
        for (int ks = 0; ks < 2; ks++) {
            uint32_t a[4][4];
            #pragma unroll
            for (int mt = 0; mt < 4; mt++) {
                const __half* ap = As + (wr * 64 + mt * 16 + g) * HA_PITCH + ks * 16 + 2 * tig;
                a[mt][0] = *reinterpret_cast<const uint32_t*>(ap);
                a[mt][1] = *reinterpret_cast<const uint32_t*>(ap + 8 * HA_PITCH);
                a[mt][2] = *reinterpret_cast<const uint32_t*>(ap + 8);
                a[mt][3] = *reinterpret_cast<const uint32_t*>(ap + 8 * HA_PITCH + 8);
            }
            #pragma unroll
            for (int mt = 0; mt < 4; mt++)
                #pragma unroll
                for (int nt = 0; nt < 8; nt++)
                    mma_f16(acc[mt][nt], a[mt], &b[nt][ks * 2]);
        }
        if (++st >= HN_STAGE) st -= HN_STAGE;
    }

    #pragma unroll
    for (int mt = 0; mt < 4; mt++) {
        const int r0 = wr * 64 + mt * 16 + g;
        const int r1 = r0 + 8;
        const float bv0 = bias[r0], bv1 = bias[r1];
        #pragma unroll
        for (int nt = 0; nt < 8; nt++) {
            const int col = n0 + wc * 64 + nt * 8 + tig * 2;
            const float4 cc = acc[mt][nt];
            *reinterpret_cast<float2*>(C + (size_t)r0 * HW + col) =
                make_float2(cc.x + bv0, cc.y + bv0);
            *reinterpret_cast<float2*>(C + (size_t)r1 * HW + col) =
                make_float2(cc.z + bv1, cc.w + bv1);
        }
    }
}

// ---------------- conv input split: X fp32 [cin][l] -> [Xhi; Xlo; Xhi] fp16 ----------------
__global__ __launch_bounds__(256)
void xcvt_kernel(const float* __restrict__ fa, const float* __restrict__ fb,
                 __half* __restrict__ dst)
{
    const int z = blockIdx.z;
    const int sel = z >> 1, bat = z & 1;
    const float* src = (sel ? fb : fa) + (size_t)bat * C_IN * HW;
    __half* d = dst + (size_t)z * CV_K * HW;

    const size_t i = ((size_t)blockIdx.x * 256 + threadIdx.x) * 8;
    const int cin = (int)(i / HW);
    const int l = (int)(i % HW);
    const float4 v0 = *reinterpret_cast<const float4*>(src + i);
    const float4 v1 = *reinterpret_cast<const float4*>(src + i + 4);
    float v[8] = { v0.x, v0.y, v0.z, v0.w, v1.x, v1.y, v1.z, v1.w };
    __half2 hi[4], lo[4];
    #pragma unroll
    for (int p = 0; p < 4; p++) {
        const __half h0 = __float2half_rn(v[2*p]);
        const __half h1 = __float2half_rn(v[2*p+1]);
        hi[p] = __halves2half2(h0, h1);
        lo[p] = __halves2half2(__float2half_rn(v[2*p] - __half2float(h0)),
                               __float2half_rn(v[2*p+1] - __half2float(h1)));
    }
    const uint4 hv = *reinterpret_cast<const uint4*>(hi);
    const uint4 lv = *reinterpret_cast<const uint4*>(lo);
    *reinterpret_cast<uint4*>(d + (size_t)cin * HW + l) = hv;
    *reinterpret_cast<uint4*>(d + (size_t)(C_IN + cin) * HW + l) = lv;
    *reinterpret_cast<uint4*>(d + (size_t)(2 * C_IN + cin) * HW + l) = hv;
}

// ---------------- conv weight split: W fp32 [136][1088] -> [Whi | Whi | Wlo] fp16 ----------------
__global__ __launch_bounds__(256)
void wcvt_kernel(const float* __restrict__ Wa, const float* __restrict__ Wb,
                 __half* __restrict__ dst)
{
    const int sel = blockIdx.z;
    const float* src = sel ? Wb : Wa;
    __half* d = dst + (size_t)sel * C_MID * CV_K;
    const int idx = (blockIdx.x * 256 + threadIdx.x) * 4;
    if (idx >= C_MID * C_IN) return;
    const int c = idx / C_IN, k = idx % C_IN;
    const float4 v = *reinterpret_cast<const float4*>(src + idx);
    float vv[4] = { v.x, v.y, v.z, v.w };
    __half2 hi[2], lo[2];
    #pragma unroll
    for (int p = 0; p < 2; p++) {
        const __half h0 = __float2half_rn(vv[2*p]);
        const __half h1 = __float2half_rn(vv[2*p+1]);
        hi[p] = __halves2half2(h0, h1);
        lo[p] = __halves2half2(__float2half_rn(vv[2*p] - __half2float(h0)),
                               __float2half_rn(vv[2*p+1] - __half2float(h1)));
    }
    __half* base = d + (size_t)c * CV_K;
    *reinterpret_cast<uint2*>(base + k) = *reinterpret_cast<const uint2*>(hi);
    *reinterpret_cast<uint2*>(base + C_IN + k) = *reinterpret_cast<const uint2*>(hi);
    *reinterpret_cast<uint2*>(base + 2 * C_IN + k) = *reinterpret_cast<const uint2*>(lo);
}

// ---------------- energy GEMM: fp16 hi/lo split, K=432, dual-orientation epilogue ----------------
#define E_CH 48
#define E_NC (E_K / E_CH)                 // 9
#define E_PITCH 56
#define E_A_BYTES (128 * E_PITCH * 2)     // 14336
#define E_ST_BYTES (2 * E_A_BYTES)        // 28672
#define E_SMEM (3 * E_ST_BYTES)           // 86016
#define EP_PITCH 132

__global__ __launch_bounds__(256)
void energy_f16_kernel(const __half* __restrict__ eh,
                       float* __restrict__ Eab, float* __restrict__ Eba)
{
    extern __shared__ char smc[];
    const uint32_t smem_base = (uint32_t)__cvta_generic_to_shared(smc);
    const int bat = blockIdx.z;
    const __half* A = eh + (size_t)bat * HW * E_K;
    const __half* B = eh + (size_t)(2 + bat) * HW * E_K;
    float* EA = Eab + (size_t)bat * HW * HW;
    float* EB = Eba + (size_t)bat * HW * HW;

    const int m0 = blockIdx.y * 128;
    const int n0 = blockIdx.x * 128;
    const int tid = threadIdx.x;
    const int wid = tid >> 5, lane = tid & 31;
    const int wr = wid >> 2, wc = wid & 3;
    const int g = lane >> 2, tig = lane & 3;

    auto load_chunk = [&](int kc, int st) {
        const uint32_t sb = smem_base + (uint32_t)(st * E_ST_BYTES);
        const int k0 = kc * E_CH;
        #pragma unroll
        for (int p = 0; p < 3; p++) {
            const int u = p * 256 + tid;
            const int row = u / 6, q = u % 6;
            cp16(sb + (uint32_t)(row * (E_PITCH * 2) + q * 16),
                 A + (size_t)(m0 + row) * E_K + k0 + q * 8, 16u);
        }
        #pragma unroll
        for (int p = 0; p < 3; p++) {
            const int u = p * 256 + tid;
            const int row = u / 6, q = u % 6;
            cp16(sb + E_A_BYTES + (uint32_t)(row * (E_PITCH * 2) + q * 16),
                 B + (size_t)(n0 + row) * E_K + k0 + q * 8, 16u);
        }
        cp_commit();
    };

    float4 acc[4][4];
    #pragma unroll
    for (int i = 0; i < 4; i++)
        #pragma unroll
        for (int j = 0; j < 4; j++) acc[i][j] = make_float4(0.f, 0.f, 0.f, 0.f);

    load_chunk(0, 0);
    load_chunk(1, 1);

    int st = 0;
    for (int j = 0; j < E_NC; j++) {
        if (j + 2 < E_NC) cp_wait1(); else cp_wait0();
        __syncthreads();
        if (j + 2 < E_NC) {
            int st2 = st + 2; if (st2 >= 3) st2 -= 3;
            load_chunk(j + 2, st2);
        }

        const __half* As = (const __half*)(smc + st * E_ST_BYTES);
        const __half* Bs = (const __half*)(smc + st * E_ST_BYTES + E_A_BYTES);
        #pragma unroll
        for (int ks = 0; ks < 3; ks++) {
            uint32_t a[4][4], b[4][2];
            #pragma unroll
            for (int mt = 0; mt < 4; mt++) {
                const __half* ap = As + (wr * 64 + mt * 16 + g) * E_PITCH + ks * 16 + 2 * tig;
                a[mt][0] = *reinterpret_cast<const uint32_t*>(ap);
                a[mt][1] = *reinterpret_cast<const uint32_t*>(ap + 8 * E_PITCH);
                a[mt][2] = *reinterpret_cast<const uint32_t*>(ap + 8);
                a[mt][3] = *reinterpret_cast<const uint32_t*>(ap + 8 * E_PITCH + 8);
            }
            #pragma unroll
            for (int nt = 0; nt < 4; nt++) {
                const __half* bp = Bs + (wc * 32 + nt * 8 + g) * E_PITCH + ks * 16 + 2 * tig;
                b[nt][0] = *reinterpret_cast<const uint32_t*>(bp);
                b[nt][1] = *reinterpret_cast<const uint32_t*>(bp + 8);
            }
            #pragma unroll
            for (int mt = 0; mt < 4; mt++)
                #pragma unroll
                for (int nt = 0; nt < 4; nt++)
                    mma_f16(acc[mt][nt], a[mt], b[nt]);
        }
        if (++st >= 3) st -= 3;
    }

    #pragma unroll
    for (int mt = 0; mt < 4; mt++)
        #pragma unroll
        for (int nt = 0; nt < 4; nt++) {
            acc[mt][nt].x *= 100.f; acc[mt][nt].y *= 100.f;
            acc[mt][nt].z *= 100.f; acc[mt][nt].w *= 100.f;
        }

    float* ep = (float*)smc;
    __syncthreads();
    #pragma unroll
    for (int mt = 0; mt < 4; mt++) {
        const int r0 = wr * 64 + mt * 16 + g, r1 = r0 + 8;
        #pragma unroll
        for (int nt = 0; nt < 4; nt++) {
            const int col = wc * 32 + nt * 8 + tig * 2;
            const float4 cc = acc[mt][nt];
            ep[r0 * EP_PITCH + col] = cc.x; ep[r0 * EP_PITCH + col + 1] = cc.y;
            ep[r1 * EP_PITCH + col] = cc.z; ep[r1 * EP_PITCH + col + 1] = cc.w;
        }
    }
    __syncthreads();
    #pragma unroll
    for (int it = 0; it < 16; it++) {
        const int e = it * 256 + tid;
        const int rr = e >> 5, c4 = (e & 31) * 4;
        *reinterpret_cast<float4*>(EA + (size_t)(m0 + rr) * HW + n0 + c4) =
            *reinterpret_cast<const float4*>(ep + rr * EP_PITCH + c4);
    }
    __syncthreads();
    #pragma unroll
    for (int mt = 0; mt < 4; mt++) {
        const int r0 = wr * 64 + mt * 16 + g, r1 = r0 + 8;
        #pragma unroll
        for (int nt = 0; nt < 4; nt++) {
            const int col = wc * 32 + nt * 8 + tig * 2;
            const float4 cc = acc[mt][nt];
            ep[col * EP_PITCH + r0] = cc.x; ep[(col + 1) * EP_PITCH + r0] = cc.y;
            ep[col * EP_PITCH + r1] = cc.z; ep[(col + 1) * EP_PITCH + r1] = cc.w;
        }
    }
    __syncthreads();
    #pragma unroll
    for (int it = 0; it < 16; it++) {
        const int e = it * 256 + tid;
        const int rr = e >> 5, c4 = (e & 31) * 4;
        *reinterpret_cast<float4*>(EB + (size_t)(n0 + rr) * HW + m0 + c4) =
            *reinterpret_cast<const float4*>(ep + rr * EP_PITCH + c4);
    }
}

// ---------------- fused L2-normalize + hi/lo split + transpose ----------------
__global__ __launch_bounds__(256)
void l2fcvt_kernel(const float* __restrict__ Fa, const float* __restrict__ Fb,
                   __half* __restrict__ outp)
{
    __shared__ float t[C_MID][33];
    __shared__ float inv_s[32];
    const int z = blockIdx.y;
    const int bat = z & 1;
    const bool is_fb = (z < 2);
    const float* src = (is_fb ? Fb : Fa) + (size_t)bat * C_MID * HW;
    __half* dst = outp + (size_t)z * HW * E_K;

    const int l0 = blockIdx.x * 32;
    const int tid = threadIdx.x;
    const int lane = tid & 31;
    const int wrow = tid >> 5;

    for (int c = wrow; c < C_MID; c += 8)
        t[c][lane] = src[(size_t)c * HW + l0 + lane];
    __syncthreads();

    const int ln = tid >> 3;
    const int j = tid & 7;
    float s = 0.f;
    for (int c = j; c < C_MID; c += 8) { const float v = t[c][ln]; s += v * v; }
    s += __shfl_down_sync(0xffffffffu, s, 4);
    s += __shfl_down_sync(0xffffffffu, s, 2);
    s += __shfl_down_sync(0xffffffffu, s, 1);
    if (j == 0) inv_s[ln] = rsqrtf(s);
    __syncthreads();

    const float inv = inv_s[ln];
    __half* base = dst + (size_t)(l0 + ln) * E_K;
    #pragma unroll
    for (int p = 0; p < 9; p++) {
        const int cp = j + p * 8;
        if (cp >= 72) break;
        const int c = cp * 2;
        const float v0 = (c < C_MID) ? t[c][ln] * inv : 0.f;
        const float v1 = (c + 1 < C_MID) ? t[c + 1][ln] * inv : 0.f;
        const __half h0 = __float2half_rn(v0), h1 = __float2half_rn(v1);
        const __half l0h = __float2half_rn(v0 - __half2float(h0));
        const __half l1h = __float2half_rn(v1 - __half2float(h1));
        const __half2 hh = __halves2half2(h0, h1);
        const __half2 llh = __halves2half2(l0h, l1h);
        *reinterpret_cast<__half2*>(base + c) = hh;
        if (is_fb) {
            *reinterpret_cast<__half2*>(base + 144 + c) = hh;
            *reinterpret_cast<__half2*>(base + 288 + c) = llh;
        } else {
            *reinterpret_cast<__half2*>(base + 144 + c) = llh;
            *reinterpret_cast<__half2*>(base + 288 + c) = hh;
        }
    }
}

// ---------------- conv tail: rows 128..135 ----------------
__global__ __launch_bounds__(256)
void conv_tail_kernel(const float* __restrict__ X0, const float* __restrict__ X1,
                      const float* __restrict__ W0, const float* __restrict__ W1,
                      const float* __restrict__ b0, const float* __restrict__ b1,
                      float* __restrict__ F0, float* __restrict__ F1)
{
    __shared__ float ws[8 * C_IN];
    const int sel = blockIdx.z >> 1, bat = blockIdx.z & 1;
    const float* X = (sel ? X1 : X0) + (long)bat * C_IN * HW;
    const float* W = (sel ? W1 : W0) + 128 * C_IN;
    const float* bias = (sel ? b1 : b0) + 128;
    float* F = (sel ? F1 : F0) + (long)bat * C_MID * HW + 128L * HW;

    const int tid = threadIdx.x;
    for (int i = tid; i < 8 * C_IN; i += 256) ws[i] = W[i];
    __syncthreads();

    const int l = blockIdx.x * 256 + tid;
    float acc[8];
    #pragma unroll
    for (int r2 = 0; r2 < 8; r2++) acc[r2] = 0.f;

    #pragma unroll 8
    for (int cin = 0; cin < C_IN; cin++) {
        const float x = X[(long)cin * HW + l];
        #pragma unroll
        for (int r2 = 0; r2 < 8; r2++)
            acc[r2] = fmaf(ws[r2 * C_IN + cin], x, acc[r2]);
    }
    #pragma unroll
    for (int r2 = 0; r2 < 8; r2++)
        F[(long)r2 * HW + l] = acc[r2] + bias[r2];
}

// ---------------- raw fp32 -> fp16 slots (b0,b1,a0,a1) ----------------
__global__ __launch_bounds__(256)
void rawcvt_kernel(const float* __restrict__ a, const float* __restrict__ b,
                   __half* __restrict__ dst)
{
    const int z = blockIdx.z;
    const long slice = (long)C_IN * HW;
    const float* src = (z < 2) ? (b + z * slice) : (a + (z - 2) * slice);
    __half* d = dst + z * slice;
    const long i = ((long)blockIdx.x * 256 + threadIdx.x) * 8;
    const float4 v0 = *reinterpret_cast<const float4*>(src + i);
    const float4 v1 = *reinterpret_cast<const float4*>(src + i + 4);
    __half2 h[4];
    h[0] = __floats2half2_rn(v0.x, v0.y);
    h[1] = __floats2half2_rn(v0.z, v0.w);
    h[2] = __floats2half2_rn(v1.x, v1.y);
    h[3] = __floats2half2_rn(v1.z, v1.w);
    *reinterpret_cast<uint4*>(d + i) = *reinterpret_cast<const uint4*>(h);
}

// ---------------- instance norm + LeakyReLU + re-center ----------------
__global__ __launch_bounds__(256)
void instnorm_kernel(float* __restrict__ Fa, float* __restrict__ Fb)
{
    __shared__ float sh[HW];
    __shared__ float red[8];
    float* F = blockIdx.z ? Fb : Fa;
    float* row = F + ((long)blockIdx.y * C_MID + blockIdx.x) * HW;
    const int tid = threadIdx.x;

    float s = 0.f, s2 = 0.f;
    for (int i = tid; i < HW; i += 256) {
        const float v = row[i];
        sh[i] = v; s += v; s2 += v * v;
    }
    s  = blk_sum(s,  red);
    s2 = blk_sum(s2, red);
    const float mean = s * (1.f / HW);
    const float var  = s2 * (1.f / HW) - mean * mean;
    const float inv  = rsqrtf(var + 1e-5f);

    float s3 = 0.f;
    for (int i = tid; i < HW; i += 256) {
        float v = (sh[i] - mean) * inv;
        v = (v >= 0.f) ? v : 0.2f * v;
        sh[i] = v;
        s3 += v;
    }
    s3 = blk_sum(s3, red);
    const float mean2 = s3 * (1.f / HW);
    for (int i = tid; i < HW; i += 256)
        row[i] = sh[i] - mean2;
}

// ---------------- in-place row softmax + fp16 emit ----------------
__global__ __launch_bounds__(256)
void softmax_kernel(float* __restrict__ E, __half* __restrict__ ch)
{
    __shared__ float sh[HW];
    __shared__ float red[8];
    const size_t roff = (size_t)blockIdx.y * HW * HW + (size_t)blockIdx.x * HW;
    float* row = E + roff;
    __half* hrow = ch + roff;
    const int tid = threadIdx.x;

    float mx = -3.4e38f;
    for (int i = tid; i < HW; i += 256) {
        const float v = row[i];
        sh[i] = v;
        mx = fmaxf(mx, v);
    }
    mx = blk_max(mx, red);

    float s = 0.f;
    for (int i = tid; i < HW; i += 256) {
        const float e = __expf(sh[i] - mx);
        sh[i] = e;
        s += e;
    }
    s = blk_sum(s, red);
    const float inv = 1.f / s;
    for (int i = tid * 4; i < HW; i += 1024) {
        const float4 p = make_float4(sh[i] * inv, sh[i + 1] * inv,
                                     sh[i + 2] * inv, sh[i + 3] * inv);
        *reinterpret_cast<float4*>(row + i) = p;
        *reinterpret_cast<__half2*>(hrow + i) = __floats2half2_rn(p.x, p.y);
        *reinterpret_cast<__half2*>(hrow + i + 2) = __floats2half2_rn(p.z, p.w);
    }
}

// ---------------- launch ----------------
extern "C" void kernel_launch(void* const* d_in, const int* in_sizes, int n_in,
                              void* d_out, int out_size)
{
    const float* fa    = (const float*)d_in[0];
    const float* fb    = (const float*)d_in[1];
    const float* a_raw = (const float*)d_in[2];
    const float* b_raw = (const float*)d_in[3];
    const float* Wa    = (const float*)d_in[4];
    const float* ba    = (const float*)d_in[5];
    const float* Wb    = (const float*)d_in[6];
    const float* bb    = (const float*)d_in[7];
    float* out = (float*)d_out;

    float *pfa, *pfb;
    __half *prawh, *pch, *peh, *pxh, *pwh;
    cudaGetSymbolAddress((void**)&pfa, g_fa);
    cudaGetSymbolAddress((void**)&pfb, g_fb);
    cudaGetSymbolAddress((void**)&prawh, g_rawh);
    cudaGetSymbolAddress((void**)&pch, g_ch);
    cudaGetSymbolAddress((void**)&peh, g_eh);
    cudaGetSymbolAddress((void**)&pxh, g_xh);
    cudaGetSymbolAddress((void**)&pwh, g_wh);

    cudaFuncSetAttribute(wgemm_f16_kernel,
                         cudaFuncAttributeMaxDynamicSharedMemorySize, WH_SMEM);
    cudaFuncSetAttribute(conv_f16_kernel,
                         cudaFuncAttributeMaxDynamicSharedMemorySize, WH_SMEM);
    cudaFuncSetAttribute(energy_f16_kernel,
                         cudaFuncAttributeMaxDynamicSharedMemorySize, E_SMEM);

    const long CORR = (long)HW * HW;
    float* corr_ab = out;
    float* corr_ba = out + (long)N_B * CORR;
    float* a_warp  = out + 2L * N_B * CORR;
    float* b_warp  = a_warp + (long)N_B * C_IN * HW;

    const dim3 blk(256);
    const long sIN = (long)C_IN * HW;

    // 0) split conv inputs and weights to fp16 hi/lo
    {
        dim3 g((unsigned)(sIN / 8 / 256), 1, 4);
        xcvt_kernel<<<g, blk>>>(fa, fb, pxh);
    }
    {
        dim3 g((C_MID * C_IN / 4 + 255) / 256, 1, 2);
        wcvt_kernel<<<g, blk>>>(Wa, Wb, pwh);
    }
    // 1) 1x1 conv rows 0..127 on fp16 tensor cores (split-K accurate)
    {
        dim3 g(HW / 256, 1, 4);
        conv_f16_kernel<<<g, blk, WH_SMEM>>>(pwh, pxh, ba, bb, pfa, pfb);
    }
    // 1b) conv tail: rows 128..135
    {
        dim3 g(HW / 256, 1, 4);
        conv_tail_kernel<<<g, blk>>>(fa, fb, Wa, Wb, ba, bb, pfa, pfb);
    }
    // 2) InstanceNorm + LeakyReLU + re-center
    {
        dim3 g(C_MID, N_B, 2);
        instnorm_kernel<<<g, blk>>>(pfa, pfb);
    }
    // 3) fused per-column L2 normalize + hi/lo split + transpose -> g_eh
    {
        dim3 g(HW / 32, 4);
        l2fcvt_kernel<<<g, blk>>>(pfa, pfb, peh);
    }
    // 4) energy GEMM on fp16 mma (K=432 split), writes E and E^T (x100)
    {
        dim3 g(HW / 128, HW / 128, 2);
        energy_f16_kernel<<<g, blk, E_SMEM>>>(peh, corr_ab, corr_ba);
    }
    // 5) softmax over all corr rows; emits fp32 output + fp16 copy for wgemm
    {
        dim3 g(HW, 2 * N_B);
        softmax_kernel<<<g, blk>>>(out, pch);
    }
    // 6) convert raw -> fp16 slots
    {
        dim3 g((unsigned)(sIN / 8 / 256), 1, 4);
        rawcvt_kernel<<<g, blk>>>(a_raw, b_raw, prawh);
    }
    // 7) warp GEMMs on fp16 mma (B via ldmatrix.trans from natural [k][n] corr)
    {
        dim3 g(HW / 256, (C_IN + 127) / 128, 4);
        wgemm_f16_kernel<<<g, blk, WH_SMEM>>>(prawh, pch, b_warp, a_warp);
    }
}